// round 9
// baseline (speedup 1.0000x reference)
#include <cuda_runtime.h>
#include <cstdint>

// ----------------------------------------------------------------------------
// Polynormer forward: N=100000, E=1.6M, D=256, H=4, C=64, L=3, OUT=64
// R9: persistent-A fused GEMM — CTA keeps its full 128x256 A tile in smem and
//     streams 3 (weight,colhalf) combos of B tiles through a 3-stage cp.async
//     ring. Cuts redundant A reads through L2 from 612MB to 204MB per launch.
// ----------------------------------------------------------------------------

#define NN 100000
#define EE 1600000
#define DD 256
#define HH 4
#define OUTD 64
#define NEG_SLOPE 0.2f
#define LNEPS 1e-5f

// ---------------- scratch (device globals; allocation-free) -----------------
__device__ float g_x   [NN * DD];
__device__ float g_h   [NN * DD];
__device__ float g_hg  [NN * DD];
__device__ float g_xl  [NN * DD];
__device__ float g_xloc[NN * DD];
__device__ float g_wr  [3 * 196608];      // tf32-rounded, TRANSPOSED [n][k] Wh|Wg|Wl
__device__ float g_asrc[NN * HH];
__device__ float g_adst[NN * HH];
__device__ int   g_cnt   [NN];
__device__ int   g_rowptr[NN + 1];
__device__ int   g_cursor[NN];
__device__ int   g_srcs  [EE + NN];
__device__ int   g_bsum[128];
__device__ int   g_boff[128];

static inline int cdiv(int a, int b) { return (a + b - 1) / b; }

__device__ __forceinline__ uint32_t f2tf32(float f) {
    uint32_t u;
    asm("cvt.rna.tf32.f32 %0, %1;" : "=r"(u) : "f"(f));
    return u;
}

// ---------------- CSR build --------------------------------------------------
__global__ void k_init_cnt() {
    int i = blockIdx.x * blockDim.x + threadIdx.x;
    if (i < NN) g_cnt[i] = 1;  // self loop
}

__global__ void k_hist(const int* __restrict__ ei) {
    int i = blockIdx.x * blockDim.x + threadIdx.x;
    if (i < EE) atomicAdd(&g_cnt[ei[EE + i]], 1);
}

__global__ void k_scan1() {
    __shared__ int sh[1024];
    int t = threadIdx.x, b = blockIdx.x;
    int idx = b * 1024 + t;
    int v = (idx < NN) ? g_cnt[idx] : 0;
    sh[t] = v;
    for (int off = 1; off < 1024; off <<= 1) {
        __syncthreads();
        int u = (t >= off) ? sh[t - off] : 0;
        __syncthreads();
        sh[t] += u;
    }
    if (idx < NN) g_rowptr[idx + 1] = sh[t];
    if (t == 1023) g_bsum[b] = sh[t];
}

__global__ void k_scan2(int nb) {
    if (threadIdx.x == 0 && blockIdx.x == 0) {
        int acc = 0;
        for (int i = 0; i < nb; i++) { g_boff[i] = acc; acc += g_bsum[i]; }
    }
}

__global__ void k_scan3() {
    int idx = blockIdx.x * blockDim.x + threadIdx.x;
    if (idx == 0) { g_rowptr[0] = 0; g_cursor[0] = 0; }
    if (idx < NN) {
        int v = g_rowptr[idx + 1] + g_boff[idx >> 10];
        g_rowptr[idx + 1] = v;
        if (idx + 1 < NN) g_cursor[idx + 1] = v;
    }
}

__global__ void k_scatter(const int* __restrict__ ei) {
    int idx = blockIdx.x * blockDim.x + threadIdx.x;
    int src, dst;
    if (idx < EE)            { src = ei[idx]; dst = ei[EE + idx]; }
    else if (idx < EE + NN)  { src = idx - EE; dst = src; }
    else return;
    int pos = atomicAdd(&g_cursor[dst], 1);
    g_srcs[pos] = src;
}

// ---------------- weight pre-round + transpose to [n][k] --------------------
__global__ void k_round(const float* __restrict__ Wh, const float* __restrict__ Wg,
                        const float* __restrict__ Wl) {
    int t = blockIdx.x * blockDim.x + threadIdx.x;    // float index
    if (t >= 589824) return;                           // 9 matrices of 256x256
    int m = t >> 16;                                   // matrix 0..8
    int o = t & 65535;
    int n = o >> 8, k = o & 255;
    const float* src = (m < 3) ? (Wh + m * 65536)
                     : (m < 6) ? (Wg + (m - 3) * 65536)
                               : (Wl + (m - 6) * 65536);
    float v = src[k * 256 + n];
    g_wr[t] = __uint_as_float(f2tf32(v));
}

// ---------------- MMA primitives ---------------------------------------------
#define GBM 128
#define GBN 128
#define GBK 16

__device__ __forceinline__ void mma_tf32(float* d, const uint32_t* a, const uint32_t* b) {
    asm volatile(
        "mma.sync.aligned.m16n8k8.row.col.f32.tf32.tf32.f32 "
        "{%0,%1,%2,%3}, {%4,%5,%6,%7}, {%8,%9}, {%0,%1,%2,%3};\n"
        : "+f"(d[0]), "+f"(d[1]), "+f"(d[2]), "+f"(d[3])
        : "r"(a[0]), "r"(a[1]), "r"(a[2]), "r"(a[3]), "r"(b[0]), "r"(b[1]));
}

__device__ __forceinline__ void cpa16(uint32_t sa, const void* g, bool p) {
    int sz = p ? 16 : 0;
    asm volatile("cp.async.cg.shared.global [%0], [%1], 16, %2;\n"
                 :: "r"(sa), "l"(g), "r"(sz) : "memory");
}
#define CP_COMMIT() asm volatile("cp.async.commit_group;\n" ::: "memory")
#define CP_WAIT1()  asm volatile("cp.async.wait_group 1;\n" ::: "memory")

#define LDSM4(r0, r1, r2, r3, addr)                                            \
    asm volatile("ldmatrix.sync.aligned.m8n8.x4.shared.b16 {%0,%1,%2,%3}, [%4];" \
                 : "=r"(r0), "=r"(r1), "=r"(r2), "=r"(r3) : "r"(addr))

// ---------------- legacy GEMM (cvt path) for input/output GEMMs --------------
template <bool RELU, bool BIAS, bool ROUND>
__global__ void __launch_bounds__(256, 2) k_mma(
    const float* __restrict__ A, const float* __restrict__ B,
    const float* __restrict__ bias, float* __restrict__ C,
    int M, int K, int Nc)
{
    __shared__ uint32_t As[2][GBM][GBK + 4];
    __shared__ uint32_t Bs[2][GBK][GBN + 8];

    int tid  = threadIdx.x;
    int lane = tid & 31;
    int warp = tid >> 5;
    int wr = warp >> 2, wc = warp & 3;
    int lr = lane >> 2, lc = lane & 3;
    int rowBase = blockIdx.y * GBM;
    int colBase = blockIdx.x * GBN;

    int aRow = tid >> 1;
    int aK   = (tid & 1) << 3;
    int bRow = tid >> 4;
    int bCol = (tid & 15) << 3;

    float acc[4][4][4];
#pragma unroll
    for (int m = 0; m < 4; m++)
#pragma unroll
        for (int n = 0; n < 4; n++)
#pragma unroll
            for (int r = 0; r < 4; r++) acc[m][n][r] = 0.f;

    float aReg[8], bReg[8];
    const int NT = K / GBK;

    {
        bool okA = (rowBase + aRow) < M;
        const float* pA = A + (size_t)(rowBase + aRow) * K + aK;
        float4 v0 = okA ? *(const float4*)pA       : make_float4(0,0,0,0);
        float4 v1 = okA ? *(const float4*)(pA + 4) : make_float4(0,0,0,0);
        aReg[0]=v0.x; aReg[1]=v0.y; aReg[2]=v0.z; aReg[3]=v0.w;
        aReg[4]=v1.x; aReg[5]=v1.y; aReg[6]=v1.z; aReg[7]=v1.w;
        bool okB = (colBase + bCol) < Nc;
        const float* pB = B + (size_t)bRow * Nc + colBase + bCol;
        float4 w0 = okB ? *(const float4*)pB       : make_float4(0,0,0,0);
        float4 w1 = okB ? *(const float4*)(pB + 4) : make_float4(0,0,0,0);
        bReg[0]=w0.x; bReg[1]=w0.y; bReg[2]=w0.z; bReg[3]=w0.w;
        bReg[4]=w1.x; bReg[5]=w1.y; bReg[6]=w1.z; bReg[7]=w1.w;
    }
#pragma unroll
    for (int j = 0; j < 8; j++) As[0][aRow][aK + j]  = f2tf32(aReg[j]);
#pragma unroll
    for (int j = 0; j < 8; j++) Bs[0][bRow][bCol + j] = f2tf32(bReg[j]);
    __syncthreads();

    for (int kt = 0; kt < NT; kt++) {
        int buf = kt & 1;
        if (kt + 1 < NT) {
            bool okA = (rowBase + aRow) < M;
            const float* pA = A + (size_t)(rowBase + aRow) * K + (kt + 1) * GBK + aK;
            float4 v0 = okA ? *(const float4*)pA       : make_float4(0,0,0,0);
            float4 v1 = okA ? *(const float4*)(pA + 4) : make_float4(0,0,0,0);
            aReg[0]=v0.x; aReg[1]=v0.y; aReg[2]=v0.z; aReg[3]=v0.w;
            aReg[4]=v1.x; aReg[5]=v1.y; aReg[6]=v1.z; aReg[7]=v1.w;
            bool okB = (colBase + bCol) < Nc;
            const float* pB = B + (size_t)((kt + 1) * GBK + bRow) * Nc + colBase + bCol;
            float4 w0 = okB ? *(const float4*)pB       : make_float4(0,0,0,0);
            float4 w1 = okB ? *(const float4*)(pB + 4) : make_float4(0,0,0,0);
            bReg[0]=w0.x; bReg[1]=w0.y; bReg[2]=w0.z; bReg[3]=w0.w;
            bReg[4]=w1.x; bReg[5]=w1.y; bReg[6]=w1.z; bReg[7]=w1.w;
        }
#pragma unroll
        for (int ks = 0; ks < 2; ks++) {
            int kb = ks * 8;
            uint32_t af[4][4], bf[4][2];
#pragma unroll
            for (int mt = 0; mt < 4; mt++) {
                int r = wr * 64 + mt * 16 + lr;
                af[mt][0] = As[buf][r    ][kb + lc];
                af[mt][1] = As[buf][r + 8][kb + lc];
                af[mt][2] = As[buf][r    ][kb + lc + 4];
                af[mt][3] = As[buf][r + 8][kb + lc + 4];
            }
#pragma unroll
            for (int nt = 0; nt < 4; nt++) {
                int c = wc * 32 + nt * 8 + lr;
                bf[nt][0] = Bs[buf][kb + lc    ][c];
                bf[nt][1] = Bs[buf][kb + lc + 4][c];
            }
#pragma unroll
            for (int mt = 0; mt < 4; mt++)
#pragma unroll
                for (int nt = 0; nt < 4; nt++)
                    mma_tf32(acc[mt][nt], af[mt], bf[nt]);
        }
        if (kt + 1 < NT) {
            int nb2 = 1 - buf;
#pragma unroll
            for (int j = 0; j < 8; j++) As[nb2][aRow][aK + j]  = f2tf32(aReg[j]);
#pragma unroll
            for (int j = 0; j < 8; j++) Bs[nb2][bRow][bCol + j] = f2tf32(bReg[j]);
        }
        __syncthreads();
    }

#pragma unroll
    for (int nt = 0; nt < 4; nt++) {
        int col = colBase + wc * 32 + nt * 8 + 2 * lc;
        if (col >= Nc) continue;
        float2 bb = make_float2(0.f, 0.f);
        if (BIAS) bb = *(const float2*)&bias[col];
#pragma unroll
        for (int mt = 0; mt < 4; mt++) {
            int row = rowBase + wr * 64 + mt * 16 + lr;
#pragma unroll
            for (int half = 0; half < 2; half++) {
                int rr = row + half * 8;
                if (rr < M) {
                    float ox = acc[mt][nt][half * 2]     + bb.x;
                    float oy = acc[mt][nt][half * 2 + 1] + bb.y;
                    if (RELU) { ox = fmaxf(ox, 0.f); oy = fmaxf(oy, 0.f); }
                    float2 o;
                    if (ROUND) {
                        o.x = __uint_as_float(f2tf32(ox));
                        o.y = __uint_as_float(f2tf32(oy));
                    } else { o.x = ox; o.y = oy; }
                    *(float2*)&C[(size_t)rr * Nc + col] = o;
                }
            }
        }
    }
}

// ---------------- persistent-A fused GEMM -----------------------------------
// grid (2, 782), 512 threads. blockIdx.x selects combo triple {0,1,2}/{3,4,5};
// c6 = seg*2 + colhalf. A tile 128x256 resident in smem (stride 260, LDSM
// conflict-free); B tiles [128 n][32 k] stream through a 3-stage ring.
#define ASTR2 260
#define BSTR 36
#define BT_W (128 * BSTR)
#define SMEMP ((128 * ASTR2 + 3 * BT_W) * 4)

__global__ void __launch_bounds__(512, 1) k_mma3p(
    const float* __restrict__ A,
    const float* __restrict__ Wh, const float* __restrict__ bh,
    const float* __restrict__ Wg,
    const float* __restrict__ Wl, const float* __restrict__ bl,
    float* __restrict__ h, float* __restrict__ hg, float* __restrict__ xl)
{
    extern __shared__ float sm[];
    uint32_t sbA = (uint32_t)__cvta_generic_to_shared(sm);
    uint32_t sbB = sbA + 128 * ASTR2 * 4;

    int tid  = threadIdx.x;
    int lane = tid & 31;
    int warp = tid >> 5;               // 0..15
    int wr = warp >> 2, wc = warp & 3; // 4x4 warp grid: 32-row x 32-col slabs
    int lr = lane >> 2, lc = lane & 3;
    int rowBase = blockIdx.y * GBM;
    int comboBase = blockIdx.x * 3;

    // --- A load: thread t -> row t>>2, interleaved 16B chunks ---
    int arow = tid >> 2;
    int aq = tid & 3;
    bool okA = (rowBase + arow) < NN;
    {
        const float* gA = A + (size_t)(rowBase + arow) * DD;
        uint32_t sa = sbA + (arow * ASTR2) * 4;
#pragma unroll
        for (int j = 0; j < 16; j++) {
            int c = (aq + j * 4) * 4;      // word offset, banks spread
            cpa16(sa + c * 4, gA + c, okA);
        }
    }
    CP_COMMIT();                            // A = one group

    // --- B stream setup: thread t -> n-row t>>2, 2x16B chunks ---
    int brow = tid >> 2;
    int bq = tid & 3;

#define ISSUEB(i, s)                                                           \
    do {                                                                       \
        int c6_ = comboBase + ((i) >> 3);                                      \
        int kt_ = (i) & 7;                                                     \
        int seg_ = c6_ >> 1;                                                   \
        const float* W_ = (seg_ == 0) ? Wh : (seg_ == 1 ? Wg : Wl);            \
        const float* gB = W_ + (size_t)((c6_ & 1) * 128 + brow) * DD           \
                             + kt_ * 32 + bq * 8;                              \
        uint32_t sb = sbB + (s) * BT_W * 4 + (brow * BSTR + bq * 8) * 4;       \
        cpa16(sb,      gB,     true);                                          \
        cpa16(sb + 16, gB + 4, true);                                          \
        CP_COMMIT();                                                           \
    } while (0)

    ISSUEB(0, 0);
    ISSUEB(1, 1);

    // ldmatrix per-lane offsets (words)
    int aOff = (wr * 32 + (lane & 7) + ((lane >> 3) & 1) * 8) * ASTR2 + (lane >> 4) * 4;
    int bOff = (wc * 32 + (lane & 7) + (lane >> 4) * 8) * BSTR + ((lane >> 3) & 1) * 4;

    float acc[2][4][4];

    const int NTI = 24;    // 3 combos x 8 k-tiles
    for (int i = 0; i < NTI; i++) {
        CP_WAIT1();
        __syncthreads();
        if (i + 2 < NTI) ISSUEB(i + 2, (i + 2) % 3);
        else CP_COMMIT();                 // keep group accounting draining

        int kt = i & 7;
        if (kt == 0) {
#pragma unroll
            for (int m = 0; m < 2; m++)
#pragma unroll
                for (int n = 0; n < 4; n++)
#pragma unroll
                    for (int r = 0; r < 4; r++) acc[m][n][r] = 0.f;
        }

        int s = i % 3;
        uint32_t bS = sbB + s * BT_W * 4 + bOff * 4;
        uint32_t aS = sbA + aOff * 4;
#pragma unroll
        for (int ks = 0; ks < 4; ks++) {
            int ko = kt * 32 + ks * 8;
            uint32_t af[2][4], bf[4][2];
            LDSM4(af[0][0], af[0][1], af[0][2], af[0][3], aS + ko * 4);
            LDSM4(af[1][0], af[1][1], af[1][2], af[1][3],
                  aS + (16 * ASTR2 + ko) * 4);
            LDSM4(bf[0][0], bf[0][1], bf[1][0], bf[1][1], bS + (ks * 8) * 4);
            LDSM4(bf[2][0], bf[2][1], bf[3][0], bf[3][1],
                  bS + (16 * BSTR + ks * 8) * 4);
#pragma unroll
            for (int mt = 0; mt < 2; mt++)
#pragma unroll
                for (int nt = 0; nt < 4; nt++)
                    mma_tf32(acc[mt][nt], af[mt], bf[nt]);
        }

        if (kt == 7) {
            int c6 = comboBase + (i >> 3);
            int seg = c6 >> 1;
            int colhalf = c6 & 1;
            bool relu = (seg == 0);
            bool hasBias = (seg != 1);
            const float* bias = (seg == 0) ? bh : bl;
            float* C = (seg == 0) ? h : (seg == 1 ? hg : xl);
#pragma unroll
            for (int nt = 0; nt < 4; nt++) {
                int col = colhalf * 128 + wc * 32 + nt * 8 + 2 * lc;
                float2 bb = make_float2(0.f, 0.f);
                if (hasBias) bb = *(const float2*)&bias[col];
#pragma unroll
                for (int mt = 0; mt < 2; mt++) {
                    int row2 = rowBase + wr * 32 + mt * 16 + lr;
#pragma unroll
                    for (int half = 0; half < 2; half++) {
                        int rr = row2 + half * 8;
                        if (rr < NN) {
                            float2 o;
                            o.x = acc[mt][nt][half * 2]     + bb.x;
                            o.y = acc[mt][nt][half * 2 + 1] + bb.y;
                            if (relu) { o.x = fmaxf(o.x, 0.f); o.y = fmaxf(o.y, 0.f); }
                            *(float2*)&C[(size_t)rr * DD + col] = o;
                        }
                    }
                }
            }
        }
    }
#undef ISSUEB
}

// ---------------- attention scalars: a_src/a_dst [N,H] ----------------------
__global__ void k_attn(const float* __restrict__ ws, const float* __restrict__ wd) {
    int w = (blockIdx.x * blockDim.x + threadIdx.x) >> 5;
    int lane = threadIdx.x & 31;
    if (w >= NN * HH) return;
    int n = w >> 2, h = w & 3;
    float2 v = *(const float2*)&g_hg[(size_t)n * DD + h * 64 + lane * 2];
    float2 a = *(const float2*)&ws[h * 64 + lane * 2];
    float2 b = *(const float2*)&wd[h * 64 + lane * 2];
    float ps = v.x * a.x + v.y * a.y;
    float pd = v.x * b.x + v.y * b.y;
#pragma unroll
    for (int o = 16; o; o >>= 1) {
        ps += __shfl_xor_sync(0xFFFFFFFFu, ps, o);
        pd += __shfl_xor_sync(0xFFFFFFFFu, pd, o);
    }
    if (lane == 0) { g_asrc[n * 4 + h] = ps; g_adst[n * 4 + h] = pd; }
}

// ---------------- GAT + combine fused: warp per node ------------------------
__device__ __forceinline__ float pick4(float4 v, int h) {
    float r = v.x;
    r = (h == 1) ? v.y : r;
    r = (h == 2) ? v.z : r;
    r = (h == 3) ? v.w : r;
    return r;
}

__global__ void __launch_bounds__(256) k_gatc(
    const float* __restrict__ bg, const float* __restrict__ lng,
    const float* __restrict__ lnb, const float* __restrict__ betas, int first)
{
    int w = (blockIdx.x * blockDim.x + threadIdx.x) >> 5;
    int lane = threadIdx.x & 31;
    if (w >= NN) return;
    int n = w;
    int h = lane >> 3;
    int colb = lane * 8;

    int beg = g_rowptr[n], end = g_rowptr[n + 1];
    float4 ad4 = *(const float4*)&g_adst[n * 4];
    float adv = pick4(ad4, h);

    float m = -1e30f, s = 0.f;
    float4 acc0 = make_float4(0,0,0,0), acc1 = make_float4(0,0,0,0);

    for (int e = beg; e < end; e++) {
        int src = g_srcs[e];
        float4 as4 = *(const float4*)&g_asrc[src * 4];
        float ev = pick4(as4, h) + adv;
        ev = ev > 0.f ? ev : NEG_SLOPE * ev;
        float nm = fmaxf(m, ev);
        float sc = __expf(m - nm);
        float wg = __expf(ev - nm);
        m = nm;
        s = fmaf(s, sc, wg);
        const float4* hv = (const float4*)&g_hg[(size_t)src * DD + colb];
        float4 v0 = hv[0], v1 = hv[1];
        acc0.x = fmaf(wg, v0.x, acc0.x * sc);
        acc0.y = fmaf(wg, v0.y, acc0.y * sc);
        acc0.z = fmaf(wg, v0.z, acc0.z * sc);
        acc0.w = fmaf(wg, v0.w, acc0.w * sc);
        acc1.x = fmaf(wg, v1.x, acc1.x * sc);
        acc1.y = fmaf(wg, v1.y, acc1.y * sc);
        acc1.z = fmaf(wg, v1.z, acc1.z * sc);
        acc1.w = fmaf(wg, v1.w, acc1.w * sc);
    }
    float inv = 1.f / s;
    size_t idx = (size_t)n * DD + colb;
    float4 b0 = *(const float4*)&bg[colb];
    float4 b1 = *(const float4*)&bg[colb + 4];
    float4 x0 = *(const float4*)&g_xl[idx];
    float4 x1 = *(const float4*)&g_xl[idx + 4];

    float xn[8];
    xn[0] = fmaxf(fmaf(acc0.x, inv, b0.x + x0.x), 0.f);
    xn[1] = fmaxf(fmaf(acc0.y, inv, b0.y + x0.y), 0.f);
    xn[2] = fmaxf(fmaf(acc0.z, inv, b0.z + x0.z), 0.f);
    xn[3] = fmaxf(fmaf(acc0.w, inv, b0.w + x0.w), 0.f);
    xn[4] = fmaxf(fmaf(acc1.x, inv, b1.x + x1.x), 0.f);
    xn[5] = fmaxf(fmaf(acc1.y, inv, b1.y + x1.y), 0.f);
    xn[6] = fmaxf(fmaf(acc1.z, inv, b1.z + x1.z), 0.f);
    xn[7] = fmaxf(fmaf(acc1.w, inv, b1.w + x1.w), 0.f);

    // ---- fused combine: x = (1-beta)*LN(h*xn) + beta*xn ; xloc += x ----
    float4 h0 = *(const float4*)&g_h[idx];
    float4 h1 = *(const float4*)&g_h[idx + 4];
    float t[8] = {h0.x * xn[0], h0.y * xn[1], h0.z * xn[2], h0.w * xn[3],
                  h1.x * xn[4], h1.y * xn[5], h1.z * xn[6], h1.w * xn[7]};

    float sum = 0.f, sq = 0.f;
#pragma unroll
    for (int i = 0; i < 8; i++) { sum += t[i]; sq += t[i] * t[i]; }
#pragma unroll
    for (int o = 16; o; o >>= 1) {
        sum += __shfl_xor_sync(0xFFFFFFFFu, sum, o);
        sq  += __shfl_xor_sync(0xFFFFFFFFu, sq,  o);
    }
    float mean = sum * (1.f / DD);
    float var = sq * (1.f / DD) - mean * mean;
    float rs = rsqrtf(var + LNEPS);

    float4 lg0 = *(const float4*)&lng[colb];
    float4 lg1 = *(const float4*)&lng[colb + 4];
    float4 lb0 = *(const float4*)&lnb[colb];
    float4 lb1 = *(const float4*)&lnb[colb + 4];
    float4 be0 = *(const float4*)&betas[colb];
    float4 be1 = *(const float4*)&betas[colb + 4];
    float lg[8] = {lg0.x, lg0.y, lg0.z, lg0.w, lg1.x, lg1.y, lg1.z, lg1.w};
    float lb[8] = {lb0.x, lb0.y, lb0.z, lb0.w, lb1.x, lb1.y, lb1.z, lb1.w};
    float bev[8] = {be0.x, be0.y, be0.z, be0.w, be1.x, be1.y, be1.z, be1.w};

    float out[8];
#pragma unroll
    for (int i = 0; i < 8; i++) {
        float ln = (t[i] - mean) * rs * lg[i] + lb[i];
        float be = 1.f / (1.f + __expf(-bev[i]));
        out[i] = (1.f - be) * ln + be * xn[i];
    }

    // g_x rounded to tf32 (next GEMM input); xloc full precision
    float4 r0, r1;
    r0.x = __uint_as_float(f2tf32(out[0]));
    r0.y = __uint_as_float(f2tf32(out[1]));
    r0.z = __uint_as_float(f2tf32(out[2]));
    r0.w = __uint_as_float(f2tf32(out[3]));
    r1.x = __uint_as_float(f2tf32(out[4]));
    r1.y = __uint_as_float(f2tf32(out[5]));
    r1.z = __uint_as_float(f2tf32(out[6]));
    r1.w = __uint_as_float(f2tf32(out[7]));
    *(float4*)&g_x[idx]     = r0;
    *(float4*)&g_x[idx + 4] = r1;

    float4 o0 = make_float4(out[0], out[1], out[2], out[3]);
    float4 o1 = make_float4(out[4], out[5], out[6], out[7]);
    if (first) {
        *(float4*)&g_xloc[idx]     = o0;
        *(float4*)&g_xloc[idx + 4] = o1;
    } else {
        float4 l0 = *(float4*)&g_xloc[idx];
        float4 l1 = *(float4*)&g_xloc[idx + 4];
        l0.x += o0.x; l0.y += o0.y; l0.z += o0.z; l0.w += o0.w;
        l1.x += o1.x; l1.y += o1.y; l1.z += o1.z; l1.w += o1.w;
        *(float4*)&g_xloc[idx]     = l0;
        *(float4*)&g_xloc[idx + 4] = l1;
    }
}

// ---------------- driver -----------------------------------------------------
extern "C" void kernel_launch(void* const* d_in, const int* in_sizes, int n_in,
                              void* d_out, int out_size) {
    const float* x_in   = (const float*)d_in[0];
    const int*   ei     = (const int*)  d_in[1];
    const float* Win    = (const float*)d_in[2];
    const float* b_in   = (const float*)d_in[3];
    const float* Wh     = (const float*)d_in[4];
    const float* bh     = (const float*)d_in[5];
    const float* Wg     = (const float*)d_in[6];
    const float* attS   = (const float*)d_in[7];
    const float* attD   = (const float*)d_in[8];
    const float* bg     = (const float*)d_in[9];
    const float* Wl     = (const float*)d_in[10];
    const float* bl     = (const float*)d_in[11];
    const float* lng    = (const float*)d_in[12];
    const float* lnb    = (const float*)d_in[13];
    const float* betas  = (const float*)d_in[14];
    const float* Wp     = (const float*)d_in[15];
    const float* bp     = (const float*)d_in[16];
    float* out = (float*)d_out;

    cudaFuncSetAttribute(k_mma3p, cudaFuncAttributeMaxDynamicSharedMemorySize, SMEMP);

    float* px;   cudaGetSymbolAddress((void**)&px,   g_x);
    float* ph;   cudaGetSymbolAddress((void**)&ph,   g_h);
    float* phg;  cudaGetSymbolAddress((void**)&phg,  g_hg);
    float* pxl;  cudaGetSymbolAddress((void**)&pxl,  g_xl);
    float* pxlo; cudaGetSymbolAddress((void**)&pxlo, g_xloc);
    float* pwr;  cudaGetSymbolAddress((void**)&pwr,  g_wr);

    const float* rWh = pwr;
    const float* rWg = pwr + 196608;
    const float* rWl = pwr + 393216;

    dim3 gA(DD / GBN, cdiv(NN, GBM));   // (2, 782)
    dim3 gF(2, cdiv(NN, GBM));          // (2, 782): combo-halves on x

    // 1: weight pre-round+transpose, 2: input GEMM, 3: init, 4: layer-0 fused GEMM
    k_round<<<cdiv(589824, 256), 256>>>(Wh, Wg, Wl);
    k_mma<false, true, true><<<gA, 256>>>(x_in, Win, b_in, px, NN, DD, DD);
    k_init_cnt<<<cdiv(NN, 256), 256>>>();
    k_mma3p<<<gF, 512, SMEMP>>>(px, rWh, bh, rWg, rWl, bl, ph, phg, pxl);

    // CSR build
    k_hist<<<cdiv(EE, 256), 256>>>(ei);
    int nb = cdiv(NN, 1024);
    k_scan1<<<nb, 1024>>>();
    k_scan2<<<1, 32>>>(nb);
    k_scan3<<<cdiv(NN, 256), 256>>>();
    k_scatter<<<cdiv(EE + NN, 256), 256>>>(ei);

    for (int i = 0; i < 3; i++) {
        if (i > 0) {
            k_mma3p<<<gF, 512, SMEMP>>>(px, rWh + i * 65536, bh + i * DD,
                                        rWg + i * 65536, rWl + i * 65536, bl + i * DD,
                                        ph, phg, pxl);
        }
        k_attn<<<cdiv(NN * HH * 32, 256), 256>>>(attS + i * DD, attD + i * DD);
        k_gatc<<<cdiv(NN * 32, 256), 256>>>(bg + i * DD, lng + i * DD,
                                            lnb + i * DD, betas + i * DD, i == 0);
    }

    // out = xloc @ Wp + bp
    dim3 gO(1, cdiv(NN, GBM));
    k_mma<false, true, false><<<gO, 256>>>(pxlo, Wp, bp, out, NN, DD, OUTD);
}

// round 10
// speedup vs baseline: 1.0150x; 1.0150x over previous
#include <cuda_runtime.h>
#include <cstdint>

// ----------------------------------------------------------------------------
// Polynormer forward: N=100000, E=1.6M, D=256, H=4, C=64, L=3, OUT=64
// R10: GEMM reverted to R8 k_mma3a (persistent-A experiment regressed);
//      GAT softmax -> two-pass (max, then exp-sum) with unroll-2 dual
//      accumulators: no serial rescale chain, 2 gathers in flight.
// ----------------------------------------------------------------------------

#define NN 100000
#define EE 1600000
#define DD 256
#define HH 4
#define OUTD 64
#define NEG_SLOPE 0.2f
#define LNEPS 1e-5f

// ---------------- scratch (device globals; allocation-free) -----------------
__device__ float g_x   [NN * DD];
__device__ float g_h   [NN * DD];
__device__ float g_hg  [NN * DD];
__device__ float g_xl  [NN * DD];
__device__ float g_xloc[NN * DD];
__device__ float g_wr  [3 * 196608];      // tf32-rounded, TRANSPOSED [n][k] Wh|Wg|Wl
__device__ float g_asrc[NN * HH];
__device__ float g_adst[NN * HH];
__device__ int   g_cnt   [NN];
__device__ int   g_rowptr[NN + 1];
__device__ int   g_cursor[NN];
__device__ int   g_srcs  [EE + NN];
__device__ int   g_bsum[128];
__device__ int   g_boff[128];

static inline int cdiv(int a, int b) { return (a + b - 1) / b; }

__device__ __forceinline__ uint32_t f2tf32(float f) {
    uint32_t u;
    asm("cvt.rna.tf32.f32 %0, %1;" : "=r"(u) : "f"(f));
    return u;
}

// ---------------- CSR build --------------------------------------------------
__global__ void k_init_cnt() {
    int i = blockIdx.x * blockDim.x + threadIdx.x;
    if (i < NN) g_cnt[i] = 1;  // self loop
}

__global__ void k_hist(const int* __restrict__ ei) {
    int i = blockIdx.x * blockDim.x + threadIdx.x;
    if (i < EE) atomicAdd(&g_cnt[ei[EE + i]], 1);
}

__global__ void k_scan1() {
    __shared__ int sh[1024];
    int t = threadIdx.x, b = blockIdx.x;
    int idx = b * 1024 + t;
    int v = (idx < NN) ? g_cnt[idx] : 0;
    sh[t] = v;
    for (int off = 1; off < 1024; off <<= 1) {
        __syncthreads();
        int u = (t >= off) ? sh[t - off] : 0;
        __syncthreads();
        sh[t] += u;
    }
    if (idx < NN) g_rowptr[idx + 1] = sh[t];
    if (t == 1023) g_bsum[b] = sh[t];
}

__global__ void k_scan2(int nb) {
    if (threadIdx.x == 0 && blockIdx.x == 0) {
        int acc = 0;
        for (int i = 0; i < nb; i++) { g_boff[i] = acc; acc += g_bsum[i]; }
    }
}

__global__ void k_scan3() {
    int idx = blockIdx.x * blockDim.x + threadIdx.x;
    if (idx == 0) { g_rowptr[0] = 0; g_cursor[0] = 0; }
    if (idx < NN) {
        int v = g_rowptr[idx + 1] + g_boff[idx >> 10];
        g_rowptr[idx + 1] = v;
        if (idx + 1 < NN) g_cursor[idx + 1] = v;
    }
}

__global__ void k_scatter(const int* __restrict__ ei) {
    int idx = blockIdx.x * blockDim.x + threadIdx.x;
    int src, dst;
    if (idx < EE)            { src = ei[idx]; dst = ei[EE + idx]; }
    else if (idx < EE + NN)  { src = idx - EE; dst = src; }
    else return;
    int pos = atomicAdd(&g_cursor[dst], 1);
    g_srcs[pos] = src;
}

// ---------------- weight pre-round + transpose to [n][k] --------------------
__global__ void k_round(const float* __restrict__ Wh, const float* __restrict__ Wg,
                        const float* __restrict__ Wl) {
    int t = blockIdx.x * blockDim.x + threadIdx.x;    // float index
    if (t >= 589824) return;                           // 9 matrices of 256x256
    int m = t >> 16;                                   // matrix 0..8
    int o = t & 65535;
    int n = o >> 8, k = o & 255;
    const float* src = (m < 3) ? (Wh + m * 65536)
                     : (m < 6) ? (Wg + (m - 3) * 65536)
                               : (Wl + (m - 6) * 65536);
    float v = src[k * 256 + n];
    g_wr[t] = __uint_as_float(f2tf32(v));
}

// ---------------- MMA primitives ---------------------------------------------
#define GBM 128
#define GBN 128
#define GBK 16

__device__ __forceinline__ void mma_tf32(float* d, const uint32_t* a, const uint32_t* b) {
    asm volatile(
        "mma.sync.aligned.m16n8k8.row.col.f32.tf32.tf32.f32 "
        "{%0,%1,%2,%3}, {%4,%5,%6,%7}, {%8,%9}, {%0,%1,%2,%3};\n"
        : "+f"(d[0]), "+f"(d[1]), "+f"(d[2]), "+f"(d[3])
        : "r"(a[0]), "r"(a[1]), "r"(a[2]), "r"(a[3]), "r"(b[0]), "r"(b[1]));
}

__device__ __forceinline__ void cpa16(uint32_t sa, const void* g, bool p) {
    int sz = p ? 16 : 0;
    asm volatile("cp.async.cg.shared.global [%0], [%1], 16, %2;\n"
                 :: "r"(sa), "l"(g), "r"(sz) : "memory");
}
#define CP_COMMIT() asm volatile("cp.async.commit_group;\n" ::: "memory")
#define CP_WAIT1()  asm volatile("cp.async.wait_group 1;\n" ::: "memory")

#define LDSM4(r0, r1, r2, r3, addr)                                            \
    asm volatile("ldmatrix.sync.aligned.m8n8.x4.shared.b16 {%0,%1,%2,%3}, [%4];" \
                 : "=r"(r0), "=r"(r1), "=r"(r2), "=r"(r3) : "r"(addr))

// ---------------- legacy GEMM (cvt path) for input/output GEMMs --------------
template <bool RELU, bool BIAS, bool ROUND>
__global__ void __launch_bounds__(256, 2) k_mma(
    const float* __restrict__ A, const float* __restrict__ B,
    const float* __restrict__ bias, float* __restrict__ C,
    int M, int K, int Nc)
{
    __shared__ uint32_t As[2][GBM][GBK + 4];
    __shared__ uint32_t Bs[2][GBK][GBN + 8];

    int tid  = threadIdx.x;
    int lane = tid & 31;
    int warp = tid >> 5;
    int wr = warp >> 2, wc = warp & 3;
    int lr = lane >> 2, lc = lane & 3;
    int rowBase = blockIdx.y * GBM;
    int colBase = blockIdx.x * GBN;

    int aRow = tid >> 1;
    int aK   = (tid & 1) << 3;
    int bRow = tid >> 4;
    int bCol = (tid & 15) << 3;

    float acc[4][4][4];
#pragma unroll
    for (int m = 0; m < 4; m++)
#pragma unroll
        for (int n = 0; n < 4; n++)
#pragma unroll
            for (int r = 0; r < 4; r++) acc[m][n][r] = 0.f;

    float aReg[8], bReg[8];
    const int NT = K / GBK;

    {
        bool okA = (rowBase + aRow) < M;
        const float* pA = A + (size_t)(rowBase + aRow) * K + aK;
        float4 v0 = okA ? *(const float4*)pA       : make_float4(0,0,0,0);
        float4 v1 = okA ? *(const float4*)(pA + 4) : make_float4(0,0,0,0);
        aReg[0]=v0.x; aReg[1]=v0.y; aReg[2]=v0.z; aReg[3]=v0.w;
        aReg[4]=v1.x; aReg[5]=v1.y; aReg[6]=v1.z; aReg[7]=v1.w;
        bool okB = (colBase + bCol) < Nc;
        const float* pB = B + (size_t)bRow * Nc + colBase + bCol;
        float4 w0 = okB ? *(const float4*)pB       : make_float4(0,0,0,0);
        float4 w1 = okB ? *(const float4*)(pB + 4) : make_float4(0,0,0,0);
        bReg[0]=w0.x; bReg[1]=w0.y; bReg[2]=w0.z; bReg[3]=w0.w;
        bReg[4]=w1.x; bReg[5]=w1.y; bReg[6]=w1.z; bReg[7]=w1.w;
    }
#pragma unroll
    for (int j = 0; j < 8; j++) As[0][aRow][aK + j]  = f2tf32(aReg[j]);
#pragma unroll
    for (int j = 0; j < 8; j++) Bs[0][bRow][bCol + j] = f2tf32(bReg[j]);
    __syncthreads();

    for (int kt = 0; kt < NT; kt++) {
        int buf = kt & 1;
        if (kt + 1 < NT) {
            bool okA = (rowBase + aRow) < M;
            const float* pA = A + (size_t)(rowBase + aRow) * K + (kt + 1) * GBK + aK;
            float4 v0 = okA ? *(const float4*)pA       : make_float4(0,0,0,0);
            float4 v1 = okA ? *(const float4*)(pA + 4) : make_float4(0,0,0,0);
            aReg[0]=v0.x; aReg[1]=v0.y; aReg[2]=v0.z; aReg[3]=v0.w;
            aReg[4]=v1.x; aReg[5]=v1.y; aReg[6]=v1.z; aReg[7]=v1.w;
            bool okB = (colBase + bCol) < Nc;
            const float* pB = B + (size_t)((kt + 1) * GBK + bRow) * Nc + colBase + bCol;
            float4 w0 = okB ? *(const float4*)pB       : make_float4(0,0,0,0);
            float4 w1 = okB ? *(const float4*)(pB + 4) : make_float4(0,0,0,0);
            bReg[0]=w0.x; bReg[1]=w0.y; bReg[2]=w0.z; bReg[3]=w0.w;
            bReg[4]=w1.x; bReg[5]=w1.y; bReg[6]=w1.z; bReg[7]=w1.w;
        }
#pragma unroll
        for (int ks = 0; ks < 2; ks++) {
            int kb = ks * 8;
            uint32_t af[4][4], bf[4][2];
#pragma unroll
            for (int mt = 0; mt < 4; mt++) {
                int r = wr * 64 + mt * 16 + lr;
                af[mt][0] = As[buf][r    ][kb + lc];
                af[mt][1] = As[buf][r + 8][kb + lc];
                af[mt][2] = As[buf][r    ][kb + lc + 4];
                af[mt][3] = As[buf][r + 8][kb + lc + 4];
            }
#pragma unroll
            for (int nt = 0; nt < 4; nt++) {
                int c = wc * 32 + nt * 8 + lr;
                bf[nt][0] = Bs[buf][kb + lc    ][c];
                bf[nt][1] = Bs[buf][kb + lc + 4][c];
            }
#pragma unroll
            for (int mt = 0; mt < 4; mt++)
#pragma unroll
                for (int nt = 0; nt < 4; nt++)
                    mma_tf32(acc[mt][nt], af[mt], bf[nt]);
        }
        if (kt + 1 < NT) {
            int nb2 = 1 - buf;
#pragma unroll
            for (int j = 0; j < 8; j++) As[nb2][aRow][aK + j]  = f2tf32(aReg[j]);
#pragma unroll
            for (int j = 0; j < 8; j++) Bs[nb2][bRow][bCol + j] = f2tf32(bReg[j]);
        }
        __syncthreads();
    }

#pragma unroll
    for (int nt = 0; nt < 4; nt++) {
        int col = colBase + wc * 32 + nt * 8 + 2 * lc;
        if (col >= Nc) continue;
        float2 bb = make_float2(0.f, 0.f);
        if (BIAS) bb = *(const float2*)&bias[col];
#pragma unroll
        for (int mt = 0; mt < 4; mt++) {
            int row = rowBase + wr * 64 + mt * 16 + lr;
#pragma unroll
            for (int half = 0; half < 2; half++) {
                int rr = row + half * 8;
                if (rr < M) {
                    float ox = acc[mt][nt][half * 2]     + bb.x;
                    float oy = acc[mt][nt][half * 2 + 1] + bb.y;
                    if (RELU) { ox = fmaxf(ox, 0.f); oy = fmaxf(oy, 0.f); }
                    float2 o;
                    if (ROUND) {
                        o.x = __uint_as_float(f2tf32(ox));
                        o.y = __uint_as_float(f2tf32(oy));
                    } else { o.x = ox; o.y = oy; }
                    *(float2*)&C[(size_t)rr * Nc + col] = o;
                }
            }
        }
    }
}

// ---------------- fused 3-GEMM, cp.async + ldmatrix, GBK=32 (R8 best) -------
#define GBK3 32
#define ST 3
#define TSTR 36
#define TILE_W (128 * TSTR)
#define SMEM3 (2 * ST * TILE_W * 4)

__global__ void __launch_bounds__(256, 2) k_mma3a(
    const float* __restrict__ A,
    const float* __restrict__ Wh, const float* __restrict__ bh,
    const float* __restrict__ Wg,
    const float* __restrict__ Wl, const float* __restrict__ bl,
    float* __restrict__ h, float* __restrict__ hg, float* __restrict__ xl)
{
    extern __shared__ float sm[];
    uint32_t sbA = (uint32_t)__cvta_generic_to_shared(sm);
    uint32_t sbB = sbA + ST * TILE_W * 4;

    int tid  = threadIdx.x;
    int lane = tid & 31;
    int warp = tid >> 5;
    int wr = warp >> 2, wc = warp & 3;
    int lr = lane >> 2, lc = lane & 3;
    int rowBase = blockIdx.y * GBM;
    int seg = blockIdx.x >> 1;
    int colBase = (blockIdx.x & 1) * GBN;
    const float* B = (seg == 0) ? Wh : (seg == 1 ? Wg : Wl);

    int row = tid >> 1;
    int kq  = (tid & 1) * 16;
    bool okA = (rowBase + row) < NN;
    const float* gA0 = A + (size_t)(rowBase + row) * DD + kq;
    const float* gB0 = B + (size_t)(colBase + row) * DD + kq;
    uint32_t saBase = ((row * TSTR + kq) * 4);
    int aOff = (wr * 64 + (lane & 7) + ((lane >> 3) & 1) * 8) * TSTR + (lane >> 4) * 4;
    int bOff = (wc * 32 + (lane & 7) + (lane >> 4) * 8) * TSTR + ((lane >> 3) & 1) * 4;

    float acc[4][4][4];
#pragma unroll
    for (int m = 0; m < 4; m++)
#pragma unroll
        for (int n = 0; n < 4; n++)
#pragma unroll
            for (int r = 0; r < 4; r++) acc[m][n][r] = 0.f;

#define ISSUE(kt, s)                                                            \
    do {                                                                        \
        const float* gA = gA0 + (kt) * GBK3;                                    \
        uint32_t sa = sbA + (s) * TILE_W * 4 + saBase;                          \
        cpa16(sa,      gA,      okA);                                           \
        cpa16(sa + 16, gA + 4,  okA);                                           \
        cpa16(sa + 32, gA + 8,  okA);                                           \
        cpa16(sa + 48, gA + 12, okA);                                           \
        const float* gB = gB0 + (kt) * GBK3;                                    \
        uint32_t sb = sbB + (s) * TILE_W * 4 + saBase;                          \
        cpa16(sb,      gB,      true);                                          \
        cpa16(sb + 16, gB + 4,  true);                                          \
        cpa16(sb + 32, gB + 8,  true);                                          \
        cpa16(sb + 48, gB + 12, true);                                          \
        CP_COMMIT();                                                            \
    } while (0)

    ISSUE(0, 0);
    ISSUE(1, 1);

    const int NT = DD / GBK3;   // 8
    for (int kt = 0; kt < NT; kt++) {
        CP_WAIT1();
        __syncthreads();
        if (kt + 2 < NT) {
            int s2 = (kt + 2) % ST;
            ISSUE(kt + 2, s2);
        } else {
            CP_COMMIT();
        }
        int s = kt % ST;
        uint32_t aS = sbA + s * TILE_W * 4 + aOff * 4;
        uint32_t bS = sbB + s * TILE_W * 4 + bOff * 4;
#pragma unroll
        for (int ks = 0; ks < 4; ks++) {
            uint32_t af[4][4], bf[4][2];
#pragma unroll
            for (int mt = 0; mt < 4; mt++)
                LDSM4(af[mt][0], af[mt][1], af[mt][2], af[mt][3],
                      aS + (mt * 16 * TSTR + ks * 8) * 4);
            LDSM4(bf[0][0], bf[0][1], bf[1][0], bf[1][1], bS + (ks * 8) * 4);
            LDSM4(bf[2][0], bf[2][1], bf[3][0], bf[3][1],
                  bS + (16 * TSTR + ks * 8) * 4);
#pragma unroll
            for (int mt = 0; mt < 4; mt++)
#pragma unroll
                for (int nt = 0; nt < 4; nt++)
                    mma_tf32(acc[mt][nt], af[mt], bf[nt]);
        }
    }
#undef ISSUE

    bool relu = (seg == 0);
    bool hasBias = (seg != 1);
    const float* bias = (seg == 0) ? bh : bl;
    float* C = (seg == 0) ? h : (seg == 1 ? hg : xl);
#pragma unroll
    for (int nt = 0; nt < 4; nt++) {
        int col = colBase + wc * 32 + nt * 8 + 2 * lc;
        float2 bb = make_float2(0.f, 0.f);
        if (hasBias) bb = *(const float2*)&bias[col];
#pragma unroll
        for (int mt = 0; mt < 4; mt++) {
            int row2 = rowBase + wr * 64 + mt * 16 + lr;
#pragma unroll
            for (int half = 0; half < 2; half++) {
                int rr = row2 + half * 8;
                if (rr < NN) {
                    float2 o;
                    o.x = acc[mt][nt][half * 2]     + bb.x;
                    o.y = acc[mt][nt][half * 2 + 1] + bb.y;
                    if (relu) { o.x = fmaxf(o.x, 0.f); o.y = fmaxf(o.y, 0.f); }
                    *(float2*)&C[(size_t)rr * DD + col] = o;
                }
            }
        }
    }
}

// ---------------- attention scalars: a_src/a_dst [N,H] ----------------------
__global__ void k_attn(const float* __restrict__ ws, const float* __restrict__ wd) {
    int w = (blockIdx.x * blockDim.x + threadIdx.x) >> 5;
    int lane = threadIdx.x & 31;
    if (w >= NN * HH) return;
    int n = w >> 2, h = w & 3;
    float2 v = *(const float2*)&g_hg[(size_t)n * DD + h * 64 + lane * 2];
    float2 a = *(const float2*)&ws[h * 64 + lane * 2];
    float2 b = *(const float2*)&wd[h * 64 + lane * 2];
    float ps = v.x * a.x + v.y * a.y;
    float pd = v.x * b.x + v.y * b.y;
#pragma unroll
    for (int o = 16; o; o >>= 1) {
        ps += __shfl_xor_sync(0xFFFFFFFFu, ps, o);
        pd += __shfl_xor_sync(0xFFFFFFFFu, pd, o);
    }
    if (lane == 0) { g_asrc[n * 4 + h] = ps; g_adst[n * 4 + h] = pd; }
}

// ---------------- GAT + combine fused: warp per node, two-pass softmax ------
__device__ __forceinline__ float pick4(float4 v, int h) {
    float r = v.x;
    r = (h == 1) ? v.y : r;
    r = (h == 2) ? v.z : r;
    r = (h == 3) ? v.w : r;
    return r;
}

__global__ void __launch_bounds__(256) k_gatc(
    const float* __restrict__ bg, const float* __restrict__ lng,
    const float* __restrict__ lnb, const float* __restrict__ betas, int first)
{
    int w = (blockIdx.x * blockDim.x + threadIdx.x) >> 5;
    int lane = threadIdx.x & 31;
    if (w >= NN) return;
    int n = w;
    int h = lane >> 3;
    int colb = lane * 8;

    int beg = g_rowptr[n], end = g_rowptr[n + 1];
    float4 ad4 = *(const float4*)&g_adst[n * 4];
    float adv = pick4(ad4, h);

    // ---- pass 1: max of leaky(e) over edges (cheap 16B gathers) ----
    float m = -1e30f;
#pragma unroll 4
    for (int e = beg; e < end; e++) {
        int src = g_srcs[e];
        float4 as4 = *(const float4*)&g_asrc[src * 4];
        float ev = pick4(as4, h) + adv;
        ev = ev > 0.f ? ev : NEG_SLOPE * ev;
        m = fmaxf(m, ev);
    }

    // ---- pass 2: exp-weighted sum, no rescale chain, unroll 2 ----
    float sA = 0.f, sB = 0.f;
    float4 p0 = make_float4(0,0,0,0), p1 = make_float4(0,0,0,0);
    float4 q0 = make_float4(0,0,0,0), q1 = make_float4(0,0,0,0);
    int e = beg;
    for (; e + 1 < end; e += 2) {
        int srcA = g_srcs[e], srcB = g_srcs[e + 1];
        float4 aA = *(const float4*)&g_asrc[srcA * 4];
        float4 aB = *(const float4*)&g_asrc[srcB * 4];
        const float4* hvA = (const float4*)&g_hg[(size_t)srcA * DD + colb];
        const float4* hvB = (const float4*)&g_hg[(size_t)srcB * DD + colb];
        float4 vA0 = hvA[0], vA1 = hvA[1];
        float4 vB0 = hvB[0], vB1 = hvB[1];
        float evA = pick4(aA, h) + adv;
        evA = evA > 0.f ? evA : NEG_SLOPE * evA;
        float evB = pick4(aB, h) + adv;
        evB = evB > 0.f ? evB : NEG_SLOPE * evB;
        float wA = __expf(evA - m);
        float wB = __expf(evB - m);
        sA += wA; sB += wB;
        p0.x = fmaf(wA, vA0.x, p0.x); p0.y = fmaf(wA, vA0.y, p0.y);
        p0.z = fmaf(wA, vA0.z, p0.z); p0.w = fmaf(wA, vA0.w, p0.w);
        p1.x = fmaf(wA, vA1.x, p1.x); p1.y = fmaf(wA, vA1.y, p1.y);
        p1.z = fmaf(wA, vA1.z, p1.z); p1.w = fmaf(wA, vA1.w, p1.w);
        q0.x = fmaf(wB, vB0.x, q0.x); q0.y = fmaf(wB, vB0.y, q0.y);
        q0.z = fmaf(wB, vB0.z, q0.z); q0.w = fmaf(wB, vB0.w, q0.w);
        q1.x = fmaf(wB, vB1.x, q1.x); q1.y = fmaf(wB, vB1.y, q1.y);
        q1.z = fmaf(wB, vB1.z, q1.z); q1.w = fmaf(wB, vB1.w, q1.w);
    }
    if (e < end) {
        int src = g_srcs[e];
        float4 a4 = *(const float4*)&g_asrc[src * 4];
        const float4* hv = (const float4*)&g_hg[(size_t)src * DD + colb];
        float4 v0 = hv[0], v1 = hv[1];
        float ev = pick4(a4, h) + adv;
        ev = ev > 0.f ? ev : NEG_SLOPE * ev;
        float wE = __expf(ev - m);
        sA += wE;
        p0.x = fmaf(wE, v0.x, p0.x); p0.y = fmaf(wE, v0.y, p0.y);
        p0.z = fmaf(wE, v0.z, p0.z); p0.w = fmaf(wE, v0.w, p0.w);
        p1.x = fmaf(wE, v1.x, p1.x); p1.y = fmaf(wE, v1.y, p1.y);
        p1.z = fmaf(wE, v1.z, p1.z); p1.w = fmaf(wE, v1.w, p1.w);
    }
    float s = sA + sB;
    float4 acc0, acc1;
    acc0.x = p0.x + q0.x; acc0.y = p0.y + q0.y;
    acc0.z = p0.z + q0.z; acc0.w = p0.w + q0.w;
    acc1.x = p1.x + q1.x; acc1.y = p1.y + q1.y;
    acc1.z = p1.z + q1.z; acc1.w = p1.w + q1.w;

    float inv = 1.f / s;
    size_t idx = (size_t)n * DD + colb;
    float4 b0 = *(const float4*)&bg[colb];
    float4 b1 = *(const float4*)&bg[colb + 4];
    float4 x0 = *(const float4*)&g_xl[idx];
    float4 x1 = *(const float4*)&g_xl[idx + 4];

    float xn[8];
    xn[0] = fmaxf(fmaf(acc0.x, inv, b0.x + x0.x), 0.f);
    xn[1] = fmaxf(fmaf(acc0.y, inv, b0.y + x0.y), 0.f);
    xn[2] = fmaxf(fmaf(acc0.z, inv, b0.z + x0.z), 0.f);
    xn[3] = fmaxf(fmaf(acc0.w, inv, b0.w + x0.w), 0.f);
    xn[4] = fmaxf(fmaf(acc1.x, inv, b1.x + x1.x), 0.f);
    xn[5] = fmaxf(fmaf(acc1.y, inv, b1.y + x1.y), 0.f);
    xn[6] = fmaxf(fmaf(acc1.z, inv, b1.z + x1.z), 0.f);
    xn[7] = fmaxf(fmaf(acc1.w, inv, b1.w + x1.w), 0.f);

    // ---- fused combine: x = (1-beta)*LN(h*xn) + beta*xn ; xloc += x ----
    float4 h0 = *(const float4*)&g_h[idx];
    float4 h1 = *(const float4*)&g_h[idx + 4];
    float t[8] = {h0.x * xn[0], h0.y * xn[1], h0.z * xn[2], h0.w * xn[3],
                  h1.x * xn[4], h1.y * xn[5], h1.z * xn[6], h1.w * xn[7]};

    float sum = 0.f, sq = 0.f;
#pragma unroll
    for (int i = 0; i < 8; i++) { sum += t[i]; sq += t[i] * t[i]; }
#pragma unroll
    for (int o = 16; o; o >>= 1) {
        sum += __shfl_xor_sync(0xFFFFFFFFu, sum, o);
        sq  += __shfl_xor_sync(0xFFFFFFFFu, sq,  o);
    }
    float mean = sum * (1.f / DD);
    float var = sq * (1.f / DD) - mean * mean;
    float rs = rsqrtf(var + LNEPS);

    float4 lg0 = *(const float4*)&lng[colb];
    float4 lg1 = *(const float4*)&lng[colb + 4];
    float4 lb0 = *(const float4*)&lnb[colb];
    float4 lb1 = *(const float4*)&lnb[colb + 4];
    float4 be0 = *(const float4*)&betas[colb];
    float4 be1 = *(const float4*)&betas[colb + 4];
    float lg[8] = {lg0.x, lg0.y, lg0.z, lg0.w, lg1.x, lg1.y, lg1.z, lg1.w};
    float lb[8] = {lb0.x, lb0.y, lb0.z, lb0.w, lb1.x, lb1.y, lb1.z, lb1.w};
    float bev[8] = {be0.x, be0.y, be0.z, be0.w, be1.x, be1.y, be1.z, be1.w};

    float out[8];
#pragma unroll
    for (int i = 0; i < 8; i++) {
        float ln = (t[i] - mean) * rs * lg[i] + lb[i];
        float be = 1.f / (1.f + __expf(-bev[i]));
        out[i] = (1.f - be) * ln + be * xn[i];
    }

    // g_x rounded to tf32 (next GEMM input); xloc full precision
    float4 r0, r1;
    r0.x = __uint_as_float(f2tf32(out[0]));
    r0.y = __uint_as_float(f2tf32(out[1]));
    r0.z = __uint_as_float(f2tf32(out[2]));
    r0.w = __uint_as_float(f2tf32(out[3]));
    r1.x = __uint_as_float(f2tf32(out[4]));
    r1.y = __uint_as_float(f2tf32(out[5]));
    r1.z = __uint_as_float(f2tf32(out[6]));
    r1.w = __uint_as_float(f2tf32(out[7]));
    *(float4*)&g_x[idx]     = r0;
    *(float4*)&g_x[idx + 4] = r1;

    float4 o0 = make_float4(out[0], out[1], out[2], out[3]);
    float4 o1 = make_float4(out[4], out[5], out[6], out[7]);
    if (first) {
        *(float4*)&g_xloc[idx]     = o0;
        *(float4*)&g_xloc[idx + 4] = o1;
    } else {
        float4 l0 = *(float4*)&g_xloc[idx];
        float4 l1 = *(float4*)&g_xloc[idx + 4];
        l0.x += o0.x; l0.y += o0.y; l0.z += o0.z; l0.w += o0.w;
        l1.x += o1.x; l1.y += o1.y; l1.z += o1.z; l1.w += o1.w;
        *(float4*)&g_xloc[idx]     = l0;
        *(float4*)&g_xloc[idx + 4] = l1;
    }
}

// ---------------- driver -----------------------------------------------------
extern "C" void kernel_launch(void* const* d_in, const int* in_sizes, int n_in,
                              void* d_out, int out_size) {
    const float* x_in   = (const float*)d_in[0];
    const int*   ei     = (const int*)  d_in[1];
    const float* Win    = (const float*)d_in[2];
    const float* b_in   = (const float*)d_in[3];
    const float* Wh     = (const float*)d_in[4];
    const float* bh     = (const float*)d_in[5];
    const float* Wg     = (const float*)d_in[6];
    const float* attS   = (const float*)d_in[7];
    const float* attD   = (const float*)d_in[8];
    const float* bg     = (const float*)d_in[9];
    const float* Wl     = (const float*)d_in[10];
    const float* bl     = (const float*)d_in[11];
    const float* lng    = (const float*)d_in[12];
    const float* lnb    = (const float*)d_in[13];
    const float* betas  = (const float*)d_in[14];
    const float* Wp     = (const float*)d_in[15];
    const float* bp     = (const float*)d_in[16];
    float* out = (float*)d_out;

    cudaFuncSetAttribute(k_mma3a, cudaFuncAttributeMaxDynamicSharedMemorySize, SMEM3);

    float* px;   cudaGetSymbolAddress((void**)&px,   g_x);
    float* ph;   cudaGetSymbolAddress((void**)&ph,   g_h);
    float* phg;  cudaGetSymbolAddress((void**)&phg,  g_hg);
    float* pxl;  cudaGetSymbolAddress((void**)&pxl,  g_xl);
    float* pxlo; cudaGetSymbolAddress((void**)&pxlo, g_xloc);
    float* pwr;  cudaGetSymbolAddress((void**)&pwr,  g_wr);

    const float* rWh = pwr;
    const float* rWg = pwr + 196608;
    const float* rWl = pwr + 393216;

    dim3 gA(DD / GBN, cdiv(NN, GBM));   // (2, 782)
    dim3 gF(6, cdiv(NN, GBM));          // (6, 782)

    // 1: weight pre-round+transpose, 2: input GEMM, 3: init, 4: layer-0 fused GEMM
    k_round<<<cdiv(589824, 256), 256>>>(Wh, Wg, Wl);
    k_mma<false, true, true><<<gA, 256>>>(x_in, Win, b_in, px, NN, DD, DD);
    k_init_cnt<<<cdiv(NN, 256), 256>>>();
    k_mma3a<<<gF, 256, SMEM3>>>(px, rWh, bh, rWg, rWl, bl, ph, phg, pxl);

    // CSR build
    k_hist<<<cdiv(EE, 256), 256>>>(ei);
    int nb = cdiv(NN, 1024);
    k_scan1<<<nb, 1024>>>();
    k_scan2<<<1, 32>>>(nb);
    k_scan3<<<cdiv(NN, 256), 256>>>();
    k_scatter<<<cdiv(EE + NN, 256), 256>>>(ei);

    for (int i = 0; i < 3; i++) {
        if (i > 0) {
            k_mma3a<<<gF, 256, SMEM3>>>(px, rWh + i * 65536, bh + i * DD,
                                        rWg + i * 65536, rWl + i * 65536, bl + i * DD,
                                        ph, phg, pxl);
        }
        k_attn<<<cdiv(NN * HH * 32, 256), 256>>>(attS + i * DD, attD + i * DD);
        k_gatc<<<cdiv(NN * 32, 256), 256>>>(bg + i * DD, lng + i * DD,
                                            lnb + i * DD, betas + i * DD, i == 0);
    }

    // out = xloc @ Wp + bp
    dim3 gO(1, cdiv(NN, GBM));
    k_mma<false, true, false><<<gO, 256>>>(pxlo, Wp, bp, out, NN, DD, OUTD);
}

// round 11
// speedup vs baseline: 1.0631x; 1.0474x over previous
#include <cuda_runtime.h>
#include <cstdint>

// ----------------------------------------------------------------------------
// Polynormer forward: N=100000, E=1.6M, D=256, H=4, C=64, L=3, OUT=64
// R11: gatc reverted to R8 online-softmax (two-pass regressed; L2-BW bound);
//      attention scalars computed in k_mma3a seg==1 epilogue from resident
//      accumulators (quad-shuffle partials -> g_attp, tiny k_attred reduce);
//      k_attn launches removed (saves 3 x 102MB hg re-reads).
// ----------------------------------------------------------------------------

#define NN 100000
#define EE 1600000
#define DD 256
#define HH 4
#define OUTD 64
#define NEG_SLOPE 0.2f
#define LNEPS 1e-5f

// ---------------- scratch (device globals; allocation-free) -----------------
__device__ float g_x   [NN * DD];
__device__ float g_h   [NN * DD];
__device__ float g_hg  [NN * DD];
__device__ float g_xl  [NN * DD];
__device__ float g_xloc[NN * DD];
__device__ float g_wr  [3 * 196608];      // tf32-rounded, TRANSPOSED [n][k] Wh|Wg|Wl
__device__ float g_asrc[NN * HH];
__device__ float g_adst[NN * HH];
__device__ float g_attp[NN * HH * 4];     // per-slab partials: [n][h][slab][src/dst]
__device__ int   g_cnt   [NN];
__device__ int   g_rowptr[NN + 1];
__device__ int   g_cursor[NN];
__device__ int   g_srcs  [EE + NN];
__device__ int   g_bsum[128];
__device__ int   g_boff[128];

static inline int cdiv(int a, int b) { return (a + b - 1) / b; }

__device__ __forceinline__ uint32_t f2tf32(float f) {
    uint32_t u;
    asm("cvt.rna.tf32.f32 %0, %1;" : "=r"(u) : "f"(f));
    return u;
}

// ---------------- CSR build --------------------------------------------------
__global__ void k_init_cnt() {
    int i = blockIdx.x * blockDim.x + threadIdx.x;
    if (i < NN) g_cnt[i] = 1;  // self loop
}

__global__ void k_hist(const int* __restrict__ ei) {
    int i = blockIdx.x * blockDim.x + threadIdx.x;
    if (i < EE) atomicAdd(&g_cnt[ei[EE + i]], 1);
}

__global__ void k_scan1() {
    __shared__ int sh[1024];
    int t = threadIdx.x, b = blockIdx.x;
    int idx = b * 1024 + t;
    int v = (idx < NN) ? g_cnt[idx] : 0;
    sh[t] = v;
    for (int off = 1; off < 1024; off <<= 1) {
        __syncthreads();
        int u = (t >= off) ? sh[t - off] : 0;
        __syncthreads();
        sh[t] += u;
    }
    if (idx < NN) g_rowptr[idx + 1] = sh[t];
    if (t == 1023) g_bsum[b] = sh[t];
}

__global__ void k_scan2(int nb) {
    if (threadIdx.x == 0 && blockIdx.x == 0) {
        int acc = 0;
        for (int i = 0; i < nb; i++) { g_boff[i] = acc; acc += g_bsum[i]; }
    }
}

__global__ void k_scan3() {
    int idx = blockIdx.x * blockDim.x + threadIdx.x;
    if (idx == 0) { g_rowptr[0] = 0; g_cursor[0] = 0; }
    if (idx < NN) {
        int v = g_rowptr[idx + 1] + g_boff[idx >> 10];
        g_rowptr[idx + 1] = v;
        if (idx + 1 < NN) g_cursor[idx + 1] = v;
    }
}

__global__ void k_scatter(const int* __restrict__ ei) {
    int idx = blockIdx.x * blockDim.x + threadIdx.x;
    int src, dst;
    if (idx < EE)            { src = ei[idx]; dst = ei[EE + idx]; }
    else if (idx < EE + NN)  { src = idx - EE; dst = src; }
    else return;
    int pos = atomicAdd(&g_cursor[dst], 1);
    g_srcs[pos] = src;
}

// ---------------- weight pre-round + transpose to [n][k] --------------------
__global__ void k_round(const float* __restrict__ Wh, const float* __restrict__ Wg,
                        const float* __restrict__ Wl) {
    int t = blockIdx.x * blockDim.x + threadIdx.x;    // float index
    if (t >= 589824) return;                           // 9 matrices of 256x256
    int m = t >> 16;                                   // matrix 0..8
    int o = t & 65535;
    int n = o >> 8, k = o & 255;
    const float* src = (m < 3) ? (Wh + m * 65536)
                     : (m < 6) ? (Wg + (m - 3) * 65536)
                               : (Wl + (m - 6) * 65536);
    float v = src[k * 256 + n];
    g_wr[t] = __uint_as_float(f2tf32(v));
}

// ---------------- MMA primitives ---------------------------------------------
#define GBM 128
#define GBN 128
#define GBK 16

__device__ __forceinline__ void mma_tf32(float* d, const uint32_t* a, const uint32_t* b) {
    asm volatile(
        "mma.sync.aligned.m16n8k8.row.col.f32.tf32.tf32.f32 "
        "{%0,%1,%2,%3}, {%4,%5,%6,%7}, {%8,%9}, {%0,%1,%2,%3};\n"
        : "+f"(d[0]), "+f"(d[1]), "+f"(d[2]), "+f"(d[3])
        : "r"(a[0]), "r"(a[1]), "r"(a[2]), "r"(a[3]), "r"(b[0]), "r"(b[1]));
}

__device__ __forceinline__ void cpa16(uint32_t sa, const void* g, bool p) {
    int sz = p ? 16 : 0;
    asm volatile("cp.async.cg.shared.global [%0], [%1], 16, %2;\n"
                 :: "r"(sa), "l"(g), "r"(sz) : "memory");
}
#define CP_COMMIT() asm volatile("cp.async.commit_group;\n" ::: "memory")
#define CP_WAIT1()  asm volatile("cp.async.wait_group 1;\n" ::: "memory")

#define LDSM4(r0, r1, r2, r3, addr)                                            \
    asm volatile("ldmatrix.sync.aligned.m8n8.x4.shared.b16 {%0,%1,%2,%3}, [%4];" \
                 : "=r"(r0), "=r"(r1), "=r"(r2), "=r"(r3) : "r"(addr))

// ---------------- legacy GEMM (cvt path) for input/output GEMMs --------------
template <bool RELU, bool BIAS, bool ROUND>
__global__ void __launch_bounds__(256, 2) k_mma(
    const float* __restrict__ A, const float* __restrict__ B,
    const float* __restrict__ bias, float* __restrict__ C,
    int M, int K, int Nc)
{
    __shared__ uint32_t As[2][GBM][GBK + 4];
    __shared__ uint32_t Bs[2][GBK][GBN + 8];

    int tid  = threadIdx.x;
    int lane = tid & 31;
    int warp = tid >> 5;
    int wr = warp >> 2, wc = warp & 3;
    int lr = lane >> 2, lc = lane & 3;
    int rowBase = blockIdx.y * GBM;
    int colBase = blockIdx.x * GBN;

    int aRow = tid >> 1;
    int aK   = (tid & 1) << 3;
    int bRow = tid >> 4;
    int bCol = (tid & 15) << 3;

    float acc[4][4][4];
#pragma unroll
    for (int m = 0; m < 4; m++)
#pragma unroll
        for (int n = 0; n < 4; n++)
#pragma unroll
            for (int r = 0; r < 4; r++) acc[m][n][r] = 0.f;

    float aReg[8], bReg[8];
    const int NT = K / GBK;

    {
        bool okA = (rowBase + aRow) < M;
        const float* pA = A + (size_t)(rowBase + aRow) * K + aK;
        float4 v0 = okA ? *(const float4*)pA       : make_float4(0,0,0,0);
        float4 v1 = okA ? *(const float4*)(pA + 4) : make_float4(0,0,0,0);
        aReg[0]=v0.x; aReg[1]=v0.y; aReg[2]=v0.z; aReg[3]=v0.w;
        aReg[4]=v1.x; aReg[5]=v1.y; aReg[6]=v1.z; aReg[7]=v1.w;
        bool okB = (colBase + bCol) < Nc;
        const float* pB = B + (size_t)bRow * Nc + colBase + bCol;
        float4 w0 = okB ? *(const float4*)pB       : make_float4(0,0,0,0);
        float4 w1 = okB ? *(const float4*)(pB + 4) : make_float4(0,0,0,0);
        bReg[0]=w0.x; bReg[1]=w0.y; bReg[2]=w0.z; bReg[3]=w0.w;
        bReg[4]=w1.x; bReg[5]=w1.y; bReg[6]=w1.z; bReg[7]=w1.w;
    }
#pragma unroll
    for (int j = 0; j < 8; j++) As[0][aRow][aK + j]  = f2tf32(aReg[j]);
#pragma unroll
    for (int j = 0; j < 8; j++) Bs[0][bRow][bCol + j] = f2tf32(bReg[j]);
    __syncthreads();

    for (int kt = 0; kt < NT; kt++) {
        int buf = kt & 1;
        if (kt + 1 < NT) {
            bool okA = (rowBase + aRow) < M;
            const float* pA = A + (size_t)(rowBase + aRow) * K + (kt + 1) * GBK + aK;
            float4 v0 = okA ? *(const float4*)pA       : make_float4(0,0,0,0);
            float4 v1 = okA ? *(const float4*)(pA + 4) : make_float4(0,0,0,0);
            aReg[0]=v0.x; aReg[1]=v0.y; aReg[2]=v0.z; aReg[3]=v0.w;
            aReg[4]=v1.x; aReg[5]=v1.y; aReg[6]=v1.z; aReg[7]=v1.w;
            bool okB = (colBase + bCol) < Nc;
            const float* pB = B + (size_t)((kt + 1) * GBK + bRow) * Nc + colBase + bCol;
            float4 w0 = okB ? *(const float4*)pB       : make_float4(0,0,0,0);
            float4 w1 = okB ? *(const float4*)(pB + 4) : make_float4(0,0,0,0);
            bReg[0]=w0.x; bReg[1]=w0.y; bReg[2]=w0.z; bReg[3]=w0.w;
            bReg[4]=w1.x; bReg[5]=w1.y; bReg[6]=w1.z; bReg[7]=w1.w;
        }
#pragma unroll
        for (int ks = 0; ks < 2; ks++) {
            int kb = ks * 8;
            uint32_t af[4][4], bf[4][2];
#pragma unroll
            for (int mt = 0; mt < 4; mt++) {
                int r = wr * 64 + mt * 16 + lr;
                af[mt][0] = As[buf][r    ][kb + lc];
                af[mt][1] = As[buf][r + 8][kb + lc];
                af[mt][2] = As[buf][r    ][kb + lc + 4];
                af[mt][3] = As[buf][r + 8][kb + lc + 4];
            }
#pragma unroll
            for (int nt = 0; nt < 4; nt++) {
                int c = wc * 32 + nt * 8 + lr;
                bf[nt][0] = Bs[buf][kb + lc    ][c];
                bf[nt][1] = Bs[buf][kb + lc + 4][c];
            }
#pragma unroll
            for (int mt = 0; mt < 4; mt++)
#pragma unroll
                for (int nt = 0; nt < 4; nt++)
                    mma_tf32(acc[mt][nt], af[mt], bf[nt]);
        }
        if (kt + 1 < NT) {
            int nb2 = 1 - buf;
#pragma unroll
            for (int j = 0; j < 8; j++) As[nb2][aRow][aK + j]  = f2tf32(aReg[j]);
#pragma unroll
            for (int j = 0; j < 8; j++) Bs[nb2][bRow][bCol + j] = f2tf32(bReg[j]);
        }
        __syncthreads();
    }

#pragma unroll
    for (int nt = 0; nt < 4; nt++) {
        int col = colBase + wc * 32 + nt * 8 + 2 * lc;
        if (col >= Nc) continue;
        float2 bb = make_float2(0.f, 0.f);
        if (BIAS) bb = *(const float2*)&bias[col];
#pragma unroll
        for (int mt = 0; mt < 4; mt++) {
            int row = rowBase + wr * 64 + mt * 16 + lr;
#pragma unroll
            for (int half = 0; half < 2; half++) {
                int rr = row + half * 8;
                if (rr < M) {
                    float ox = acc[mt][nt][half * 2]     + bb.x;
                    float oy = acc[mt][nt][half * 2 + 1] + bb.y;
                    if (RELU) { ox = fmaxf(ox, 0.f); oy = fmaxf(oy, 0.f); }
                    float2 o;
                    if (ROUND) {
                        o.x = __uint_as_float(f2tf32(ox));
                        o.y = __uint_as_float(f2tf32(oy));
                    } else { o.x = ox; o.y = oy; }
                    *(float2*)&C[(size_t)rr * Nc + col] = o;
                }
            }
        }
    }
}

// ---------------- fused 3-GEMM, cp.async + ldmatrix, GBK=32 -----------------
// seg==1 epilogue also emits attention-scalar partials from resident accs.
#define GBK3 32
#define ST 3
#define TSTR 36
#define TILE_W (128 * TSTR)
#define SMEM3 (2 * ST * TILE_W * 4)

__global__ void __launch_bounds__(256, 2) k_mma3a(
    const float* __restrict__ A,
    const float* __restrict__ Wh, const float* __restrict__ bh,
    const float* __restrict__ Wg,
    const float* __restrict__ Wl, const float* __restrict__ bl,
    const float* __restrict__ attS, const float* __restrict__ attD,
    float* __restrict__ h, float* __restrict__ hg, float* __restrict__ xl)
{
    extern __shared__ float sm[];
    uint32_t sbA = (uint32_t)__cvta_generic_to_shared(sm);
    uint32_t sbB = sbA + ST * TILE_W * 4;

    int tid  = threadIdx.x;
    int lane = tid & 31;
    int warp = tid >> 5;
    int wr = warp >> 2, wc = warp & 3;
    int lr = lane >> 2, lc = lane & 3;
    int rowBase = blockIdx.y * GBM;
    int seg = blockIdx.x >> 1;
    int colBase = (blockIdx.x & 1) * GBN;
    const float* B = (seg == 0) ? Wh : (seg == 1 ? Wg : Wl);

    int row = tid >> 1;
    int kq  = (tid & 1) * 16;
    bool okA = (rowBase + row) < NN;
    const float* gA0 = A + (size_t)(rowBase + row) * DD + kq;
    const float* gB0 = B + (size_t)(colBase + row) * DD + kq;
    uint32_t saBase = ((row * TSTR + kq) * 4);
    int aOff = (wr * 64 + (lane & 7) + ((lane >> 3) & 1) * 8) * TSTR + (lane >> 4) * 4;
    int bOff = (wc * 32 + (lane & 7) + (lane >> 4) * 8) * TSTR + ((lane >> 3) & 1) * 4;

    float acc[4][4][4];
#pragma unroll
    for (int m = 0; m < 4; m++)
#pragma unroll
        for (int n = 0; n < 4; n++)
#pragma unroll
            for (int r = 0; r < 4; r++) acc[m][n][r] = 0.f;

#define ISSUE(kt, s)                                                            \
    do {                                                                        \
        const float* gA = gA0 + (kt) * GBK3;                                    \
        uint32_t sa = sbA + (s) * TILE_W * 4 + saBase;                          \
        cpa16(sa,      gA,      okA);                                           \
        cpa16(sa + 16, gA + 4,  okA);                                           \
        cpa16(sa + 32, gA + 8,  okA);                                           \
        cpa16(sa + 48, gA + 12, okA);                                           \
        const float* gB = gB0 + (kt) * GBK3;                                    \
        uint32_t sb = sbB + (s) * TILE_W * 4 + saBase;                          \
        cpa16(sb,      gB,      true);                                          \
        cpa16(sb + 16, gB + 4,  true);                                          \
        cpa16(sb + 32, gB + 8,  true);                                          \
        cpa16(sb + 48, gB + 12, true);                                          \
        CP_COMMIT();                                                            \
    } while (0)

    ISSUE(0, 0);
    ISSUE(1, 1);

    const int NT = DD / GBK3;   // 8
    for (int kt = 0; kt < NT; kt++) {
        CP_WAIT1();
        __syncthreads();
        if (kt + 2 < NT) {
            int s2 = (kt + 2) % ST;
            ISSUE(kt + 2, s2);
        } else {
            CP_COMMIT();
        }
        int s = kt % ST;
        uint32_t aS = sbA + s * TILE_W * 4 + aOff * 4;
        uint32_t bS = sbB + s * TILE_W * 4 + bOff * 4;
#pragma unroll
        for (int ks = 0; ks < 4; ks++) {
            uint32_t af[4][4], bf[4][2];
#pragma unroll
            for (int mt = 0; mt < 4; mt++)
                LDSM4(af[mt][0], af[mt][1], af[mt][2], af[mt][3],
                      aS + (mt * 16 * TSTR + ks * 8) * 4);
            LDSM4(bf[0][0], bf[0][1], bf[1][0], bf[1][1], bS + (ks * 8) * 4);
            LDSM4(bf[2][0], bf[2][1], bf[3][0], bf[3][1],
                  bS + (16 * TSTR + ks * 8) * 4);
#pragma unroll
            for (int mt = 0; mt < 4; mt++)
#pragma unroll
                for (int nt = 0; nt < 4; nt++)
                    mma_tf32(acc[mt][nt], af[mt], bf[nt]);
        }
    }
#undef ISSUE

    bool relu = (seg == 0);
    bool hasBias = (seg != 1);
    const float* bias = (seg == 0) ? bh : bl;
    float* C = (seg == 0) ? h : (seg == 1 ? hg : xl);
#pragma unroll
    for (int nt = 0; nt < 4; nt++) {
        int col = colBase + wc * 32 + nt * 8 + 2 * lc;
        float2 bb = make_float2(0.f, 0.f);
        if (hasBias) bb = *(const float2*)&bias[col];
#pragma unroll
        for (int mt = 0; mt < 4; mt++) {
            int row2 = rowBase + wr * 64 + mt * 16 + lr;
#pragma unroll
            for (int half = 0; half < 2; half++) {
                int rr = row2 + half * 8;
                if (rr < NN) {
                    float2 o;
                    o.x = acc[mt][nt][half * 2]     + bb.x;
                    o.y = acc[mt][nt][half * 2 + 1] + bb.y;
                    if (relu) { o.x = fmaxf(o.x, 0.f); o.y = fmaxf(o.y, 0.f); }
                    *(float2*)&C[(size_t)rr * DD + col] = o;
                }
            }
        }
    }

    // attention scalar partials from resident hg accumulators (seg==1 only)
    if (seg == 1) {
        float2 asw[4], adw[4];
#pragma unroll
        for (int nt = 0; nt < 4; nt++) {
            int col = colBase + wc * 32 + nt * 8 + 2 * lc;
            asw[nt] = *(const float2*)&attS[col];
            adw[nt] = *(const float2*)&attD[col];
        }
        int hh = (colBase + wc * 32) >> 6;   // head of this 32-col slab
        int slab = wc & 1;                   // slab index within head
#pragma unroll
        for (int mt = 0; mt < 4; mt++) {
#pragma unroll
            for (int half = 0; half < 2; half++) {
                float ps = 0.f, pd = 0.f;
#pragma unroll
                for (int nt = 0; nt < 4; nt++) {
                    float v0 = acc[mt][nt][half * 2];
                    float v1 = acc[mt][nt][half * 2 + 1];
                    ps = fmaf(v0, asw[nt].x, fmaf(v1, asw[nt].y, ps));
                    pd = fmaf(v0, adw[nt].x, fmaf(v1, adw[nt].y, pd));
                }
                ps += __shfl_xor_sync(0xFFFFFFFFu, ps, 1);
                ps += __shfl_xor_sync(0xFFFFFFFFu, ps, 2);
                pd += __shfl_xor_sync(0xFFFFFFFFu, pd, 1);
                pd += __shfl_xor_sync(0xFFFFFFFFu, pd, 2);
                int rr = rowBase + wr * 64 + mt * 16 + lr + half * 8;
                if (lc == 0 && rr < NN) {
                    float2 o = make_float2(ps, pd);
                    *(float2*)&g_attp[((size_t)(rr * 4 + hh) * 2 + slab) * 2] = o;
                }
            }
        }
    }
}

// ---------------- attention partial reduce: a_src/a_dst [N,H] ---------------
__global__ void k_attred() {
    int i = blockIdx.x * blockDim.x + threadIdx.x;   // n*4 + h
    if (i >= NN * HH) return;
    float4 v = *(const float4*)&g_attp[(size_t)i * 4];
    g_asrc[i] = v.x + v.z;
    g_adst[i] = v.y + v.w;
}

// ---------------- GAT + combine fused: warp per node (online softmax) -------
__device__ __forceinline__ float pick4(float4 v, int h) {
    float r = v.x;
    r = (h == 1) ? v.y : r;
    r = (h == 2) ? v.z : r;
    r = (h == 3) ? v.w : r;
    return r;
}

__global__ void __launch_bounds__(256) k_gatc(
    const float* __restrict__ bg, const float* __restrict__ lng,
    const float* __restrict__ lnb, const float* __restrict__ betas, int first)
{
    int w = (blockIdx.x * blockDim.x + threadIdx.x) >> 5;
    int lane = threadIdx.x & 31;
    if (w >= NN) return;
    int n = w;
    int h = lane >> 3;
    int colb = lane * 8;

    int beg = g_rowptr[n], end = g_rowptr[n + 1];
    float4 ad4 = *(const float4*)&g_adst[n * 4];
    float adv = pick4(ad4, h);

    float m = -1e30f, s = 0.f;
    float4 acc0 = make_float4(0,0,0,0), acc1 = make_float4(0,0,0,0);

    for (int e = beg; e < end; e++) {
        int src = g_srcs[e];
        float4 as4 = *(const float4*)&g_asrc[src * 4];
        float ev = pick4(as4, h) + adv;
        ev = ev > 0.f ? ev : NEG_SLOPE * ev;
        float nm = fmaxf(m, ev);
        float sc = __expf(m - nm);
        float wg = __expf(ev - nm);
        m = nm;
        s = fmaf(s, sc, wg);
        const float4* hv = (const float4*)&g_hg[(size_t)src * DD + colb];
        float4 v0 = hv[0], v1 = hv[1];
        acc0.x = fmaf(wg, v0.x, acc0.x * sc);
        acc0.y = fmaf(wg, v0.y, acc0.y * sc);
        acc0.z = fmaf(wg, v0.z, acc0.z * sc);
        acc0.w = fmaf(wg, v0.w, acc0.w * sc);
        acc1.x = fmaf(wg, v1.x, acc1.x * sc);
        acc1.y = fmaf(wg, v1.y, acc1.y * sc);
        acc1.z = fmaf(wg, v1.z, acc1.z * sc);
        acc1.w = fmaf(wg, v1.w, acc1.w * sc);
    }
    float inv = 1.f / s;
    size_t idx = (size_t)n * DD + colb;
    float4 b0 = *(const float4*)&bg[colb];
    float4 b1 = *(const float4*)&bg[colb + 4];
    float4 x0 = *(const float4*)&g_xl[idx];
    float4 x1 = *(const float4*)&g_xl[idx + 4];

    float xn[8];
    xn[0] = fmaxf(fmaf(acc0.x, inv, b0.x + x0.x), 0.f);
    xn[1] = fmaxf(fmaf(acc0.y, inv, b0.y + x0.y), 0.f);
    xn[2] = fmaxf(fmaf(acc0.z, inv, b0.z + x0.z), 0.f);
    xn[3] = fmaxf(fmaf(acc0.w, inv, b0.w + x0.w), 0.f);
    xn[4] = fmaxf(fmaf(acc1.x, inv, b1.x + x1.x), 0.f);
    xn[5] = fmaxf(fmaf(acc1.y, inv, b1.y + x1.y), 0.f);
    xn[6] = fmaxf(fmaf(acc1.z, inv, b1.z + x1.z), 0.f);
    xn[7] = fmaxf(fmaf(acc1.w, inv, b1.w + x1.w), 0.f);

    // ---- fused combine: x = (1-beta)*LN(h*xn) + beta*xn ; xloc += x ----
    float4 h0 = *(const float4*)&g_h[idx];
    float4 h1 = *(const float4*)&g_h[idx + 4];
    float t[8] = {h0.x * xn[0], h0.y * xn[1], h0.z * xn[2], h0.w * xn[3],
                  h1.x * xn[4], h1.y * xn[5], h1.z * xn[6], h1.w * xn[7]};

    float sum = 0.f, sq = 0.f;
#pragma unroll
    for (int i = 0; i < 8; i++) { sum += t[i]; sq += t[i] * t[i]; }
#pragma unroll
    for (int o = 16; o; o >>= 1) {
        sum += __shfl_xor_sync(0xFFFFFFFFu, sum, o);
        sq  += __shfl_xor_sync(0xFFFFFFFFu, sq,  o);
    }
    float mean = sum * (1.f / DD);
    float var = sq * (1.f / DD) - mean * mean;
    float rs = rsqrtf(var + LNEPS);

    float4 lg0 = *(const float4*)&lng[colb];
    float4 lg1 = *(const float4*)&lng[colb + 4];
    float4 lb0 = *(const float4*)&lnb[colb];
    float4 lb1 = *(const float4*)&lnb[colb + 4];
    float4 be0 = *(const float4*)&betas[colb];
    float4 be1 = *(const float4*)&betas[colb + 4];
    float lg[8] = {lg0.x, lg0.y, lg0.z, lg0.w, lg1.x, lg1.y, lg1.z, lg1.w};
    float lb[8] = {lb0.x, lb0.y, lb0.z, lb0.w, lb1.x, lb1.y, lb1.z, lb1.w};
    float bev[8] = {be0.x, be0.y, be0.z, be0.w, be1.x, be1.y, be1.z, be1.w};

    float out[8];
#pragma unroll
    for (int i = 0; i < 8; i++) {
        float ln = (t[i] - mean) * rs * lg[i] + lb[i];
        float be = 1.f / (1.f + __expf(-bev[i]));
        out[i] = (1.f - be) * ln + be * xn[i];
    }

    // g_x rounded to tf32 (next GEMM input); xloc full precision
    float4 r0, r1;
    r0.x = __uint_as_float(f2tf32(out[0]));
    r0.y = __uint_as_float(f2tf32(out[1]));
    r0.z = __uint_as_float(f2tf32(out[2]));
    r0.w = __uint_as_float(f2tf32(out[3]));
    r1.x = __uint_as_float(f2tf32(out[4]));
    r1.y = __uint_as_float(f2tf32(out[5]));
    r1.z = __uint_as_float(f2tf32(out[6]));
    r1.w = __uint_as_float(f2tf32(out[7]));
    *(float4*)&g_x[idx]     = r0;
    *(float4*)&g_x[idx + 4] = r1;

    float4 o0 = make_float4(out[0], out[1], out[2], out[3]);
    float4 o1 = make_float4(out[4], out[5], out[6], out[7]);
    if (first) {
        *(float4*)&g_xloc[idx]     = o0;
        *(float4*)&g_xloc[idx + 4] = o1;
    } else {
        float4 l0 = *(float4*)&g_xloc[idx];
        float4 l1 = *(float4*)&g_xloc[idx + 4];
        l0.x += o0.x; l0.y += o0.y; l0.z += o0.z; l0.w += o0.w;
        l1.x += o1.x; l1.y += o1.y; l1.z += o1.z; l1.w += o1.w;
        *(float4*)&g_xloc[idx]     = l0;
        *(float4*)&g_xloc[idx + 4] = l1;
    }
}

// ---------------- driver -----------------------------------------------------
extern "C" void kernel_launch(void* const* d_in, const int* in_sizes, int n_in,
                              void* d_out, int out_size) {
    const float* x_in   = (const float*)d_in[0];
    const int*   ei     = (const int*)  d_in[1];
    const float* Win    = (const float*)d_in[2];
    const float* b_in   = (const float*)d_in[3];
    const float* Wh     = (const float*)d_in[4];
    const float* bh     = (const float*)d_in[5];
    const float* Wg     = (const float*)d_in[6];
    const float* attS   = (const float*)d_in[7];
    const float* attD   = (const float*)d_in[8];
    const float* bg     = (const float*)d_in[9];
    const float* Wl     = (const float*)d_in[10];
    const float* bl     = (const float*)d_in[11];
    const float* lng    = (const float*)d_in[12];
    const float* lnb    = (const float*)d_in[13];
    const float* betas  = (const float*)d_in[14];
    const float* Wp     = (const float*)d_in[15];
    const float* bp     = (const float*)d_in[16];
    float* out = (float*)d_out;

    cudaFuncSetAttribute(k_mma3a, cudaFuncAttributeMaxDynamicSharedMemorySize, SMEM3);

    float* px;   cudaGetSymbolAddress((void**)&px,   g_x);
    float* ph;   cudaGetSymbolAddress((void**)&ph,   g_h);
    float* phg;  cudaGetSymbolAddress((void**)&phg,  g_hg);
    float* pxl;  cudaGetSymbolAddress((void**)&pxl,  g_xl);
    float* pxlo; cudaGetSymbolAddress((void**)&pxlo, g_xloc);
    float* pwr;  cudaGetSymbolAddress((void**)&pwr,  g_wr);

    const float* rWh = pwr;
    const float* rWg = pwr + 196608;
    const float* rWl = pwr + 393216;

    dim3 gA(DD / GBN, cdiv(NN, GBM));   // (2, 782)
    dim3 gF(6, cdiv(NN, GBM));          // (6, 782)

    // 1: weight pre-round+transpose, 2: input GEMM, 3: init, 4: layer-0 fused GEMM
    k_round<<<cdiv(589824, 256), 256>>>(Wh, Wg, Wl);
    k_mma<false, true, true><<<gA, 256>>>(x_in, Win, b_in, px, NN, DD, DD);
    k_init_cnt<<<cdiv(NN, 256), 256>>>();
    k_mma3a<<<gF, 256, SMEM3>>>(px, rWh, bh, rWg, rWl, bl, attS, attD,
                                ph, phg, pxl);

    // CSR build
    k_hist<<<cdiv(EE, 256), 256>>>(ei);
    int nb = cdiv(NN, 1024);
    k_scan1<<<nb, 1024>>>();
    k_scan2<<<1, 32>>>(nb);
    k_scan3<<<cdiv(NN, 256), 256>>>();
    k_scatter<<<cdiv(EE + NN, 256), 256>>>(ei);

    for (int i = 0; i < 3; i++) {
        if (i > 0) {
            k_mma3a<<<gF, 256, SMEM3>>>(px, rWh + i * 65536, bh + i * DD,
                                        rWg + i * 65536, rWl + i * 65536, bl + i * DD,
                                        attS + i * DD, attD + i * DD,
                                        ph, phg, pxl);
        }
        k_attred<<<cdiv(NN * HH, 256), 256>>>();
        k_gatc<<<cdiv(NN * 32, 256), 256>>>(bg + i * DD, lng + i * DD,
                                            lnb + i * DD, betas + i * DD, i == 0);
    }

    // out = xloc @ Wp + bp
    dim3 gO(1, cdiv(NN, GBM));
    k_mma<false, true, false><<<gO, 256>>>(pxlo, Wp, bp, out, NN, DD, OUTD);
}

// round 12
// speedup vs baseline: 1.0758x; 1.0120x over previous
#include <cuda_runtime.h>
#include <cstdint>

// ----------------------------------------------------------------------------
// Polynormer forward: N=100000, E=1.6M, D=256, H=4, C=64, L=3, OUT=64
// R12: streaming-cache hints — gatc's once-touched arrays (h, xl, x, xloc) use
//      __ldcs/__stcs (evict-first) so the 102MB hg gather target stays L2-
//      resident instead of being thrashed by 400MB of streaming traffic.
// ----------------------------------------------------------------------------

#define NN 100000
#define EE 1600000
#define DD 256
#define HH 4
#define OUTD 64
#define NEG_SLOPE 0.2f
#define LNEPS 1e-5f

// ---------------- scratch (device globals; allocation-free) -----------------
__device__ float g_x   [NN * DD];
__device__ float g_h   [NN * DD];
__device__ float g_hg  [NN * DD];
__device__ float g_xl  [NN * DD];
__device__ float g_xloc[NN * DD];
__device__ float g_wr  [3 * 196608];      // tf32-rounded, TRANSPOSED [n][k] Wh|Wg|Wl
__device__ float g_asrc[NN * HH];
__device__ float g_adst[NN * HH];
__device__ float g_attp[NN * HH * 4];     // per-slab partials: [n][h][slab][src/dst]
__device__ int   g_cnt   [NN];
__device__ int   g_rowptr[NN + 1];
__device__ int   g_cursor[NN];
__device__ int   g_srcs  [EE + NN];
__device__ int   g_bsum[128];
__device__ int   g_boff[128];

static inline int cdiv(int a, int b) { return (a + b - 1) / b; }

__device__ __forceinline__ uint32_t f2tf32(float f) {
    uint32_t u;
    asm("cvt.rna.tf32.f32 %0, %1;" : "=r"(u) : "f"(f));
    return u;
}

// ---------------- CSR build --------------------------------------------------
__global__ void k_init_cnt() {
    int i = blockIdx.x * blockDim.x + threadIdx.x;
    if (i < NN) g_cnt[i] = 1;  // self loop
}

__global__ void k_hist(const int* __restrict__ ei) {
    int i = blockIdx.x * blockDim.x + threadIdx.x;
    if (i < EE) atomicAdd(&g_cnt[ei[EE + i]], 1);
}

__global__ void k_scan1() {
    __shared__ int sh[1024];
    int t = threadIdx.x, b = blockIdx.x;
    int idx = b * 1024 + t;
    int v = (idx < NN) ? g_cnt[idx] : 0;
    sh[t] = v;
    for (int off = 1; off < 1024; off <<= 1) {
        __syncthreads();
        int u = (t >= off) ? sh[t - off] : 0;
        __syncthreads();
        sh[t] += u;
    }
    if (idx < NN) g_rowptr[idx + 1] = sh[t];
    if (t == 1023) g_bsum[b] = sh[t];
}

__global__ void k_scan2(int nb) {
    if (threadIdx.x == 0 && blockIdx.x == 0) {
        int acc = 0;
        for (int i = 0; i < nb; i++) { g_boff[i] = acc; acc += g_bsum[i]; }
    }
}

__global__ void k_scan3() {
    int idx = blockIdx.x * blockDim.x + threadIdx.x;
    if (idx == 0) { g_rowptr[0] = 0; g_cursor[0] = 0; }
    if (idx < NN) {
        int v = g_rowptr[idx + 1] + g_boff[idx >> 10];
        g_rowptr[idx + 1] = v;
        if (idx + 1 < NN) g_cursor[idx + 1] = v;
    }
}

__global__ void k_scatter(const int* __restrict__ ei) {
    int idx = blockIdx.x * blockDim.x + threadIdx.x;
    int src, dst;
    if (idx < EE)            { src = ei[idx]; dst = ei[EE + idx]; }
    else if (idx < EE + NN)  { src = idx - EE; dst = src; }
    else return;
    int pos = atomicAdd(&g_cursor[dst], 1);
    g_srcs[pos] = src;
}

// ---------------- weight pre-round + transpose to [n][k] --------------------
__global__ void k_round(const float* __restrict__ Wh, const float* __restrict__ Wg,
                        const float* __restrict__ Wl) {
    int t = blockIdx.x * blockDim.x + threadIdx.x;    // float index
    if (t >= 589824) return;                           // 9 matrices of 256x256
    int m = t >> 16;                                   // matrix 0..8
    int o = t & 65535;
    int n = o >> 8, k = o & 255;
    const float* src = (m < 3) ? (Wh + m * 65536)
                     : (m < 6) ? (Wg + (m - 3) * 65536)
                               : (Wl + (m - 6) * 65536);
    float v = src[k * 256 + n];
    g_wr[t] = __uint_as_float(f2tf32(v));
}

// ---------------- MMA primitives ---------------------------------------------
#define GBM 128
#define GBN 128
#define GBK 16

__device__ __forceinline__ void mma_tf32(float* d, const uint32_t* a, const uint32_t* b) {
    asm volatile(
        "mma.sync.aligned.m16n8k8.row.col.f32.tf32.tf32.f32 "
        "{%0,%1,%2,%3}, {%4,%5,%6,%7}, {%8,%9}, {%0,%1,%2,%3};\n"
        : "+f"(d[0]), "+f"(d[1]), "+f"(d[2]), "+f"(d[3])
        : "r"(a[0]), "r"(a[1]), "r"(a[2]), "r"(a[3]), "r"(b[0]), "r"(b[1]));
}

__device__ __forceinline__ void cpa16(uint32_t sa, const void* g, bool p) {
    int sz = p ? 16 : 0;
    asm volatile("cp.async.cg.shared.global [%0], [%1], 16, %2;\n"
                 :: "r"(sa), "l"(g), "r"(sz) : "memory");
}
#define CP_COMMIT() asm volatile("cp.async.commit_group;\n" ::: "memory")
#define CP_WAIT1()  asm volatile("cp.async.wait_group 1;\n" ::: "memory")

#define LDSM4(r0, r1, r2, r3, addr)                                            \
    asm volatile("ldmatrix.sync.aligned.m8n8.x4.shared.b16 {%0,%1,%2,%3}, [%4];" \
                 : "=r"(r0), "=r"(r1), "=r"(r2), "=r"(r3) : "r"(addr))

// ---------------- legacy GEMM (cvt path) for input/output GEMMs --------------
template <bool RELU, bool BIAS, bool ROUND>
__global__ void __launch_bounds__(256, 2) k_mma(
    const float* __restrict__ A, const float* __restrict__ B,
    const float* __restrict__ bias, float* __restrict__ C,
    int M, int K, int Nc)
{
    __shared__ uint32_t As[2][GBM][GBK + 4];
    __shared__ uint32_t Bs[2][GBK][GBN + 8];

    int tid  = threadIdx.x;
    int lane = tid & 31;
    int warp = tid >> 5;
    int wr = warp >> 2, wc = warp & 3;
    int lr = lane >> 2, lc = lane & 3;
    int rowBase = blockIdx.y * GBM;
    int colBase = blockIdx.x * GBN;

    int aRow = tid >> 1;
    int aK   = (tid & 1) << 3;
    int bRow = tid >> 4;
    int bCol = (tid & 15) << 3;

    float acc[4][4][4];
#pragma unroll
    for (int m = 0; m < 4; m++)
#pragma unroll
        for (int n = 0; n < 4; n++)
#pragma unroll
            for (int r = 0; r < 4; r++) acc[m][n][r] = 0.f;

    float aReg[8], bReg[8];
    const int NT = K / GBK;

    {
        bool okA = (rowBase + aRow) < M;
        const float* pA = A + (size_t)(rowBase + aRow) * K + aK;
        float4 v0 = okA ? *(const float4*)pA       : make_float4(0,0,0,0);
        float4 v1 = okA ? *(const float4*)(pA + 4) : make_float4(0,0,0,0);
        aReg[0]=v0.x; aReg[1]=v0.y; aReg[2]=v0.z; aReg[3]=v0.w;
        aReg[4]=v1.x; aReg[5]=v1.y; aReg[6]=v1.z; aReg[7]=v1.w;
        bool okB = (colBase + bCol) < Nc;
        const float* pB = B + (size_t)bRow * Nc + colBase + bCol;
        float4 w0 = okB ? *(const float4*)pB       : make_float4(0,0,0,0);
        float4 w1 = okB ? *(const float4*)(pB + 4) : make_float4(0,0,0,0);
        bReg[0]=w0.x; bReg[1]=w0.y; bReg[2]=w0.z; bReg[3]=w0.w;
        bReg[4]=w1.x; bReg[5]=w1.y; bReg[6]=w1.z; bReg[7]=w1.w;
    }
#pragma unroll
    for (int j = 0; j < 8; j++) As[0][aRow][aK + j]  = f2tf32(aReg[j]);
#pragma unroll
    for (int j = 0; j < 8; j++) Bs[0][bRow][bCol + j] = f2tf32(bReg[j]);
    __syncthreads();

    for (int kt = 0; kt < NT; kt++) {
        int buf = kt & 1;
        if (kt + 1 < NT) {
            bool okA = (rowBase + aRow) < M;
            const float* pA = A + (size_t)(rowBase + aRow) * K + (kt + 1) * GBK + aK;
            float4 v0 = okA ? *(const float4*)pA       : make_float4(0,0,0,0);
            float4 v1 = okA ? *(const float4*)(pA + 4) : make_float4(0,0,0,0);
            aReg[0]=v0.x; aReg[1]=v0.y; aReg[2]=v0.z; aReg[3]=v0.w;
            aReg[4]=v1.x; aReg[5]=v1.y; aReg[6]=v1.z; aReg[7]=v1.w;
            bool okB = (colBase + bCol) < Nc;
            const float* pB = B + (size_t)((kt + 1) * GBK + bRow) * Nc + colBase + bCol;
            float4 w0 = okB ? *(const float4*)pB       : make_float4(0,0,0,0);
            float4 w1 = okB ? *(const float4*)(pB + 4) : make_float4(0,0,0,0);
            bReg[0]=w0.x; bReg[1]=w0.y; bReg[2]=w0.z; bReg[3]=w0.w;
            bReg[4]=w1.x; bReg[5]=w1.y; bReg[6]=w1.z; bReg[7]=w1.w;
        }
#pragma unroll
        for (int ks = 0; ks < 2; ks++) {
            int kb = ks * 8;
            uint32_t af[4][4], bf[4][2];
#pragma unroll
            for (int mt = 0; mt < 4; mt++) {
                int r = wr * 64 + mt * 16 + lr;
                af[mt][0] = As[buf][r    ][kb + lc];
                af[mt][1] = As[buf][r + 8][kb + lc];
                af[mt][2] = As[buf][r    ][kb + lc + 4];
                af[mt][3] = As[buf][r + 8][kb + lc + 4];
            }
#pragma unroll
            for (int nt = 0; nt < 4; nt++) {
                int c = wc * 32 + nt * 8 + lr;
                bf[nt][0] = Bs[buf][kb + lc    ][c];
                bf[nt][1] = Bs[buf][kb + lc + 4][c];
            }
#pragma unroll
            for (int mt = 0; mt < 4; mt++)
#pragma unroll
                for (int nt = 0; nt < 4; nt++)
                    mma_tf32(acc[mt][nt], af[mt], bf[nt]);
        }
        if (kt + 1 < NT) {
            int nb2 = 1 - buf;
#pragma unroll
            for (int j = 0; j < 8; j++) As[nb2][aRow][aK + j]  = f2tf32(aReg[j]);
#pragma unroll
            for (int j = 0; j < 8; j++) Bs[nb2][bRow][bCol + j] = f2tf32(bReg[j]);
        }
        __syncthreads();
    }

#pragma unroll
    for (int nt = 0; nt < 4; nt++) {
        int col = colBase + wc * 32 + nt * 8 + 2 * lc;
        if (col >= Nc) continue;
        float2 bb = make_float2(0.f, 0.f);
        if (BIAS) bb = *(const float2*)&bias[col];
#pragma unroll
        for (int mt = 0; mt < 4; mt++) {
            int row = rowBase + wr * 64 + mt * 16 + lr;
#pragma unroll
            for (int half = 0; half < 2; half++) {
                int rr = row + half * 8;
                if (rr < M) {
                    float ox = acc[mt][nt][half * 2]     + bb.x;
                    float oy = acc[mt][nt][half * 2 + 1] + bb.y;
                    if (RELU) { ox = fmaxf(ox, 0.f); oy = fmaxf(oy, 0.f); }
                    float2 o;
                    if (ROUND) {
                        o.x = __uint_as_float(f2tf32(ox));
                        o.y = __uint_as_float(f2tf32(oy));
                    } else { o.x = ox; o.y = oy; }
                    *(float2*)&C[(size_t)rr * Nc + col] = o;
                }
            }
        }
    }
}

// ---------------- fused 3-GEMM, cp.async + ldmatrix, GBK=32 -----------------
// seg==1 epilogue also emits attention-scalar partials from resident accs.
#define GBK3 32
#define ST 3
#define TSTR 36
#define TILE_W (128 * TSTR)
#define SMEM3 (2 * ST * TILE_W * 4)

__global__ void __launch_bounds__(256, 2) k_mma3a(
    const float* __restrict__ A,
    const float* __restrict__ Wh, const float* __restrict__ bh,
    const float* __restrict__ Wg,
    const float* __restrict__ Wl, const float* __restrict__ bl,
    const float* __restrict__ attS, const float* __restrict__ attD,
    float* __restrict__ h, float* __restrict__ hg, float* __restrict__ xl)
{
    extern __shared__ float sm[];
    uint32_t sbA = (uint32_t)__cvta_generic_to_shared(sm);
    uint32_t sbB = sbA + ST * TILE_W * 4;

    int tid  = threadIdx.x;
    int lane = tid & 31;
    int warp = tid >> 5;
    int wr = warp >> 2, wc = warp & 3;
    int lr = lane >> 2, lc = lane & 3;
    int rowBase = blockIdx.y * GBM;
    int seg = blockIdx.x >> 1;
    int colBase = (blockIdx.x & 1) * GBN;
    const float* B = (seg == 0) ? Wh : (seg == 1 ? Wg : Wl);

    int row = tid >> 1;
    int kq  = (tid & 1) * 16;
    bool okA = (rowBase + row) < NN;
    const float* gA0 = A + (size_t)(rowBase + row) * DD + kq;
    const float* gB0 = B + (size_t)(colBase + row) * DD + kq;
    uint32_t saBase = ((row * TSTR + kq) * 4);
    int aOff = (wr * 64 + (lane & 7) + ((lane >> 3) & 1) * 8) * TSTR + (lane >> 4) * 4;
    int bOff = (wc * 32 + (lane & 7) + (lane >> 4) * 8) * TSTR + ((lane >> 3) & 1) * 4;

    float acc[4][4][4];
#pragma unroll
    for (int m = 0; m < 4; m++)
#pragma unroll
        for (int n = 0; n < 4; n++)
#pragma unroll
            for (int r = 0; r < 4; r++) acc[m][n][r] = 0.f;

#define ISSUE(kt, s)                                                            \
    do {                                                                        \
        const float* gA = gA0 + (kt) * GBK3;                                    \
        uint32_t sa = sbA + (s) * TILE_W * 4 + saBase;                          \
        cpa16(sa,      gA,      okA);                                           \
        cpa16(sa + 16, gA + 4,  okA);                                           \
        cpa16(sa + 32, gA + 8,  okA);                                           \
        cpa16(sa + 48, gA + 12, okA);                                           \
        const float* gB = gB0 + (kt) * GBK3;                                    \
        uint32_t sb = sbB + (s) * TILE_W * 4 + saBase;                          \
        cpa16(sb,      gB,      true);                                          \
        cpa16(sb + 16, gB + 4,  true);                                          \
        cpa16(sb + 32, gB + 8,  true);                                          \
        cpa16(sb + 48, gB + 12, true);                                          \
        CP_COMMIT();                                                            \
    } while (0)

    ISSUE(0, 0);
    ISSUE(1, 1);

    const int NT = DD / GBK3;   // 8
    for (int kt = 0; kt < NT; kt++) {
        CP_WAIT1();
        __syncthreads();
        if (kt + 2 < NT) {
            int s2 = (kt + 2) % ST;
            ISSUE(kt + 2, s2);
        } else {
            CP_COMMIT();
        }
        int s = kt % ST;
        uint32_t aS = sbA + s * TILE_W * 4 + aOff * 4;
        uint32_t bS = sbB + s * TILE_W * 4 + bOff * 4;
#pragma unroll
        for (int ks = 0; ks < 4; ks++) {
            uint32_t af[4][4], bf[4][2];
#pragma unroll
            for (int mt = 0; mt < 4; mt++)
                LDSM4(af[mt][0], af[mt][1], af[mt][2], af[mt][3],
                      aS + (mt * 16 * TSTR + ks * 8) * 4);
            LDSM4(bf[0][0], bf[0][1], bf[1][0], bf[1][1], bS + (ks * 8) * 4);
            LDSM4(bf[2][0], bf[2][1], bf[3][0], bf[3][1],
                  bS + (16 * TSTR + ks * 8) * 4);
#pragma unroll
            for (int mt = 0; mt < 4; mt++)
#pragma unroll
                for (int nt = 0; nt < 4; nt++)
                    mma_tf32(acc[mt][nt], af[mt], bf[nt]);
        }
    }
#undef ISSUE

    bool relu = (seg == 0);
    bool hasBias = (seg != 1);
    const float* bias = (seg == 0) ? bh : bl;
    float* C = (seg == 0) ? h : (seg == 1 ? hg : xl);
#pragma unroll
    for (int nt = 0; nt < 4; nt++) {
        int col = colBase + wc * 32 + nt * 8 + 2 * lc;
        float2 bb = make_float2(0.f, 0.f);
        if (hasBias) bb = *(const float2*)&bias[col];
#pragma unroll
        for (int mt = 0; mt < 4; mt++) {
            int row2 = rowBase + wr * 64 + mt * 16 + lr;
#pragma unroll
            for (int half = 0; half < 2; half++) {
                int rr = row2 + half * 8;
                if (rr < NN) {
                    float2 o;
                    o.x = acc[mt][nt][half * 2]     + bb.x;
                    o.y = acc[mt][nt][half * 2 + 1] + bb.y;
                    if (relu) { o.x = fmaxf(o.x, 0.f); o.y = fmaxf(o.y, 0.f); }
                    float2* dst = (float2*)&C[(size_t)rr * DD + col];
                    if (seg == 1) *dst = o;          // hg: keep L2-resident
                    else __stcs(dst, o);             // h/xl: evict-first
                }
            }
        }
    }

    // attention scalar partials from resident hg accumulators (seg==1 only)
    if (seg == 1) {
        float2 asw[4], adw[4];
#pragma unroll
        for (int nt = 0; nt < 4; nt++) {
            int col = colBase + wc * 32 + nt * 8 + 2 * lc;
            asw[nt] = *(const float2*)&attS[col];
            adw[nt] = *(const float2*)&attD[col];
        }
        int hh = (colBase + wc * 32) >> 6;   // head of this 32-col slab
        int slab = wc & 1;                   // slab index within head
#pragma unroll
        for (int mt = 0; mt < 4; mt++) {
#pragma unroll
            for (int half = 0; half < 2; half++) {
                float ps = 0.f, pd = 0.f;
#pragma unroll
                for (int nt = 0; nt < 4; nt++) {
                    float v0 = acc[mt][nt][half * 2];
                    float v1 = acc[mt][nt][half * 2 + 1];
                    ps = fmaf(v0, asw[nt].x, fmaf(v1, asw[nt].y, ps));
                    pd = fmaf(v0, adw[nt].x, fmaf(v1, adw[nt].y, pd));
                }
                ps += __shfl_xor_sync(0xFFFFFFFFu, ps, 1);
                ps += __shfl_xor_sync(0xFFFFFFFFu, ps, 2);
                pd += __shfl_xor_sync(0xFFFFFFFFu, pd, 1);
                pd += __shfl_xor_sync(0xFFFFFFFFu, pd, 2);
                int rr = rowBase + wr * 64 + mt * 16 + lr + half * 8;
                if (lc == 0 && rr < NN) {
                    float2 o = make_float2(ps, pd);
                    *(float2*)&g_attp[((size_t)(rr * 4 + hh) * 2 + slab) * 2] = o;
                }
            }
        }
    }
}

// ---------------- attention partial reduce: a_src/a_dst [N,H] ---------------
__global__ void k_attred() {
    int i = blockIdx.x * blockDim.x + threadIdx.x;   // n*4 + h
    if (i >= NN * HH) return;
    float4 v = *(const float4*)&g_attp[(size_t)i * 4];
    g_asrc[i] = v.x + v.z;
    g_adst[i] = v.y + v.w;
}

// ---------------- GAT + combine fused: warp per node (online softmax) -------
__device__ __forceinline__ float pick4(float4 v, int h) {
    float r = v.x;
    r = (h == 1) ? v.y : r;
    r = (h == 2) ? v.z : r;
    r = (h == 3) ? v.w : r;
    return r;
}

__global__ void __launch_bounds__(256) k_gatc(
    const float* __restrict__ bg, const float* __restrict__ lng,
    const float* __restrict__ lnb, const float* __restrict__ betas, int first)
{
    int w = (blockIdx.x * blockDim.x + threadIdx.x) >> 5;
    int lane = threadIdx.x & 31;
    if (w >= NN) return;
    int n = w;
    int h = lane >> 3;
    int colb = lane * 8;

    int beg = g_rowptr[n], end = g_rowptr[n + 1];
    float4 ad4 = *(const float4*)&g_adst[n * 4];
    float adv = pick4(ad4, h);

    float m = -1e30f, s = 0.f;
    float4 acc0 = make_float4(0,0,0,0), acc1 = make_float4(0,0,0,0);

    for (int e = beg; e < end; e++) {
        int src = g_srcs[e];
        float4 as4 = *(const float4*)&g_asrc[src * 4];
        float ev = pick4(as4, h) + adv;
        ev = ev > 0.f ? ev : NEG_SLOPE * ev;
        float nm = fmaxf(m, ev);
        float sc = __expf(m - nm);
        float wg = __expf(ev - nm);
        m = nm;
        s = fmaf(s, sc, wg);
        const float4* hv = (const float4*)&g_hg[(size_t)src * DD + colb];
        float4 v0 = hv[0], v1 = hv[1];
        acc0.x = fmaf(wg, v0.x, acc0.x * sc);
        acc0.y = fmaf(wg, v0.y, acc0.y * sc);
        acc0.z = fmaf(wg, v0.z, acc0.z * sc);
        acc0.w = fmaf(wg, v0.w, acc0.w * sc);
        acc1.x = fmaf(wg, v1.x, acc1.x * sc);
        acc1.y = fmaf(wg, v1.y, acc1.y * sc);
        acc1.z = fmaf(wg, v1.z, acc1.z * sc);
        acc1.w = fmaf(wg, v1.w, acc1.w * sc);
    }
    float inv = 1.f / s;
    size_t idx = (size_t)n * DD + colb;
    float4 b0 = *(const float4*)&bg[colb];
    float4 b1 = *(const float4*)&bg[colb + 4];
    float4 x0 = __ldcs((const float4*)&g_xl[idx]);
    float4 x1 = __ldcs((const float4*)&g_xl[idx + 4]);

    float xn[8];
    xn[0] = fmaxf(fmaf(acc0.x, inv, b0.x + x0.x), 0.f);
    xn[1] = fmaxf(fmaf(acc0.y, inv, b0.y + x0.y), 0.f);
    xn[2] = fmaxf(fmaf(acc0.z, inv, b0.z + x0.z), 0.f);
    xn[3] = fmaxf(fmaf(acc0.w, inv, b0.w + x0.w), 0.f);
    xn[4] = fmaxf(fmaf(acc1.x, inv, b1.x + x1.x), 0.f);
    xn[5] = fmaxf(fmaf(acc1.y, inv, b1.y + x1.y), 0.f);
    xn[6] = fmaxf(fmaf(acc1.z, inv, b1.z + x1.z), 0.f);
    xn[7] = fmaxf(fmaf(acc1.w, inv, b1.w + x1.w), 0.f);

    // ---- fused combine: x = (1-beta)*LN(h*xn) + beta*xn ; xloc += x ----
    float4 h0 = __ldcs((const float4*)&g_h[idx]);
    float4 h1 = __ldcs((const float4*)&g_h[idx + 4]);
    float t[8] = {h0.x * xn[0], h0.y * xn[1], h0.z * xn[2], h0.w * xn[3],
                  h1.x * xn[4], h1.y * xn[5], h1.z * xn[6], h1.w * xn[7]};

    float sum = 0.f, sq = 0.f;
#pragma unroll
    for (int i = 0; i < 8; i++) { sum += t[i]; sq += t[i] * t[i]; }
#pragma unroll
    for (int o = 16; o; o >>= 1) {
        sum += __shfl_xor_sync(0xFFFFFFFFu, sum, o);
        sq  += __shfl_xor_sync(0xFFFFFFFFu, sq,  o);
    }
    float mean = sum * (1.f / DD);
    float var = sq * (1.f / DD) - mean * mean;
    float rs = rsqrtf(var + LNEPS);

    float4 lg0 = *(const float4*)&lng[colb];
    float4 lg1 = *(const float4*)&lng[colb + 4];
    float4 lb0 = *(const float4*)&lnb[colb];
    float4 lb1 = *(const float4*)&lnb[colb + 4];
    float4 be0 = *(const float4*)&betas[colb];
    float4 be1 = *(const float4*)&betas[colb + 4];
    float lg[8] = {lg0.x, lg0.y, lg0.z, lg0.w, lg1.x, lg1.y, lg1.z, lg1.w};
    float lb[8] = {lb0.x, lb0.y, lb0.z, lb0.w, lb1.x, lb1.y, lb1.z, lb1.w};
    float bev[8] = {be0.x, be0.y, be0.z, be0.w, be1.x, be1.y, be1.z, be1.w};

    float out[8];
#pragma unroll
    for (int i = 0; i < 8; i++) {
        float ln = (t[i] - mean) * rs * lg[i] + lb[i];
        float be = 1.f / (1.f + __expf(-bev[i]));
        out[i] = (1.f - be) * ln + be * xn[i];
    }

    // g_x rounded to tf32 (next GEMM input); xloc full precision
    float4 r0, r1;
    r0.x = __uint_as_float(f2tf32(out[0]));
    r0.y = __uint_as_float(f2tf32(out[1]));
    r0.z = __uint_as_float(f2tf32(out[2]));
    r0.w = __uint_as_float(f2tf32(out[3]));
    r1.x = __uint_as_float(f2tf32(out[4]));
    r1.y = __uint_as_float(f2tf32(out[5]));
    r1.z = __uint_as_float(f2tf32(out[6]));
    r1.w = __uint_as_float(f2tf32(out[7]));
    __stcs((float4*)&g_x[idx],     r0);
    __stcs((float4*)&g_x[idx + 4], r1);

    float4 o0 = make_float4(out[0], out[1], out[2], out[3]);
    float4 o1 = make_float4(out[4], out[5], out[6], out[7]);
    if (first) {
        __stcs((float4*)&g_xloc[idx],     o0);
        __stcs((float4*)&g_xloc[idx + 4], o1);
    } else {
        float4 l0 = __ldcs((const float4*)&g_xloc[idx]);
        float4 l1 = __ldcs((const float4*)&g_xloc[idx + 4]);
        l0.x += o0.x; l0.y += o0.y; l0.z += o0.z; l0.w += o0.w;
        l1.x += o1.x; l1.y += o1.y; l1.z += o1.z; l1.w += o1.w;
        __stcs((float4*)&g_xloc[idx],     l0);
        __stcs((float4*)&g_xloc[idx + 4], l1);
    }
}

// ---------------- driver -----------------------------------------------------
extern "C" void kernel_launch(void* const* d_in, const int* in_sizes, int n_in,
                              void* d_out, int out_size) {
    const float* x_in   = (const float*)d_in[0];
    const int*   ei     = (const int*)  d_in[1];
    const float* Win    = (const float*)d_in[2];
    const float* b_in   = (const float*)d_in[3];
    const float* Wh     = (const float*)d_in[4];
    const float* bh     = (const float*)d_in[5];
    const float* Wg     = (const float*)d_in[6];
    const float* attS   = (const float*)d_in[7];
    const float* attD   = (const float*)d_in[8];
    const float* bg     = (const float*)d_in[9];
    const float* Wl     = (const float*)d_in[10];
    const float* bl     = (const float*)d_in[11];
    const float* lng    = (const float*)d_in[12];
    const float* lnb    = (const float*)d_in[13];
    const float* betas  = (const float*)d_in[14];
    const float* Wp     = (const float*)d_in[15];
    const float* bp     = (const float*)d_in[16];
    float* out = (float*)d_out;

    cudaFuncSetAttribute(k_mma3a, cudaFuncAttributeMaxDynamicSharedMemorySize, SMEM3);

    float* px;   cudaGetSymbolAddress((void**)&px,   g_x);
    float* ph;   cudaGetSymbolAddress((void**)&ph,   g_h);
    float* phg;  cudaGetSymbolAddress((void**)&phg,  g_hg);
    float* pxl;  cudaGetSymbolAddress((void**)&pxl,  g_xl);
    float* pxlo; cudaGetSymbolAddress((void**)&pxlo, g_xloc);
    float* pwr;  cudaGetSymbolAddress((void**)&pwr,  g_wr);

    const float* rWh = pwr;
    const float* rWg = pwr + 196608;
    const float* rWl = pwr + 393216;

    dim3 gA(DD / GBN, cdiv(NN, GBM));   // (2, 782)
    dim3 gF(6, cdiv(NN, GBM));          // (6, 782)

    // 1: weight pre-round+transpose, 2: input GEMM, 3: init, 4: layer-0 fused GEMM
    k_round<<<cdiv(589824, 256), 256>>>(Wh, Wg, Wl);
    k_mma<false, true, true><<<gA, 256>>>(x_in, Win, b_in, px, NN, DD, DD);
    k_init_cnt<<<cdiv(NN, 256), 256>>>();
    k_mma3a<<<gF, 256, SMEM3>>>(px, rWh, bh, rWg, rWl, bl, attS, attD,
                                ph, phg, pxl);

    // CSR build
    k_hist<<<cdiv(EE, 256), 256>>>(ei);
    int nb = cdiv(NN, 1024);
    k_scan1<<<nb, 1024>>>();
    k_scan2<<<1, 32>>>(nb);
    k_scan3<<<cdiv(NN, 256), 256>>>();
    k_scatter<<<cdiv(EE + NN, 256), 256>>>(ei);

    for (int i = 0; i < 3; i++) {
        if (i > 0) {
            k_mma3a<<<gF, 256, SMEM3>>>(px, rWh + i * 65536, bh + i * DD,
                                        rWg + i * 65536, rWl + i * 65536, bl + i * DD,
                                        attS + i * DD, attD + i * DD,
                                        ph, phg, pxl);
        }
        k_attred<<<cdiv(NN * HH, 256), 256>>>();
        k_gatc<<<cdiv(NN * 32, 256), 256>>>(bg + i * DD, lng + i * DD,
                                            lnb + i * DD, betas + i * DD, i == 0);
    }

    // out = xloc @ Wp + bp
    dim3 gO(1, cdiv(NN, GBM));
    k_mma<false, true, false><<<gO, 256>>>(pxlo, Wp, bp, out, NN, DD, OUTD);
}

// round 13
// speedup vs baseline: 1.0868x; 1.0102x over previous
#include <cuda_runtime.h>
#include <cstdint>

// ----------------------------------------------------------------------------
// Polynormer forward: N=100000, E=1.6M, D=256, H=4, C=64, L=3, OUT=64
// R13: CSR build forked onto a side stream (hides ~110us behind the input +
//      layer-0 GEMMs via capture-legal event fork/join); dedicated 128x64-tile
//      output GEMM (stops computing 64 zero columns).
// ----------------------------------------------------------------------------

#define NN 100000
#define EE 1600000
#define DD 256
#define HH 4
#define OUTD 64
#define NEG_SLOPE 0.2f
#define LNEPS 1e-5f

// ---------------- scratch (device globals; allocation-free) -----------------
__device__ float g_x   [NN * DD];
__device__ float g_h   [NN * DD];
__device__ float g_hg  [NN * DD];
__device__ float g_xl  [NN * DD];
__device__ float g_xloc[NN * DD];
__device__ float g_wr  [3 * 196608];      // tf32-rounded, TRANSPOSED [n][k] Wh|Wg|Wl
__device__ float g_asrc[NN * HH];
__device__ float g_adst[NN * HH];
__device__ float g_attp[NN * HH * 4];     // per-slab partials: [n][h][slab][src/dst]
__device__ int   g_cnt   [NN];
__device__ int   g_rowptr[NN + 1];
__device__ int   g_cursor[NN];
__device__ int   g_srcs  [EE + NN];
__device__ int   g_bsum[128];
__device__ int   g_boff[128];

static inline int cdiv(int a, int b) { return (a + b - 1) / b; }

__device__ __forceinline__ uint32_t f2tf32(float f) {
    uint32_t u;
    asm("cvt.rna.tf32.f32 %0, %1;" : "=r"(u) : "f"(f));
    return u;
}

// ---------------- CSR build --------------------------------------------------
__global__ void k_init_cnt() {
    int i = blockIdx.x * blockDim.x + threadIdx.x;
    if (i < NN) g_cnt[i] = 1;  // self loop
}

__global__ void k_hist(const int* __restrict__ ei) {
    int i = blockIdx.x * blockDim.x + threadIdx.x;
    if (i < EE) atomicAdd(&g_cnt[ei[EE + i]], 1);
}

__global__ void k_scan1() {
    __shared__ int sh[1024];
    int t = threadIdx.x, b = blockIdx.x;
    int idx = b * 1024 + t;
    int v = (idx < NN) ? g_cnt[idx] : 0;
    sh[t] = v;
    for (int off = 1; off < 1024; off <<= 1) {
        __syncthreads();
        int u = (t >= off) ? sh[t - off] : 0;
        __syncthreads();
        sh[t] += u;
    }
    if (idx < NN) g_rowptr[idx + 1] = sh[t];
    if (t == 1023) g_bsum[b] = sh[t];
}

__global__ void k_scan2(int nb) {
    if (threadIdx.x == 0 && blockIdx.x == 0) {
        int acc = 0;
        for (int i = 0; i < nb; i++) { g_boff[i] = acc; acc += g_bsum[i]; }
    }
}

__global__ void k_scan3() {
    int idx = blockIdx.x * blockDim.x + threadIdx.x;
    if (idx == 0) { g_rowptr[0] = 0; g_cursor[0] = 0; }
    if (idx < NN) {
        int v = g_rowptr[idx + 1] + g_boff[idx >> 10];
        g_rowptr[idx + 1] = v;
        if (idx + 1 < NN) g_cursor[idx + 1] = v;
    }
}

__global__ void k_scatter(const int* __restrict__ ei) {
    int idx = blockIdx.x * blockDim.x + threadIdx.x;
    int src, dst;
    if (idx < EE)            { src = ei[idx]; dst = ei[EE + idx]; }
    else if (idx < EE + NN)  { src = idx - EE; dst = src; }
    else return;
    int pos = atomicAdd(&g_cursor[dst], 1);
    g_srcs[pos] = src;
}

// ---------------- weight pre-round + transpose to [n][k] --------------------
__global__ void k_round(const float* __restrict__ Wh, const float* __restrict__ Wg,
                        const float* __restrict__ Wl) {
    int t = blockIdx.x * blockDim.x + threadIdx.x;    // float index
    if (t >= 589824) return;                           // 9 matrices of 256x256
    int m = t >> 16;                                   // matrix 0..8
    int o = t & 65535;
    int n = o >> 8, k = o & 255;
    const float* src = (m < 3) ? (Wh + m * 65536)
                     : (m < 6) ? (Wg + (m - 3) * 65536)
                               : (Wl + (m - 6) * 65536);
    float v = src[k * 256 + n];
    g_wr[t] = __uint_as_float(f2tf32(v));
}

// ---------------- MMA primitives ---------------------------------------------
#define GBM 128
#define GBN 128
#define GBK 16

__device__ __forceinline__ void mma_tf32(float* d, const uint32_t* a, const uint32_t* b) {
    asm volatile(
        "mma.sync.aligned.m16n8k8.row.col.f32.tf32.tf32.f32 "
        "{%0,%1,%2,%3}, {%4,%5,%6,%7}, {%8,%9}, {%0,%1,%2,%3};\n"
        : "+f"(d[0]), "+f"(d[1]), "+f"(d[2]), "+f"(d[3])
        : "r"(a[0]), "r"(a[1]), "r"(a[2]), "r"(a[3]), "r"(b[0]), "r"(b[1]));
}

__device__ __forceinline__ void cpa16(uint32_t sa, const void* g, bool p) {
    int sz = p ? 16 : 0;
    asm volatile("cp.async.cg.shared.global [%0], [%1], 16, %2;\n"
                 :: "r"(sa), "l"(g), "r"(sz) : "memory");
}
#define CP_COMMIT() asm volatile("cp.async.commit_group;\n" ::: "memory")
#define CP_WAIT1()  asm volatile("cp.async.wait_group 1;\n" ::: "memory")

#define LDSM4(r0, r1, r2, r3, addr)                                            \
    asm volatile("ldmatrix.sync.aligned.m8n8.x4.shared.b16 {%0,%1,%2,%3}, [%4];" \
                 : "=r"(r0), "=r"(r1), "=r"(r2), "=r"(r3) : "r"(addr))

// ---------------- legacy GEMM (cvt path) for the input GEMM ------------------
template <bool RELU, bool BIAS, bool ROUND>
__global__ void __launch_bounds__(256, 2) k_mma(
    const float* __restrict__ A, const float* __restrict__ B,
    const float* __restrict__ bias, float* __restrict__ C,
    int M, int K, int Nc)
{
    __shared__ uint32_t As[2][GBM][GBK + 4];
    __shared__ uint32_t Bs[2][GBK][GBN + 8];

    int tid  = threadIdx.x;
    int lane = tid & 31;
    int warp = tid >> 5;
    int wr = warp >> 2, wc = warp & 3;
    int lr = lane >> 2, lc = lane & 3;
    int rowBase = blockIdx.y * GBM;
    int colBase = blockIdx.x * GBN;

    int aRow = tid >> 1;
    int aK   = (tid & 1) << 3;
    int bRow = tid >> 4;
    int bCol = (tid & 15) << 3;

    float acc[4][4][4];
#pragma unroll
    for (int m = 0; m < 4; m++)
#pragma unroll
        for (int n = 0; n < 4; n++)
#pragma unroll
            for (int r = 0; r < 4; r++) acc[m][n][r] = 0.f;

    float aReg[8], bReg[8];
    const int NT = K / GBK;

    {
        bool okA = (rowBase + aRow) < M;
        const float* pA = A + (size_t)(rowBase + aRow) * K + aK;
        float4 v0 = okA ? *(const float4*)pA       : make_float4(0,0,0,0);
        float4 v1 = okA ? *(const float4*)(pA + 4) : make_float4(0,0,0,0);
        aReg[0]=v0.x; aReg[1]=v0.y; aReg[2]=v0.z; aReg[3]=v0.w;
        aReg[4]=v1.x; aReg[5]=v1.y; aReg[6]=v1.z; aReg[7]=v1.w;
        bool okB = (colBase + bCol) < Nc;
        const float* pB = B + (size_t)bRow * Nc + colBase + bCol;
        float4 w0 = okB ? *(const float4*)pB       : make_float4(0,0,0,0);
        float4 w1 = okB ? *(const float4*)(pB + 4) : make_float4(0,0,0,0);
        bReg[0]=w0.x; bReg[1]=w0.y; bReg[2]=w0.z; bReg[3]=w0.w;
        bReg[4]=w1.x; bReg[5]=w1.y; bReg[6]=w1.z; bReg[7]=w1.w;
    }
#pragma unroll
    for (int j = 0; j < 8; j++) As[0][aRow][aK + j]  = f2tf32(aReg[j]);
#pragma unroll
    for (int j = 0; j < 8; j++) Bs[0][bRow][bCol + j] = f2tf32(bReg[j]);
    __syncthreads();

    for (int kt = 0; kt < NT; kt++) {
        int buf = kt & 1;
        if (kt + 1 < NT) {
            bool okA = (rowBase + aRow) < M;
            const float* pA = A + (size_t)(rowBase + aRow) * K + (kt + 1) * GBK + aK;
            float4 v0 = okA ? *(const float4*)pA       : make_float4(0,0,0,0);
            float4 v1 = okA ? *(const float4*)(pA + 4) : make_float4(0,0,0,0);
            aReg[0]=v0.x; aReg[1]=v0.y; aReg[2]=v0.z; aReg[3]=v0.w;
            aReg[4]=v1.x; aReg[5]=v1.y; aReg[6]=v1.z; aReg[7]=v1.w;
            bool okB = (colBase + bCol) < Nc;
            const float* pB = B + (size_t)((kt + 1) * GBK + bRow) * Nc + colBase + bCol;
            float4 w0 = okB ? *(const float4*)pB       : make_float4(0,0,0,0);
            float4 w1 = okB ? *(const float4*)(pB + 4) : make_float4(0,0,0,0);
            bReg[0]=w0.x; bReg[1]=w0.y; bReg[2]=w0.z; bReg[3]=w0.w;
            bReg[4]=w1.x; bReg[5]=w1.y; bReg[6]=w1.z; bReg[7]=w1.w;
        }
#pragma unroll
        for (int ks = 0; ks < 2; ks++) {
            int kb = ks * 8;
            uint32_t af[4][4], bf[4][2];
#pragma unroll
            for (int mt = 0; mt < 4; mt++) {
                int r = wr * 64 + mt * 16 + lr;
                af[mt][0] = As[buf][r    ][kb + lc];
                af[mt][1] = As[buf][r + 8][kb + lc];
                af[mt][2] = As[buf][r    ][kb + lc + 4];
                af[mt][3] = As[buf][r + 8][kb + lc + 4];
            }
#pragma unroll
            for (int nt = 0; nt < 4; nt++) {
                int c = wc * 32 + nt * 8 + lr;
                bf[nt][0] = Bs[buf][kb + lc    ][c];
                bf[nt][1] = Bs[buf][kb + lc + 4][c];
            }
#pragma unroll
            for (int mt = 0; mt < 4; mt++)
#pragma unroll
                for (int nt = 0; nt < 4; nt++)
                    mma_tf32(acc[mt][nt], af[mt], bf[nt]);
        }
        if (kt + 1 < NT) {
            int nb2 = 1 - buf;
#pragma unroll
            for (int j = 0; j < 8; j++) As[nb2][aRow][aK + j]  = f2tf32(aReg[j]);
#pragma unroll
            for (int j = 0; j < 8; j++) Bs[nb2][bRow][bCol + j] = f2tf32(bReg[j]);
        }
        __syncthreads();
    }

#pragma unroll
    for (int nt = 0; nt < 4; nt++) {
        int col = colBase + wc * 32 + nt * 8 + 2 * lc;
        if (col >= Nc) continue;
        float2 bb = make_float2(0.f, 0.f);
        if (BIAS) bb = *(const float2*)&bias[col];
#pragma unroll
        for (int mt = 0; mt < 4; mt++) {
            int row = rowBase + wr * 64 + mt * 16 + lr;
#pragma unroll
            for (int half = 0; half < 2; half++) {
                int rr = row + half * 8;
                if (rr < M) {
                    float ox = acc[mt][nt][half * 2]     + bb.x;
                    float oy = acc[mt][nt][half * 2 + 1] + bb.y;
                    if (RELU) { ox = fmaxf(ox, 0.f); oy = fmaxf(oy, 0.f); }
                    float2 o;
                    if (ROUND) {
                        o.x = __uint_as_float(f2tf32(ox));
                        o.y = __uint_as_float(f2tf32(oy));
                    } else { o.x = ox; o.y = oy; }
                    *(float2*)&C[(size_t)rr * Nc + col] = o;
                }
            }
        }
    }
}

// ---------------- output GEMM: 128x64 tile (Nc=64, no wasted columns) --------
__global__ void __launch_bounds__(256, 2) k_mmaO(
    const float* __restrict__ A, const float* __restrict__ B,
    const float* __restrict__ bias, float* __restrict__ C)   // M=NN,K=256,Nc=64
{
    __shared__ uint32_t As[2][128][GBK + 4];
    __shared__ uint32_t Bs[2][GBK][64 + 8];

    int tid  = threadIdx.x;
    int lane = tid & 31;
    int warp = tid >> 5;
    int wr = warp >> 1, wc = warp & 1;     // 4x2 warp grid: 32-row x 32-col
    int lr = lane >> 2, lc = lane & 3;
    int rowBase = blockIdx.x * 128;

    int aRow = tid >> 1;
    int aK   = (tid & 1) << 3;
    int bRow = tid >> 4;                   // 0..15
    int bCol = (tid & 15) << 2;            // 0..60

    float acc[2][4][4];
#pragma unroll
    for (int m = 0; m < 2; m++)
#pragma unroll
        for (int n = 0; n < 4; n++)
#pragma unroll
            for (int r = 0; r < 4; r++) acc[m][n][r] = 0.f;

    float aReg[8], bReg[4];
    const int NT = DD / GBK;   // 16

    {
        bool okA = (rowBase + aRow) < NN;
        const float* pA = A + (size_t)(rowBase + aRow) * DD + aK;
        float4 v0 = okA ? *(const float4*)pA       : make_float4(0,0,0,0);
        float4 v1 = okA ? *(const float4*)(pA + 4) : make_float4(0,0,0,0);
        aReg[0]=v0.x; aReg[1]=v0.y; aReg[2]=v0.z; aReg[3]=v0.w;
        aReg[4]=v1.x; aReg[5]=v1.y; aReg[6]=v1.z; aReg[7]=v1.w;
        float4 w = *(const float4*)&B[(size_t)bRow * OUTD + bCol];
        bReg[0]=w.x; bReg[1]=w.y; bReg[2]=w.z; bReg[3]=w.w;
    }
#pragma unroll
    for (int j = 0; j < 8; j++) As[0][aRow][aK + j]  = f2tf32(aReg[j]);
#pragma unroll
    for (int j = 0; j < 4; j++) Bs[0][bRow][bCol + j] = f2tf32(bReg[j]);
    __syncthreads();

    for (int kt = 0; kt < NT; kt++) {
        int buf = kt & 1;
        if (kt + 1 < NT) {
            bool okA = (rowBase + aRow) < NN;
            const float* pA = A + (size_t)(rowBase + aRow) * DD + (kt + 1) * GBK + aK;
            float4 v0 = okA ? *(const float4*)pA       : make_float4(0,0,0,0);
            float4 v1 = okA ? *(const float4*)(pA + 4) : make_float4(0,0,0,0);
            aReg[0]=v0.x; aReg[1]=v0.y; aReg[2]=v0.z; aReg[3]=v0.w;
            aReg[4]=v1.x; aReg[5]=v1.y; aReg[6]=v1.z; aReg[7]=v1.w;
            float4 w = *(const float4*)&B[(size_t)((kt + 1) * GBK + bRow) * OUTD + bCol];
            bReg[0]=w.x; bReg[1]=w.y; bReg[2]=w.z; bReg[3]=w.w;
        }
#pragma unroll
        for (int ks = 0; ks < 2; ks++) {
            int kb = ks * 8;
            uint32_t af[2][4], bf[4][2];
#pragma unroll
            for (int mt = 0; mt < 2; mt++) {
                int r = wr * 32 + mt * 16 + lr;
                af[mt][0] = As[buf][r    ][kb + lc];
                af[mt][1] = As[buf][r + 8][kb + lc];
                af[mt][2] = As[buf][r    ][kb + lc + 4];
                af[mt][3] = As[buf][r + 8][kb + lc + 4];
            }
#pragma unroll
            for (int nt = 0; nt < 4; nt++) {
                int c = wc * 32 + nt * 8 + lr;
                bf[nt][0] = Bs[buf][kb + lc    ][c];
                bf[nt][1] = Bs[buf][kb + lc + 4][c];
            }
#pragma unroll
            for (int mt = 0; mt < 2; mt++)
#pragma unroll
                for (int nt = 0; nt < 4; nt++)
                    mma_tf32(acc[mt][nt], af[mt], bf[nt]);
        }
        if (kt + 1 < NT) {
            int nb2 = 1 - buf;
#pragma unroll
            for (int j = 0; j < 8; j++) As[nb2][aRow][aK + j]  = f2tf32(aReg[j]);
#pragma unroll
            for (int j = 0; j < 4; j++) Bs[nb2][bRow][bCol + j] = f2tf32(bReg[j]);
        }
        __syncthreads();
    }

#pragma unroll
    for (int nt = 0; nt < 4; nt++) {
        int col = wc * 32 + nt * 8 + 2 * lc;
        float2 bb = *(const float2*)&bias[col];
#pragma unroll
        for (int mt = 0; mt < 2; mt++) {
            int row = rowBase + wr * 32 + mt * 16 + lr;
#pragma unroll
            for (int half = 0; half < 2; half++) {
                int rr = row + half * 8;
                if (rr < NN) {
                    float2 o;
                    o.x = acc[mt][nt][half * 2]     + bb.x;
                    o.y = acc[mt][nt][half * 2 + 1] + bb.y;
                    *(float2*)&C[(size_t)rr * OUTD + col] = o;
                }
            }
        }
    }
}

// ---------------- fused 3-GEMM, cp.async + ldmatrix, GBK=32 -----------------
#define GBK3 32
#define ST 3
#define TSTR 36
#define TILE_W (128 * TSTR)
#define SMEM3 (2 * ST * TILE_W * 4)

__global__ void __launch_bounds__(256, 2) k_mma3a(
    const float* __restrict__ A,
    const float* __restrict__ Wh, const float* __restrict__ bh,
    const float* __restrict__ Wg,
    const float* __restrict__ Wl, const float* __restrict__ bl,
    const float* __restrict__ attS, const float* __restrict__ attD,
    float* __restrict__ h, float* __restrict__ hg, float* __restrict__ xl)
{
    extern __shared__ float sm[];
    uint32_t sbA = (uint32_t)__cvta_generic_to_shared(sm);
    uint32_t sbB = sbA + ST * TILE_W * 4;

    int tid  = threadIdx.x;
    int lane = tid & 31;
    int warp = tid >> 5;
    int wr = warp >> 2, wc = warp & 3;
    int lr = lane >> 2, lc = lane & 3;
    int rowBase = blockIdx.y * GBM;
    int seg = blockIdx.x >> 1;
    int colBase = (blockIdx.x & 1) * GBN;
    const float* B = (seg == 0) ? Wh : (seg == 1 ? Wg : Wl);

    int row = tid >> 1;
    int kq  = (tid & 1) * 16;
    bool okA = (rowBase + row) < NN;
    const float* gA0 = A + (size_t)(rowBase + row) * DD + kq;
    const float* gB0 = B + (size_t)(colBase + row) * DD + kq;
    uint32_t saBase = ((row * TSTR + kq) * 4);
    int aOff = (wr * 64 + (lane & 7) + ((lane >> 3) & 1) * 8) * TSTR + (lane >> 4) * 4;
    int bOff = (wc * 32 + (lane & 7) + (lane >> 4) * 8) * TSTR + ((lane >> 3) & 1) * 4;

    float acc[4][4][4];
#pragma unroll
    for (int m = 0; m < 4; m++)
#pragma unroll
        for (int n = 0; n < 4; n++)
#pragma unroll
            for (int r = 0; r < 4; r++) acc[m][n][r] = 0.f;

#define ISSUE(kt, s)                                                            \
    do {                                                                        \
        const float* gA = gA0 + (kt) * GBK3;                                    \
        uint32_t sa = sbA + (s) * TILE_W * 4 + saBase;                          \
        cpa16(sa,      gA,      okA);                                           \
        cpa16(sa + 16, gA + 4,  okA);                                           \
        cpa16(sa + 32, gA + 8,  okA);                                           \
        cpa16(sa + 48, gA + 12, okA);                                           \
        const float* gB = gB0 + (kt) * GBK3;                                    \
        uint32_t sb = sbB + (s) * TILE_W * 4 + saBase;                          \
        cpa16(sb,      gB,      true);                                          \
        cpa16(sb + 16, gB + 4,  true);                                          \
        cpa16(sb + 32, gB + 8,  true);                                          \
        cpa16(sb + 48, gB + 12, true);                                          \
        CP_COMMIT();                                                            \
    } while (0)

    ISSUE(0, 0);
    ISSUE(1, 1);

    const int NT = DD / GBK3;   // 8
    for (int kt = 0; kt < NT; kt++) {
        CP_WAIT1();
        __syncthreads();
        if (kt + 2 < NT) {
            int s2 = (kt + 2) % ST;
            ISSUE(kt + 2, s2);
        } else {
            CP_COMMIT();
        }
        int s = kt % ST;
        uint32_t aS = sbA + s * TILE_W * 4 + aOff * 4;
        uint32_t bS = sbB + s * TILE_W * 4 + bOff * 4;
#pragma unroll
        for (int ks = 0; ks < 4; ks++) {
            uint32_t af[4][4], bf[4][2];
#pragma unroll
            for (int mt = 0; mt < 4; mt++)
                LDSM4(af[mt][0], af[mt][1], af[mt][2], af[mt][3],
                      aS + (mt * 16 * TSTR + ks * 8) * 4);
            LDSM4(bf[0][0], bf[0][1], bf[1][0], bf[1][1], bS + (ks * 8) * 4);
            LDSM4(bf[2][0], bf[2][1], bf[3][0], bf[3][1],
                  bS + (16 * TSTR + ks * 8) * 4);
#pragma unroll
            for (int mt = 0; mt < 4; mt++)
#pragma unroll
                for (int nt = 0; nt < 4; nt++)
                    mma_tf32(acc[mt][nt], af[mt], bf[nt]);
        }
    }
#undef ISSUE

    bool relu = (seg == 0);
    bool hasBias = (seg != 1);
    const float* bias = (seg == 0) ? bh : bl;
    float* C = (seg == 0) ? h : (seg == 1 ? hg : xl);
#pragma unroll
    for (int nt = 0; nt < 4; nt++) {
        int col = colBase + wc * 32 + nt * 8 + 2 * lc;
        float2 bb = make_float2(0.f, 0.f);
        if (hasBias) bb = *(const float2*)&bias[col];
#pragma unroll
        for (int mt = 0; mt < 4; mt++) {
            int row2 = rowBase + wr * 64 + mt * 16 + lr;
#pragma unroll
            for (int half = 0; half < 2; half++) {
                int rr = row2 + half * 8;
                if (rr < NN) {
                    float2 o;
                    o.x = acc[mt][nt][half * 2]     + bb.x;
                    o.y = acc[mt][nt][half * 2 + 1] + bb.y;
                    if (relu) { o.x = fmaxf(o.x, 0.f); o.y = fmaxf(o.y, 0.f); }
                    float2* dst = (float2*)&C[(size_t)rr * DD + col];
                    if (seg == 1) *dst = o;          // hg: keep L2-resident
                    else __stcs(dst, o);             // h/xl: evict-first
                }
            }
        }
    }

    // attention scalar partials from resident hg accumulators (seg==1 only)
    if (seg == 1) {
        float2 asw[4], adw[4];
#pragma unroll
        for (int nt = 0; nt < 4; nt++) {
            int col = colBase + wc * 32 + nt * 8 + 2 * lc;
            asw[nt] = *(const float2*)&attS[col];
            adw[nt] = *(const float2*)&attD[col];
        }
        int hh = (colBase + wc * 32) >> 6;   // head of this 32-col slab
        int slab = wc & 1;                   // slab index within head
#pragma unroll
        for (int mt = 0; mt < 4; mt++) {
#pragma unroll
            for (int half = 0; half < 2; half++) {
                float ps = 0.f, pd = 0.f;
#pragma unroll
                for (int nt = 0; nt < 4; nt++) {
                    float v0 = acc[mt][nt][half * 2];
                    float v1 = acc[mt][nt][half * 2 + 1];
                    ps = fmaf(v0, asw[nt].x, fmaf(v1, asw[nt].y, ps));
                    pd = fmaf(v0, adw[nt].x, fmaf(v1, adw[nt].y, pd));
                }
                ps += __shfl_xor_sync(0xFFFFFFFFu, ps, 1);
                ps += __shfl_xor_sync(0xFFFFFFFFu, ps, 2);
                pd += __shfl_xor_sync(0xFFFFFFFFu, pd, 1);
                pd += __shfl_xor_sync(0xFFFFFFFFu, pd, 2);
                int rr = rowBase + wr * 64 + mt * 16 + lr + half * 8;
                if (lc == 0 && rr < NN) {
                    float2 o = make_float2(ps, pd);
                    *(float2*)&g_attp[((size_t)(rr * 4 + hh) * 2 + slab) * 2] = o;
                }
            }
        }
    }
}

// ---------------- attention partial reduce: a_src/a_dst [N,H] ---------------
__global__ void k_attred() {
    int i = blockIdx.x * blockDim.x + threadIdx.x;   // n*4 + h
    if (i >= NN * HH) return;
    float4 v = *(const float4*)&g_attp[(size_t)i * 4];
    g_asrc[i] = v.x + v.z;
    g_adst[i] = v.y + v.w;
}

// ---------------- GAT + combine fused: warp per node (online softmax) -------
__device__ __forceinline__ float pick4(float4 v, int h) {
    float r = v.x;
    r = (h == 1) ? v.y : r;
    r = (h == 2) ? v.z : r;
    r = (h == 3) ? v.w : r;
    return r;
}

__global__ void __launch_bounds__(256) k_gatc(
    const float* __restrict__ bg, const float* __restrict__ lng,
    const float* __restrict__ lnb, const float* __restrict__ betas, int first)
{
    int w = (blockIdx.x * blockDim.x + threadIdx.x) >> 5;
    int lane = threadIdx.x & 31;
    if (w >= NN) return;
    int n = w;
    int h = lane >> 3;
    int colb = lane * 8;

    int beg = g_rowptr[n], end = g_rowptr[n + 1];
    float4 ad4 = *(const float4*)&g_adst[n * 4];
    float adv = pick4(ad4, h);

    float m = -1e30f, s = 0.f;
    float4 acc0 = make_float4(0,0,0,0), acc1 = make_float4(0,0,0,0);

    for (int e = beg; e < end; e++) {
        int src = g_srcs[e];
        float4 as4 = *(const float4*)&g_asrc[src * 4];
        float ev = pick4(as4, h) + adv;
        ev = ev > 0.f ? ev : NEG_SLOPE * ev;
        float nm = fmaxf(m, ev);
        float sc = __expf(m - nm);
        float wg = __expf(ev - nm);
        m = nm;
        s = fmaf(s, sc, wg);
        const float4* hv = (const float4*)&g_hg[(size_t)src * DD + colb];
        float4 v0 = hv[0], v1 = hv[1];
        acc0.x = fmaf(wg, v0.x, acc0.x * sc);
        acc0.y = fmaf(wg, v0.y, acc0.y * sc);
        acc0.z = fmaf(wg, v0.z, acc0.z * sc);
        acc0.w = fmaf(wg, v0.w, acc0.w * sc);
        acc1.x = fmaf(wg, v1.x, acc1.x * sc);
        acc1.y = fmaf(wg, v1.y, acc1.y * sc);
        acc1.z = fmaf(wg, v1.z, acc1.z * sc);
        acc1.w = fmaf(wg, v1.w, acc1.w * sc);
    }
    float inv = 1.f / s;
    size_t idx = (size_t)n * DD + colb;
    float4 b0 = *(const float4*)&bg[colb];
    float4 b1 = *(const float4*)&bg[colb + 4];
    float4 x0 = __ldcs((const float4*)&g_xl[idx]);
    float4 x1 = __ldcs((const float4*)&g_xl[idx + 4]);

    float xn[8];
    xn[0] = fmaxf(fmaf(acc0.x, inv, b0.x + x0.x), 0.f);
    xn[1] = fmaxf(fmaf(acc0.y, inv, b0.y + x0.y), 0.f);
    xn[2] = fmaxf(fmaf(acc0.z, inv, b0.z + x0.z), 0.f);
    xn[3] = fmaxf(fmaf(acc0.w, inv, b0.w + x0.w), 0.f);
    xn[4] = fmaxf(fmaf(acc1.x, inv, b1.x + x1.x), 0.f);
    xn[5] = fmaxf(fmaf(acc1.y, inv, b1.y + x1.y), 0.f);
    xn[6] = fmaxf(fmaf(acc1.z, inv, b1.z + x1.z), 0.f);
    xn[7] = fmaxf(fmaf(acc1.w, inv, b1.w + x1.w), 0.f);

    // ---- fused combine: x = (1-beta)*LN(h*xn) + beta*xn ; xloc += x ----
    float4 h0 = __ldcs((const float4*)&g_h[idx]);
    float4 h1 = __ldcs((const float4*)&g_h[idx + 4]);
    float t[8] = {h0.x * xn[0], h0.y * xn[1], h0.z * xn[2], h0.w * xn[3],
                  h1.x * xn[4], h1.y * xn[5], h1.z * xn[6], h1.w * xn[7]};

    float sum = 0.f, sq = 0.f;
#pragma unroll
    for (int i = 0; i < 8; i++) { sum += t[i]; sq += t[i] * t[i]; }
#pragma unroll
    for (int o = 16; o; o >>= 1) {
        sum += __shfl_xor_sync(0xFFFFFFFFu, sum, o);
        sq  += __shfl_xor_sync(0xFFFFFFFFu, sq,  o);
    }
    float mean = sum * (1.f / DD);
    float var = sq * (1.f / DD) - mean * mean;
    float rs = rsqrtf(var + LNEPS);

    float4 lg0 = *(const float4*)&lng[colb];
    float4 lg1 = *(const float4*)&lng[colb + 4];
    float4 lb0 = *(const float4*)&lnb[colb];
    float4 lb1 = *(const float4*)&lnb[colb + 4];
    float4 be0 = *(const float4*)&betas[colb];
    float4 be1 = *(const float4*)&betas[colb + 4];
    float lg[8] = {lg0.x, lg0.y, lg0.z, lg0.w, lg1.x, lg1.y, lg1.z, lg1.w};
    float lb[8] = {lb0.x, lb0.y, lb0.z, lb0.w, lb1.x, lb1.y, lb1.z, lb1.w};
    float bev[8] = {be0.x, be0.y, be0.z, be0.w, be1.x, be1.y, be1.z, be1.w};

    float out[8];
#pragma unroll
    for (int i = 0; i < 8; i++) {
        float ln = (t[i] - mean) * rs * lg[i] + lb[i];
        float be = 1.f / (1.f + __expf(-bev[i]));
        out[i] = (1.f - be) * ln + be * xn[i];
    }

    // g_x rounded to tf32 (next GEMM input); xloc full precision
    float4 r0, r1;
    r0.x = __uint_as_float(f2tf32(out[0]));
    r0.y = __uint_as_float(f2tf32(out[1]));
    r0.z = __uint_as_float(f2tf32(out[2]));
    r0.w = __uint_as_float(f2tf32(out[3]));
    r1.x = __uint_as_float(f2tf32(out[4]));
    r1.y = __uint_as_float(f2tf32(out[5]));
    r1.z = __uint_as_float(f2tf32(out[6]));
    r1.w = __uint_as_float(f2tf32(out[7]));
    __stcs((float4*)&g_x[idx],     r0);
    __stcs((float4*)&g_x[idx + 4], r1);

    float4 o0 = make_float4(out[0], out[1], out[2], out[3]);
    float4 o1 = make_float4(out[4], out[5], out[6], out[7]);
    if (first) {
        __stcs((float4*)&g_xloc[idx],     o0);
        __stcs((float4*)&g_xloc[idx + 4], o1);
    } else {
        float4 l0 = __ldcs((const float4*)&g_xloc[idx]);
        float4 l1 = __ldcs((const float4*)&g_xloc[idx + 4]);
        l0.x += o0.x; l0.y += o0.y; l0.z += o0.z; l0.w += o0.w;
        l1.x += o1.x; l1.y += o1.y; l1.z += o1.z; l1.w += o1.w;
        __stcs((float4*)&g_xloc[idx],     l0);
        __stcs((float4*)&g_xloc[idx + 4], l1);
    }
}

// ---------------- driver -----------------------------------------------------
extern "C" void kernel_launch(void* const* d_in, const int* in_sizes, int n_in,
                              void* d_out, int out_size) {
    const float* x_in   = (const float*)d_in[0];
    const int*   ei     = (const int*)  d_in[1];
    const float* Win    = (const float*)d_in[2];
    const float* b_in   = (const float*)d_in[3];
    const float* Wh     = (const float*)d_in[4];
    const float* bh     = (const float*)d_in[5];
    const float* Wg     = (const float*)d_in[6];
    const float* attS   = (const float*)d_in[7];
    const float* attD   = (const float*)d_in[8];
    const float* bg     = (const float*)d_in[9];
    const float* Wl     = (const float*)d_in[10];
    const float* bl     = (const float*)d_in[11];
    const float* lng    = (const float*)d_in[12];
    const float* lnb    = (const float*)d_in[13];
    const float* betas  = (const float*)d_in[14];
    const float* Wp     = (const float*)d_in[15];
    const float* bp     = (const float*)d_in[16];
    float* out = (float*)d_out;

    cudaFuncSetAttribute(k_mma3a, cudaFuncAttributeMaxDynamicSharedMemorySize, SMEM3);

    // side stream + fork/join events (created once; no device memory involved)
    static cudaStream_t s2 = nullptr;
    static cudaEvent_t evFork = nullptr, evJoin = nullptr;
    if (s2 == nullptr) {
        cudaStreamCreateWithFlags(&s2, cudaStreamNonBlocking);
        cudaEventCreateWithFlags(&evFork, cudaEventDisableTiming);
        cudaEventCreateWithFlags(&evJoin, cudaEventDisableTiming);
    }

    float* px;   cudaGetSymbolAddress((void**)&px,   g_x);
    float* ph;   cudaGetSymbolAddress((void**)&ph,   g_h);
    float* phg;  cudaGetSymbolAddress((void**)&phg,  g_hg);
    float* pxl;  cudaGetSymbolAddress((void**)&pxl,  g_xl);
    float* pxlo; cudaGetSymbolAddress((void**)&pxlo, g_xloc);
    float* pwr;  cudaGetSymbolAddress((void**)&pwr,  g_wr);

    const float* rWh = pwr;
    const float* rWg = pwr + 196608;
    const float* rWl = pwr + 393216;

    dim3 gA(DD / GBN, cdiv(NN, GBM));   // (2, 782)
    dim3 gF(6, cdiv(NN, GBM));          // (6, 782)

    // fork: CSR chain (depends only on ei) runs on s2 under the GEMMs
    cudaEventRecord(evFork, 0);
    cudaStreamWaitEvent(s2, evFork, 0);

    // main: weight pre-round, input GEMM  |  s2: init_cnt  | main: layer-0 GEMM
    k_round<<<cdiv(589824, 256), 256>>>(Wh, Wg, Wl);
    k_mma<false, true, true><<<gA, 256>>>(x_in, Win, b_in, px, NN, DD, DD);
    k_init_cnt<<<cdiv(NN, 256), 256, 0, s2>>>();
    k_mma3a<<<gF, 256, SMEM3>>>(px, rWh, bh, rWg, rWl, bl, attS, attD,
                                ph, phg, pxl);

    // rest of CSR on s2
    k_hist<<<cdiv(EE, 256), 256, 0, s2>>>(ei);
    int nb = cdiv(NN, 1024);
    k_scan1<<<nb, 1024, 0, s2>>>();
    k_scan2<<<1, 32, 0, s2>>>(nb);
    k_scan3<<<cdiv(NN, 256), 256, 0, s2>>>();
    k_scatter<<<cdiv(EE + NN, 256), 256, 0, s2>>>(ei);
    cudaEventRecord(evJoin, s2);
    cudaStreamWaitEvent(0, evJoin, 0);   // join before first gatc

    for (int i = 0; i < 3; i++) {
        if (i > 0) {
            k_mma3a<<<gF, 256, SMEM3>>>(px, rWh + i * 65536, bh + i * DD,
                                        rWg + i * 65536, rWl + i * 65536, bl + i * DD,
                                        attS + i * DD, attD + i * DD,
                                        ph, phg, pxl);
        }
        k_attred<<<cdiv(NN * HH, 256), 256>>>();
        k_gatc<<<cdiv(NN * 32, 256), 256>>>(bg + i * DD, lng + i * DD,
                                            lnb + i * DD, betas + i * DD, i == 0);
    }

    // out = xloc @ Wp + bp   (dedicated 128x64-tile kernel)
    k_mmaO<<<cdiv(NN, 128), 256>>>(pxlo, Wp, bp, out);
}

// round 14
// speedup vs baseline: 1.2212x; 1.1237x over previous
#include <cuda_runtime.h>
#include <cuda_fp16.h>
#include <cstdint>

// ----------------------------------------------------------------------------
// Polynormer forward: N=100000, E=1.6M, D=256, H=4, C=64, L=3, OUT=64
// R14: hg stored as fp16 straight from the GEMM epilogue (its only consumer is
//      the gatc softmax-weighted gather; fp16 mantissa == tf32 mantissa).
//      Gather traffic halves (1.74GB->0.87GB) and the 51MB gather set becomes
//      fully L2-resident.
// ----------------------------------------------------------------------------

#define NN 100000
#define EE 1600000
#define DD 256
#define HH 4
#define OUTD 64
#define NEG_SLOPE 0.2f
#define LNEPS 1e-5f

// ---------------- scratch (device globals; allocation-free) -----------------
__device__ float  g_x   [NN * DD];
__device__ float  g_h   [NN * DD];
__device__ __half g_hgh [NN * DD];        // fp16 hg (gather target)
__device__ float  g_xl  [NN * DD];
__device__ float  g_xloc[NN * DD];
__device__ float  g_wr  [3 * 196608];     // tf32-rounded, TRANSPOSED [n][k] Wh|Wg|Wl
__device__ float  g_asrc[NN * HH];
__device__ float  g_adst[NN * HH];
__device__ float  g_attp[NN * HH * 4];    // per-slab partials: [n][h][slab][src/dst]
__device__ int    g_cnt   [NN];
__device__ int    g_rowptr[NN + 1];
__device__ int    g_cursor[NN];
__device__ int    g_srcs  [EE + NN];
__device__ int    g_bsum[128];
__device__ int    g_boff[128];

static inline int cdiv(int a, int b) { return (a + b - 1) / b; }

__device__ __forceinline__ uint32_t f2tf32(float f) {
    uint32_t u;
    asm("cvt.rna.tf32.f32 %0, %1;" : "=r"(u) : "f"(f));
    return u;
}

// ---------------- CSR build --------------------------------------------------
__global__ void k_init_cnt() {
    int i = blockIdx.x * blockDim.x + threadIdx.x;
    if (i < NN) g_cnt[i] = 1;  // self loop
}

__global__ void k_hist(const int* __restrict__ ei) {
    int i = blockIdx.x * blockDim.x + threadIdx.x;
    if (i < EE) atomicAdd(&g_cnt[ei[EE + i]], 1);
}

__global__ void k_scan1() {
    __shared__ int sh[1024];
    int t = threadIdx.x, b = blockIdx.x;
    int idx = b * 1024 + t;
    int v = (idx < NN) ? g_cnt[idx] : 0;
    sh[t] = v;
    for (int off = 1; off < 1024; off <<= 1) {
        __syncthreads();
        int u = (t >= off) ? sh[t - off] : 0;
        __syncthreads();
        sh[t] += u;
    }
    if (idx < NN) g_rowptr[idx + 1] = sh[t];
    if (t == 1023) g_bsum[b] = sh[t];
}

__global__ void k_scan2(int nb) {
    if (threadIdx.x == 0 && blockIdx.x == 0) {
        int acc = 0;
        for (int i = 0; i < nb; i++) { g_boff[i] = acc; acc += g_bsum[i]; }
    }
}

__global__ void k_scan3() {
    int idx = blockIdx.x * blockDim.x + threadIdx.x;
    if (idx == 0) { g_rowptr[0] = 0; g_cursor[0] = 0; }
    if (idx < NN) {
        int v = g_rowptr[idx + 1] + g_boff[idx >> 10];
        g_rowptr[idx + 1] = v;
        if (idx + 1 < NN) g_cursor[idx + 1] = v;
    }
}

__global__ void k_scatter(const int* __restrict__ ei) {
    int idx = blockIdx.x * blockDim.x + threadIdx.x;
    int src, dst;
    if (idx < EE)            { src = ei[idx]; dst = ei[EE + idx]; }
    else if (idx < EE + NN)  { src = idx - EE; dst = src; }
    else return;
    int pos = atomicAdd(&g_cursor[dst], 1);
    g_srcs[pos] = src;
}

// ---------------- weight pre-round + transpose to [n][k] --------------------
__global__ void k_round(const float* __restrict__ Wh, const float* __restrict__ Wg,
                        const float* __restrict__ Wl) {
    int t = blockIdx.x * blockDim.x + threadIdx.x;    // float index
    if (t >= 589824) return;                           // 9 matrices of 256x256
    int m = t >> 16;                                   // matrix 0..8
    int o = t & 65535;
    int n = o >> 8, k = o & 255;
    const float* src = (m < 3) ? (Wh + m * 65536)
                     : (m < 6) ? (Wg + (m - 3) * 65536)
                               : (Wl + (m - 6) * 65536);
    float v = src[k * 256 + n];
    g_wr[t] = __uint_as_float(f2tf32(v));
}

// ---------------- MMA primitives ---------------------------------------------
#define GBM 128
#define GBN 128
#define GBK 16

__device__ __forceinline__ void mma_tf32(float* d, const uint32_t* a, const uint32_t* b) {
    asm volatile(
        "mma.sync.aligned.m16n8k8.row.col.f32.tf32.tf32.f32 "
        "{%0,%1,%2,%3}, {%4,%5,%6,%7}, {%8,%9}, {%0,%1,%2,%3};\n"
        : "+f"(d[0]), "+f"(d[1]), "+f"(d[2]), "+f"(d[3])
        : "r"(a[0]), "r"(a[1]), "r"(a[2]), "r"(a[3]), "r"(b[0]), "r"(b[1]));
}

__device__ __forceinline__ void cpa16(uint32_t sa, const void* g, bool p) {
    int sz = p ? 16 : 0;
    asm volatile("cp.async.cg.shared.global [%0], [%1], 16, %2;\n"
                 :: "r"(sa), "l"(g), "r"(sz) : "memory");
}
#define CP_COMMIT() asm volatile("cp.async.commit_group;\n" ::: "memory")
#define CP_WAIT1()  asm volatile("cp.async.wait_group 1;\n" ::: "memory")

#define LDSM4(r0, r1, r2, r3, addr)                                            \
    asm volatile("ldmatrix.sync.aligned.m8n8.x4.shared.b16 {%0,%1,%2,%3}, [%4];" \
                 : "=r"(r0), "=r"(r1), "=r"(r2), "=r"(r3) : "r"(addr))

// ---------------- legacy GEMM (cvt path) for the input GEMM ------------------
template <bool RELU, bool BIAS, bool ROUND>
__global__ void __launch_bounds__(256, 2) k_mma(
    const float* __restrict__ A, const float* __restrict__ B,
    const float* __restrict__ bias, float* __restrict__ C,
    int M, int K, int Nc)
{
    __shared__ uint32_t As[2][GBM][GBK + 4];
    __shared__ uint32_t Bs[2][GBK][GBN + 8];

    int tid  = threadIdx.x;
    int lane = tid & 31;
    int warp = tid >> 5;
    int wr = warp >> 2, wc = warp & 3;
    int lr = lane >> 2, lc = lane & 3;
    int rowBase = blockIdx.y * GBM;
    int colBase = blockIdx.x * GBN;

    int aRow = tid >> 1;
    int aK   = (tid & 1) << 3;
    int bRow = tid >> 4;
    int bCol = (tid & 15) << 3;

    float acc[4][4][4];
#pragma unroll
    for (int m = 0; m < 4; m++)
#pragma unroll
        for (int n = 0; n < 4; n++)
#pragma unroll
            for (int r = 0; r < 4; r++) acc[m][n][r] = 0.f;

    float aReg[8], bReg[8];
    const int NT = K / GBK;

    {
        bool okA = (rowBase + aRow) < M;
        const float* pA = A + (size_t)(rowBase + aRow) * K + aK;
        float4 v0 = okA ? *(const float4*)pA       : make_float4(0,0,0,0);
        float4 v1 = okA ? *(const float4*)(pA + 4) : make_float4(0,0,0,0);
        aReg[0]=v0.x; aReg[1]=v0.y; aReg[2]=v0.z; aReg[3]=v0.w;
        aReg[4]=v1.x; aReg[5]=v1.y; aReg[6]=v1.z; aReg[7]=v1.w;
        bool okB = (colBase + bCol) < Nc;
        const float* pB = B + (size_t)bRow * Nc + colBase + bCol;
        float4 w0 = okB ? *(const float4*)pB       : make_float4(0,0,0,0);
        float4 w1 = okB ? *(const float4*)(pB + 4) : make_float4(0,0,0,0);
        bReg[0]=w0.x; bReg[1]=w0.y; bReg[2]=w0.z; bReg[3]=w0.w;
        bReg[4]=w1.x; bReg[5]=w1.y; bReg[6]=w1.z; bReg[7]=w1.w;
    }
#pragma unroll
    for (int j = 0; j < 8; j++) As[0][aRow][aK + j]  = f2tf32(aReg[j]);
#pragma unroll
    for (int j = 0; j < 8; j++) Bs[0][bRow][bCol + j] = f2tf32(bReg[j]);
    __syncthreads();

    for (int kt = 0; kt < NT; kt++) {
        int buf = kt & 1;
        if (kt + 1 < NT) {
            bool okA = (rowBase + aRow) < M;
            const float* pA = A + (size_t)(rowBase + aRow) * K + (kt + 1) * GBK + aK;
            float4 v0 = okA ? *(const float4*)pA       : make_float4(0,0,0,0);
            float4 v1 = okA ? *(const float4*)(pA + 4) : make_float4(0,0,0,0);
            aReg[0]=v0.x; aReg[1]=v0.y; aReg[2]=v0.z; aReg[3]=v0.w;
            aReg[4]=v1.x; aReg[5]=v1.y; aReg[6]=v1.z; aReg[7]=v1.w;
            bool okB = (colBase + bCol) < Nc;
            const float* pB = B + (size_t)((kt + 1) * GBK + bRow) * Nc + colBase + bCol;
            float4 w0 = okB ? *(const float4*)pB       : make_float4(0,0,0,0);
            float4 w1 = okB ? *(const float4*)(pB + 4) : make_float4(0,0,0,0);
            bReg[0]=w0.x; bReg[1]=w0.y; bReg[2]=w0.z; bReg[3]=w0.w;
            bReg[4]=w1.x; bReg[5]=w1.y; bReg[6]=w1.z; bReg[7]=w1.w;
        }
#pragma unroll
        for (int ks = 0; ks < 2; ks++) {
            int kb = ks * 8;
            uint32_t af[4][4], bf[4][2];
#pragma unroll
            for (int mt = 0; mt < 4; mt++) {
                int r = wr * 64 + mt * 16 + lr;
                af[mt][0] = As[buf][r    ][kb + lc];
                af[mt][1] = As[buf][r + 8][kb + lc];
                af[mt][2] = As[buf][r    ][kb + lc + 4];
                af[mt][3] = As[buf][r + 8][kb + lc + 4];
            }
#pragma unroll
            for (int nt = 0; nt < 4; nt++) {
                int c = wc * 32 + nt * 8 + lr;
                bf[nt][0] = Bs[buf][kb + lc    ][c];
                bf[nt][1] = Bs[buf][kb + lc + 4][c];
            }
#pragma unroll
            for (int mt = 0; mt < 4; mt++)
#pragma unroll
                for (int nt = 0; nt < 4; nt++)
                    mma_tf32(acc[mt][nt], af[mt], bf[nt]);
        }
        if (kt + 1 < NT) {
            int nb2 = 1 - buf;
#pragma unroll
            for (int j = 0; j < 8; j++) As[nb2][aRow][aK + j]  = f2tf32(aReg[j]);
#pragma unroll
            for (int j = 0; j < 8; j++) Bs[nb2][bRow][bCol + j] = f2tf32(bReg[j]);
        }
        __syncthreads();
    }

#pragma unroll
    for (int nt = 0; nt < 4; nt++) {
        int col = colBase + wc * 32 + nt * 8 + 2 * lc;
        if (col >= Nc) continue;
        float2 bb = make_float2(0.f, 0.f);
        if (BIAS) bb = *(const float2*)&bias[col];
#pragma unroll
        for (int mt = 0; mt < 4; mt++) {
            int row = rowBase + wr * 64 + mt * 16 + lr;
#pragma unroll
            for (int half = 0; half < 2; half++) {
                int rr = row + half * 8;
                if (rr < M) {
                    float ox = acc[mt][nt][half * 2]     + bb.x;
                    float oy = acc[mt][nt][half * 2 + 1] + bb.y;
                    if (RELU) { ox = fmaxf(ox, 0.f); oy = fmaxf(oy, 0.f); }
                    float2 o;
                    if (ROUND) {
                        o.x = __uint_as_float(f2tf32(ox));
                        o.y = __uint_as_float(f2tf32(oy));
                    } else { o.x = ox; o.y = oy; }
                    *(float2*)&C[(size_t)rr * Nc + col] = o;
                }
            }
        }
    }
}

// ---------------- output GEMM: 128x64 tile ------------------------------------
__global__ void __launch_bounds__(256, 2) k_mmaO(
    const float* __restrict__ A, const float* __restrict__ B,
    const float* __restrict__ bias, float* __restrict__ C)   // M=NN,K=256,Nc=64
{
    __shared__ uint32_t As[2][128][GBK + 4];
    __shared__ uint32_t Bs[2][GBK][64 + 8];

    int tid  = threadIdx.x;
    int lane = tid & 31;
    int warp = tid >> 5;
    int wr = warp >> 1, wc = warp & 1;
    int lr = lane >> 2, lc = lane & 3;
    int rowBase = blockIdx.x * 128;

    int aRow = tid >> 1;
    int aK   = (tid & 1) << 3;
    int bRow = tid >> 4;
    int bCol = (tid & 15) << 2;

    float acc[2][4][4];
#pragma unroll
    for (int m = 0; m < 2; m++)
#pragma unroll
        for (int n = 0; n < 4; n++)
#pragma unroll
            for (int r = 0; r < 4; r++) acc[m][n][r] = 0.f;

    float aReg[8], bReg[4];
    const int NT = DD / GBK;   // 16

    {
        bool okA = (rowBase + aRow) < NN;
        const float* pA = A + (size_t)(rowBase + aRow) * DD + aK;
        float4 v0 = okA ? *(const float4*)pA       : make_float4(0,0,0,0);
        float4 v1 = okA ? *(const float4*)(pA + 4) : make_float4(0,0,0,0);
        aReg[0]=v0.x; aReg[1]=v0.y; aReg[2]=v0.z; aReg[3]=v0.w;
        aReg[4]=v1.x; aReg[5]=v1.y; aReg[6]=v1.z; aReg[7]=v1.w;
        float4 w = *(const float4*)&B[(size_t)bRow * OUTD + bCol];
        bReg[0]=w.x; bReg[1]=w.y; bReg[2]=w.z; bReg[3]=w.w;
    }
#pragma unroll
    for (int j = 0; j < 8; j++) As[0][aRow][aK + j]  = f2tf32(aReg[j]);
#pragma unroll
    for (int j = 0; j < 4; j++) Bs[0][bRow][bCol + j] = f2tf32(bReg[j]);
    __syncthreads();

    for (int kt = 0; kt < NT; kt++) {
        int buf = kt & 1;
        if (kt + 1 < NT) {
            bool okA = (rowBase + aRow) < NN;
            const float* pA = A + (size_t)(rowBase + aRow) * DD + (kt + 1) * GBK + aK;
            float4 v0 = okA ? *(const float4*)pA       : make_float4(0,0,0,0);
            float4 v1 = okA ? *(const float4*)(pA + 4) : make_float4(0,0,0,0);
            aReg[0]=v0.x; aReg[1]=v0.y; aReg[2]=v0.z; aReg[3]=v0.w;
            aReg[4]=v1.x; aReg[5]=v1.y; aReg[6]=v1.z; aReg[7]=v1.w;
            float4 w = *(const float4*)&B[(size_t)((kt + 1) * GBK + bRow) * OUTD + bCol];
            bReg[0]=w.x; bReg[1]=w.y; bReg[2]=w.z; bReg[3]=w.w;
        }
#pragma unroll
        for (int ks = 0; ks < 2; ks++) {
            int kb = ks * 8;
            uint32_t af[2][4], bf[4][2];
#pragma unroll
            for (int mt = 0; mt < 2; mt++) {
                int r = wr * 32 + mt * 16 + lr;
                af[mt][0] = As[buf][r    ][kb + lc];
                af[mt][1] = As[buf][r + 8][kb + lc];
                af[mt][2] = As[buf][r    ][kb + lc + 4];
                af[mt][3] = As[buf][r + 8][kb + lc + 4];
            }
#pragma unroll
            for (int nt = 0; nt < 4; nt++) {
                int c = wc * 32 + nt * 8 + lr;
                bf[nt][0] = Bs[buf][kb + lc    ][c];
                bf[nt][1] = Bs[buf][kb + lc + 4][c];
            }
#pragma unroll
            for (int mt = 0; mt < 2; mt++)
#pragma unroll
                for (int nt = 0; nt < 4; nt++)
                    mma_tf32(acc[mt][nt], af[mt], bf[nt]);
        }
        if (kt + 1 < NT) {
            int nb2 = 1 - buf;
#pragma unroll
            for (int j = 0; j < 8; j++) As[nb2][aRow][aK + j]  = f2tf32(aReg[j]);
#pragma unroll
            for (int j = 0; j < 4; j++) Bs[nb2][bRow][bCol + j] = f2tf32(bReg[j]);
        }
        __syncthreads();
    }

#pragma unroll
    for (int nt = 0; nt < 4; nt++) {
        int col = wc * 32 + nt * 8 + 2 * lc;
        float2 bb = *(const float2*)&bias[col];
#pragma unroll
        for (int mt = 0; mt < 2; mt++) {
            int row = rowBase + wr * 32 + mt * 16 + lr;
#pragma unroll
            for (int half = 0; half < 2; half++) {
                int rr = row + half * 8;
                if (rr < NN) {
                    float2 o;
                    o.x = acc[mt][nt][half * 2]     + bb.x;
                    o.y = acc[mt][nt][half * 2 + 1] + bb.y;
                    *(float2*)&C[(size_t)rr * OUTD + col] = o;
                }
            }
        }
    }
}

// ---------------- fused 3-GEMM, cp.async + ldmatrix, GBK=32 -----------------
#define GBK3 32
#define ST 3
#define TSTR 36
#define TILE_W (128 * TSTR)
#define SMEM3 (2 * ST * TILE_W * 4)

__global__ void __launch_bounds__(256, 2) k_mma3a(
    const float* __restrict__ A,
    const float* __restrict__ Wh, const float* __restrict__ bh,
    const float* __restrict__ Wg,
    const float* __restrict__ Wl, const float* __restrict__ bl,
    const float* __restrict__ attS, const float* __restrict__ attD,
    float* __restrict__ h, float* __restrict__ xl)
{
    extern __shared__ float sm[];
    uint32_t sbA = (uint32_t)__cvta_generic_to_shared(sm);
    uint32_t sbB = sbA + ST * TILE_W * 4;

    int tid  = threadIdx.x;
    int lane = tid & 31;
    int warp = tid >> 5;
    int wr = warp >> 2, wc = warp & 3;
    int lr = lane >> 2, lc = lane & 3;
    int rowBase = blockIdx.y * GBM;
    int seg = blockIdx.x >> 1;
    int colBase = (blockIdx.x & 1) * GBN;
    const float* B = (seg == 0) ? Wh : (seg == 1 ? Wg : Wl);

    int row = tid >> 1;
    int kq  = (tid & 1) * 16;
    bool okA = (rowBase + row) < NN;
    const float* gA0 = A + (size_t)(rowBase + row) * DD + kq;
    const float* gB0 = B + (size_t)(colBase + row) * DD + kq;
    uint32_t saBase = ((row * TSTR + kq) * 4);
    int aOff = (wr * 64 + (lane & 7) + ((lane >> 3) & 1) * 8) * TSTR + (lane >> 4) * 4;
    int bOff = (wc * 32 + (lane & 7) + (lane >> 4) * 8) * TSTR + ((lane >> 3) & 1) * 4;

    float acc[4][4][4];
#pragma unroll
    for (int m = 0; m < 4; m++)
#pragma unroll
        for (int n = 0; n < 4; n++)
#pragma unroll
            for (int r = 0; r < 4; r++) acc[m][n][r] = 0.f;

#define ISSUE(kt, s)                                                            \
    do {                                                                        \
        const float* gA = gA0 + (kt) * GBK3;                                    \
        uint32_t sa = sbA + (s) * TILE_W * 4 + saBase;                          \
        cpa16(sa,      gA,      okA);                                           \
        cpa16(sa + 16, gA + 4,  okA);                                           \
        cpa16(sa + 32, gA + 8,  okA);                                           \
        cpa16(sa + 48, gA + 12, okA);                                           \
        const float* gB = gB0 + (kt) * GBK3;                                    \
        uint32_t sb = sbB + (s) * TILE_W * 4 + saBase;                          \
        cpa16(sb,      gB,      true);                                          \
        cpa16(sb + 16, gB + 4,  true);                                          \
        cpa16(sb + 32, gB + 8,  true);                                          \
        cpa16(sb + 48, gB + 12, true);                                          \
        CP_COMMIT();                                                            \
    } while (0)

    ISSUE(0, 0);
    ISSUE(1, 1);

    const int NT = DD / GBK3;   // 8
    for (int kt = 0; kt < NT; kt++) {
        CP_WAIT1();
        __syncthreads();
        if (kt + 2 < NT) {
            int s2 = (kt + 2) % ST;
            ISSUE(kt + 2, s2);
        } else {
            CP_COMMIT();
        }
        int s = kt % ST;
        uint32_t aS = sbA + s * TILE_W * 4 + aOff * 4;
        uint32_t bS = sbB + s * TILE_W * 4 + bOff * 4;
#pragma unroll
        for (int ks = 0; ks < 4; ks++) {
            uint32_t af[4][4], bf[4][2];
#pragma unroll
            for (int mt = 0; mt < 4; mt++)
                LDSM4(af[mt][0], af[mt][1], af[mt][2], af[mt][3],
                      aS + (mt * 16 * TSTR + ks * 8) * 4);
            LDSM4(bf[0][0], bf[0][1], bf[1][0], bf[1][1], bS + (ks * 8) * 4);
            LDSM4(bf[2][0], bf[2][1], bf[3][0], bf[3][1],
                  bS + (16 * TSTR + ks * 8) * 4);
#pragma unroll
            for (int mt = 0; mt < 4; mt++)
#pragma unroll
                for (int nt = 0; nt < 4; nt++)
                    mma_tf32(acc[mt][nt], af[mt], bf[nt]);
        }
    }
#undef ISSUE

    if (seg == 1) {
        // hg: store fp16 (only consumer is gatc's gather); keep L2-resident
#pragma unroll
        for (int nt = 0; nt < 4; nt++) {
            int col = colBase + wc * 32 + nt * 8 + 2 * lc;
#pragma unroll
            for (int mt = 0; mt < 4; mt++) {
                int row2 = rowBase + wr * 64 + mt * 16 + lr;
#pragma unroll
                for (int half = 0; half < 2; half++) {
                    int rr = row2 + half * 8;
                    if (rr < NN) {
                        float2 o;
                        o.x = acc[mt][nt][half * 2];
                        o.y = acc[mt][nt][half * 2 + 1];
                        *(__half2*)&g_hgh[(size_t)rr * DD + col] =
                            __float22half2_rn(o);
                    }
                }
            }
        }
        // attention scalar partials from resident accumulators
        float2 asw[4], adw[4];
#pragma unroll
        for (int nt = 0; nt < 4; nt++) {
            int col = colBase + wc * 32 + nt * 8 + 2 * lc;
            asw[nt] = *(const float2*)&attS[col];
            adw[nt] = *(const float2*)&attD[col];
        }
        int hh = (colBase + wc * 32) >> 6;
        int slab = wc & 1;
#pragma unroll
        for (int mt = 0; mt < 4; mt++) {
#pragma unroll
            for (int half = 0; half < 2; half++) {
                float ps = 0.f, pd = 0.f;
#pragma unroll
                for (int nt = 0; nt < 4; nt++) {
                    float v0 = acc[mt][nt][half * 2];
                    float v1 = acc[mt][nt][half * 2 + 1];
                    ps = fmaf(v0, asw[nt].x, fmaf(v1, asw[nt].y, ps));
                    pd = fmaf(v0, adw[nt].x, fmaf(v1, adw[nt].y, pd));
                }
                ps += __shfl_xor_sync(0xFFFFFFFFu, ps, 1);
                ps += __shfl_xor_sync(0xFFFFFFFFu, ps, 2);
                pd += __shfl_xor_sync(0xFFFFFFFFu, pd, 1);
                pd += __shfl_xor_sync(0xFFFFFFFFu, pd, 2);
                int rr = rowBase + wr * 64 + mt * 16 + lr + half * 8;
                if (lc == 0 && rr < NN) {
                    float2 o = make_float2(ps, pd);
                    *(float2*)&g_attp[((size_t)(rr * 4 + hh) * 2 + slab) * 2] = o;
                }
            }
        }
    } else {
        bool relu = (seg == 0);
        const float* bias = (seg == 0) ? bh : bl;
        float* C = (seg == 0) ? h : xl;
#pragma unroll
        for (int nt = 0; nt < 4; nt++) {
            int col = colBase + wc * 32 + nt * 8 + 2 * lc;
            float2 bb = *(const float2*)&bias[col];
#pragma unroll
            for (int mt = 0; mt < 4; mt++) {
                int row2 = rowBase + wr * 64 + mt * 16 + lr;
#pragma unroll
                for (int half = 0; half < 2; half++) {
                    int rr = row2 + half * 8;
                    if (rr < NN) {
                        float2 o;
                        o.x = acc[mt][nt][half * 2]     + bb.x;
                        o.y = acc[mt][nt][half * 2 + 1] + bb.y;
                        if (relu) { o.x = fmaxf(o.x, 0.f); o.y = fmaxf(o.y, 0.f); }
                        __stcs((float2*)&C[(size_t)rr * DD + col], o);
                    }
                }
            }
        }
    }
}

// ---------------- attention partial reduce: a_src/a_dst [N,H] ---------------
__global__ void k_attred() {
    int i = blockIdx.x * blockDim.x + threadIdx.x;   // n*4 + h
    if (i >= NN * HH) return;
    float4 v = *(const float4*)&g_attp[(size_t)i * 4];
    g_asrc[i] = v.x + v.z;
    g_adst[i] = v.y + v.w;
}

// ---------------- GAT + combine fused: warp per node (online softmax) -------
__device__ __forceinline__ float pick4(float4 v, int h) {
    float r = v.x;
    r = (h == 1) ? v.y : r;
    r = (h == 2) ? v.z : r;
    r = (h == 3) ? v.w : r;
    return r;
}

__global__ void __launch_bounds__(256) k_gatc(
    const float* __restrict__ bg, const float* __restrict__ lng,
    const float* __restrict__ lnb, const float* __restrict__ betas, int first)
{
    int w = (blockIdx.x * blockDim.x + threadIdx.x) >> 5;
    int lane = threadIdx.x & 31;
    if (w >= NN) return;
    int n = w;
    int h = lane >> 3;
    int colb = lane * 8;

    int beg = g_rowptr[n], end = g_rowptr[n + 1];
    float4 ad4 = *(const float4*)&g_adst[n * 4];
    float adv = pick4(ad4, h);

    float m = -1e30f, s = 0.f;
    float4 acc0 = make_float4(0,0,0,0), acc1 = make_float4(0,0,0,0);

    for (int e = beg; e < end; e++) {
        int src = g_srcs[e];
        float4 as4 = *(const float4*)&g_asrc[src * 4];
        float ev = pick4(as4, h) + adv;
        ev = ev > 0.f ? ev : NEG_SLOPE * ev;
        float nm = fmaxf(m, ev);
        float sc = __expf(m - nm);
        float wg = __expf(ev - nm);
        m = nm;
        s = fmaf(s, sc, wg);
        // fp16 gather: 8 cols = 16 bytes
        const __half2* hp = (const __half2*)&g_hgh[(size_t)src * DD + colb];
        uint4 raw = *(const uint4*)hp;
        float2 f0 = __half22float2(*(const __half2*)&raw.x);
        float2 f1 = __half22float2(*(const __half2*)&raw.y);
        float2 f2 = __half22float2(*(const __half2*)&raw.z);
        float2 f3 = __half22float2(*(const __half2*)&raw.w);
        acc0.x = fmaf(wg, f0.x, acc0.x * sc);
        acc0.y = fmaf(wg, f0.y, acc0.y * sc);
        acc0.z = fmaf(wg, f1.x, acc0.z * sc);
        acc0.w = fmaf(wg, f1.y, acc0.w * sc);
        acc1.x = fmaf(wg, f2.x, acc1.x * sc);
        acc1.y = fmaf(wg, f2.y, acc1.y * sc);
        acc1.z = fmaf(wg, f3.x, acc1.z * sc);
        acc1.w = fmaf(wg, f3.y, acc1.w * sc);
    }
    float inv = 1.f / s;
    size_t idx = (size_t)n * DD + colb;
    float4 b0 = *(const float4*)&bg[colb];
    float4 b1 = *(const float4*)&bg[colb + 4];
    float4 x0 = __ldcs((const float4*)&g_xl[idx]);
    float4 x1 = __ldcs((const float4*)&g_xl[idx + 4]);

    float xn[8];
    xn[0] = fmaxf(fmaf(acc0.x, inv, b0.x + x0.x), 0.f);
    xn[1] = fmaxf(fmaf(acc0.y, inv, b0.y + x0.y), 0.f);
    xn[2] = fmaxf(fmaf(acc0.z, inv, b0.z + x0.z), 0.f);
    xn[3] = fmaxf(fmaf(acc0.w, inv, b0.w + x0.w), 0.f);
    xn[4] = fmaxf(fmaf(acc1.x, inv, b1.x + x1.x), 0.f);
    xn[5] = fmaxf(fmaf(acc1.y, inv, b1.y + x1.y), 0.f);
    xn[6] = fmaxf(fmaf(acc1.z, inv, b1.z + x1.z), 0.f);
    xn[7] = fmaxf(fmaf(acc1.w, inv, b1.w + x1.w), 0.f);

    // ---- fused combine: x = (1-beta)*LN(h*xn) + beta*xn ; xloc += x ----
    float4 h0 = __ldcs((const float4*)&g_h[idx]);
    float4 h1 = __ldcs((const float4*)&g_h[idx + 4]);
    float t[8] = {h0.x * xn[0], h0.y * xn[1], h0.z * xn[2], h0.w * xn[3],
                  h1.x * xn[4], h1.y * xn[5], h1.z * xn[6], h1.w * xn[7]};

    float sum = 0.f, sq = 0.f;
#pragma unroll
    for (int i = 0; i < 8; i++) { sum += t[i]; sq += t[i] * t[i]; }
#pragma unroll
    for (int o = 16; o; o >>= 1) {
        sum += __shfl_xor_sync(0xFFFFFFFFu, sum, o);
        sq  += __shfl_xor_sync(0xFFFFFFFFu, sq,  o);
    }
    float mean = sum * (1.f / DD);
    float var = sq * (1.f / DD) - mean * mean;
    float rs = rsqrtf(var + LNEPS);

    float4 lg0 = *(const float4*)&lng[colb];
    float4 lg1 = *(const float4*)&lng[colb + 4];
    float4 lb0 = *(const float4*)&lnb[colb];
    float4 lb1 = *(const float4*)&lnb[colb + 4];
    float4 be0 = *(const float4*)&betas[colb];
    float4 be1 = *(const float4*)&betas[colb + 4];
    float lg[8] = {lg0.x, lg0.y, lg0.z, lg0.w, lg1.x, lg1.y, lg1.z, lg1.w};
    float lb[8] = {lb0.x, lb0.y, lb0.z, lb0.w, lb1.x, lb1.y, lb1.z, lb1.w};
    float bev[8] = {be0.x, be0.y, be0.z, be0.w, be1.x, be1.y, be1.z, be1.w};

    float out[8];
#pragma unroll
    for (int i = 0; i < 8; i++) {
        float ln = (t[i] - mean) * rs * lg[i] + lb[i];
        float be = 1.f / (1.f + __expf(-bev[i]));
        out[i] = (1.f - be) * ln + be * xn[i];
    }

    // g_x rounded to tf32 (next GEMM input); xloc full precision
    float4 r0, r1;
    r0.x = __uint_as_float(f2tf32(out[0]));
    r0.y = __uint_as_float(f2tf32(out[1]));
    r0.z = __uint_as_float(f2tf32(out[2]));
    r0.w = __uint_as_float(f2tf32(out[3]));
    r1.x = __uint_as_float(f2tf32(out[4]));
    r1.y = __uint_as_float(f2tf32(out[5]));
    r1.z = __uint_as_float(f2tf32(out[6]));
    r1.w = __uint_as_float(f2tf32(out[7]));
    __stcs((float4*)&g_x[idx],     r0);
    __stcs((float4*)&g_x[idx + 4], r1);

    float4 o0 = make_float4(out[0], out[1], out[2], out[3]);
    float4 o1 = make_float4(out[4], out[5], out[6], out[7]);
    if (first) {
        __stcs((float4*)&g_xloc[idx],     o0);
        __stcs((float4*)&g_xloc[idx + 4], o1);
    } else {
        float4 l0 = __ldcs((const float4*)&g_xloc[idx]);
        float4 l1 = __ldcs((const float4*)&g_xloc[idx + 4]);
        l0.x += o0.x; l0.y += o0.y; l0.z += o0.z; l0.w += o0.w;
        l1.x += o1.x; l1.y += o1.y; l1.z += o1.z; l1.w += o1.w;
        __stcs((float4*)&g_xloc[idx],     l0);
        __stcs((float4*)&g_xloc[idx + 4], l1);
    }
}

// ---------------- driver -----------------------------------------------------
extern "C" void kernel_launch(void* const* d_in, const int* in_sizes, int n_in,
                              void* d_out, int out_size) {
    const float* x_in   = (const float*)d_in[0];
    const int*   ei     = (const int*)  d_in[1];
    const float* Win    = (const float*)d_in[2];
    const float* b_in   = (const float*)d_in[3];
    const float* Wh     = (const float*)d_in[4];
    const float* bh     = (const float*)d_in[5];
    const float* Wg     = (const float*)d_in[6];
    const float* attS   = (const float*)d_in[7];
    const float* attD   = (const float*)d_in[8];
    const float* bg     = (const float*)d_in[9];
    const float* Wl     = (const float*)d_in[10];
    const float* bl     = (const float*)d_in[11];
    const float* lng    = (const float*)d_in[12];
    const float* lnb    = (const float*)d_in[13];
    const float* betas  = (const float*)d_in[14];
    const float* Wp     = (const float*)d_in[15];
    const float* bp     = (const float*)d_in[16];
    float* out = (float*)d_out;

    cudaFuncSetAttribute(k_mma3a, cudaFuncAttributeMaxDynamicSharedMemorySize, SMEM3);

    static cudaStream_t s2 = nullptr;
    static cudaEvent_t evFork = nullptr, evJoin = nullptr;
    if (s2 == nullptr) {
        cudaStreamCreateWithFlags(&s2, cudaStreamNonBlocking);
        cudaEventCreateWithFlags(&evFork, cudaEventDisableTiming);
        cudaEventCreateWithFlags(&evJoin, cudaEventDisableTiming);
    }

    float* px;   cudaGetSymbolAddress((void**)&px,   g_x);
    float* ph;   cudaGetSymbolAddress((void**)&ph,   g_h);
    float* pxl;  cudaGetSymbolAddress((void**)&pxl,  g_xl);
    float* pxlo; cudaGetSymbolAddress((void**)&pxlo, g_xloc);
    float* pwr;  cudaGetSymbolAddress((void**)&pwr,  g_wr);

    const float* rWh = pwr;
    const float* rWg = pwr + 196608;
    const float* rWl = pwr + 393216;

    dim3 gA(DD / GBN, cdiv(NN, GBM));   // (2, 782)
    dim3 gF(6, cdiv(NN, GBM));          // (6, 782)

    // fork: CSR chain on s2
    cudaEventRecord(evFork, 0);
    cudaStreamWaitEvent(s2, evFork, 0);

    k_round<<<cdiv(589824, 256), 256>>>(Wh, Wg, Wl);
    k_mma<false, true, true><<<gA, 256>>>(x_in, Win, b_in, px, NN, DD, DD);
    k_init_cnt<<<cdiv(NN, 256), 256, 0, s2>>>();
    k_mma3a<<<gF, 256, SMEM3>>>(px, rWh, bh, rWg, rWl, bl, attS, attD, ph, pxl);

    k_hist<<<cdiv(EE, 256), 256, 0, s2>>>(ei);
    int nb = cdiv(NN, 1024);
    k_scan1<<<nb, 1024, 0, s2>>>();
    k_scan2<<<1, 32, 0, s2>>>(nb);
    k_scan3<<<cdiv(NN, 256), 256, 0, s2>>>();
    k_scatter<<<cdiv(EE + NN, 256), 256, 0, s2>>>(ei);
    cudaEventRecord(evJoin, s2);
    cudaStreamWaitEvent(0, evJoin, 0);

    for (int i = 0; i < 3; i++) {
        if (i > 0) {
            k_mma3a<<<gF, 256, SMEM3>>>(px, rWh + i * 65536, bh + i * DD,
                                        rWg + i * 65536, rWl + i * 65536, bl + i * DD,
                                        attS + i * DD, attD + i * DD,
                                        ph, pxl);
        }
        k_attred<<<cdiv(NN * HH, 256), 256>>>();
        k_gatc<<<cdiv(NN * 32, 256), 256>>>(bg + i * DD, lng + i * DD,
                                            lnb + i * DD, betas + i * DD, i == 0);
    }

    // out = xloc @ Wp + bp
    k_mmaO<<<cdiv(NN, 128), 256>>>(pxlo, Wp, bp, out);
}

// round 15
// speedup vs baseline: 1.7748x; 1.4533x over previous
#include <cuda_runtime.h>
#include <cuda_fp16.h>
#include <cstdint>

// ----------------------------------------------------------------------------
// Polynormer forward: N=100000, E=1.6M, D=256, H=4, C=64, L=3, OUT=64
// R15: fused layer GEMMs switched to fp16 m16n8k16 MMA (fp16 mantissa ==
//      tf32 mantissa; fp32 accumulate). MMAs, LDSMs, cp.async bytes and smem
//      all halve. x and weights stored fp16 for the layer GEMMs.
// ----------------------------------------------------------------------------

#define NN 100000
#define EE 1600000
#define DD 256
#define HH 4
#define OUTD 64
#define NEG_SLOPE 0.2f
#define LNEPS 1e-5f

// ---------------- scratch (device globals; allocation-free) -----------------
__device__ __half g_xh  [NN * DD];        // fp16 x (layer-GEMM A operand)
__device__ float  g_h   [NN * DD];
__device__ __half g_hgh [NN * DD];        // fp16 hg (gather target)
__device__ float  g_xl  [NN * DD];
__device__ float  g_xloc[NN * DD];
__device__ __half g_wrh [3 * 196608];     // fp16, TRANSPOSED [n][k] Wh|Wg|Wl
__device__ float  g_asrc[NN * HH];
__device__ float  g_adst[NN * HH];
__device__ float  g_attp[NN * HH * 4];
__device__ int    g_cnt   [NN];
__device__ int    g_rowptr[NN + 1];
__device__ int    g_cursor[NN];
__device__ int    g_srcs  [EE + NN];
__device__ int    g_bsum[128];
__device__ int    g_boff[128];

static inline int cdiv(int a, int b) { return (a + b - 1) / b; }

__device__ __forceinline__ uint32_t f2tf32(float f) {
    uint32_t u;
    asm("cvt.rna.tf32.f32 %0, %1;" : "=r"(u) : "f"(f));
    return u;
}

// ---------------- CSR build --------------------------------------------------
__global__ void k_init_cnt() {
    int i = blockIdx.x * blockDim.x + threadIdx.x;
    if (i < NN) g_cnt[i] = 1;  // self loop
}

__global__ void k_hist(const int* __restrict__ ei) {
    int i = blockIdx.x * blockDim.x + threadIdx.x;
    if (i < EE) atomicAdd(&g_cnt[ei[EE + i]], 1);
}

__global__ void k_scan1() {
    __shared__ int sh[1024];
    int t = threadIdx.x, b = blockIdx.x;
    int idx = b * 1024 + t;
    int v = (idx < NN) ? g_cnt[idx] : 0;
    sh[t] = v;
    for (int off = 1; off < 1024; off <<= 1) {
        __syncthreads();
        int u = (t >= off) ? sh[t - off] : 0;
        __syncthreads();
        sh[t] += u;
    }
    if (idx < NN) g_rowptr[idx + 1] = sh[t];
    if (t == 1023) g_bsum[b] = sh[t];
}

__global__ void k_scan2(int nb) {
    if (threadIdx.x == 0 && blockIdx.x == 0) {
        int acc = 0;
        for (int i = 0; i < nb; i++) { g_boff[i] = acc; acc += g_bsum[i]; }
    }
}

__global__ void k_scan3() {
    int idx = blockIdx.x * blockDim.x + threadIdx.x;
    if (idx == 0) { g_rowptr[0] = 0; g_cursor[0] = 0; }
    if (idx < NN) {
        int v = g_rowptr[idx + 1] + g_boff[idx >> 10];
        g_rowptr[idx + 1] = v;
        if (idx + 1 < NN) g_cursor[idx + 1] = v;
    }
}

__global__ void k_scatter(const int* __restrict__ ei) {
    int idx = blockIdx.x * blockDim.x + threadIdx.x;
    int src, dst;
    if (idx < EE)            { src = ei[idx]; dst = ei[EE + idx]; }
    else if (idx < EE + NN)  { src = idx - EE; dst = src; }
    else return;
    int pos = atomicAdd(&g_cursor[dst], 1);
    g_srcs[pos] = src;
}

// ---------------- weight fp16 + transpose to [n][k] --------------------------
__global__ void k_round(const float* __restrict__ Wh, const float* __restrict__ Wg,
                        const float* __restrict__ Wl) {
    int t = blockIdx.x * blockDim.x + threadIdx.x;    // element index
    if (t >= 589824) return;                           // 9 matrices of 256x256
    int m = t >> 16;
    int o = t & 65535;
    int n = o >> 8, k = o & 255;
    const float* src = (m < 3) ? (Wh + m * 65536)
                     : (m < 6) ? (Wg + (m - 3) * 65536)
                               : (Wl + (m - 6) * 65536);
    g_wrh[t] = __float2half_rn(src[k * 256 + n]);
}

// ---------------- MMA primitives ---------------------------------------------
#define GBM 128
#define GBN 128
#define GBK 16

__device__ __forceinline__ void mma_tf32(float* d, const uint32_t* a, const uint32_t* b) {
    asm volatile(
        "mma.sync.aligned.m16n8k8.row.col.f32.tf32.tf32.f32 "
        "{%0,%1,%2,%3}, {%4,%5,%6,%7}, {%8,%9}, {%0,%1,%2,%3};\n"
        : "+f"(d[0]), "+f"(d[1]), "+f"(d[2]), "+f"(d[3])
        : "r"(a[0]), "r"(a[1]), "r"(a[2]), "r"(a[3]), "r"(b[0]), "r"(b[1]));
}

__device__ __forceinline__ void mma_f16(float* d, const uint32_t* a, const uint32_t* b) {
    asm volatile(
        "mma.sync.aligned.m16n8k16.row.col.f32.f16.f16.f32 "
        "{%0,%1,%2,%3}, {%4,%5,%6,%7}, {%8,%9}, {%0,%1,%2,%3};\n"
        : "+f"(d[0]), "+f"(d[1]), "+f"(d[2]), "+f"(d[3])
        : "r"(a[0]), "r"(a[1]), "r"(a[2]), "r"(a[3]), "r"(b[0]), "r"(b[1]));
}

__device__ __forceinline__ void cpa16(uint32_t sa, const void* g, bool p) {
    int sz = p ? 16 : 0;
    asm volatile("cp.async.cg.shared.global [%0], [%1], 16, %2;\n"
                 :: "r"(sa), "l"(g), "r"(sz) : "memory");
}
#define CP_COMMIT() asm volatile("cp.async.commit_group;\n" ::: "memory")
#define CP_WAIT1()  asm volatile("cp.async.wait_group 1;\n" ::: "memory")

#define LDSM4(r0, r1, r2, r3, addr)                                            \
    asm volatile("ldmatrix.sync.aligned.m8n8.x4.shared.b16 {%0,%1,%2,%3}, [%4];" \
                 : "=r"(r0), "=r"(r1), "=r"(r2), "=r"(r3) : "r"(addr))

// ---------------- input GEMM (tf32 cvt path), writes fp16 x ------------------
__global__ void __launch_bounds__(256, 2) k_mmaIn(
    const float* __restrict__ A, const float* __restrict__ B,
    const float* __restrict__ bias, __half* __restrict__ C,
    int M, int K, int Nc)
{
    __shared__ uint32_t As[2][GBM][GBK + 4];
    __shared__ uint32_t Bs[2][GBK][GBN + 8];

    int tid  = threadIdx.x;
    int lane = tid & 31;
    int warp = tid >> 5;
    int wr = warp >> 2, wc = warp & 3;
    int lr = lane >> 2, lc = lane & 3;
    int rowBase = blockIdx.y * GBM;
    int colBase = blockIdx.x * GBN;

    int aRow = tid >> 1;
    int aK   = (tid & 1) << 3;
    int bRow = tid >> 4;
    int bCol = (tid & 15) << 3;

    float acc[4][4][4];
#pragma unroll
    for (int m = 0; m < 4; m++)
#pragma unroll
        for (int n = 0; n < 4; n++)
#pragma unroll
            for (int r = 0; r < 4; r++) acc[m][n][r] = 0.f;

    float aReg[8], bReg[8];
    const int NT = K / GBK;

    {
        bool okA = (rowBase + aRow) < M;
        const float* pA = A + (size_t)(rowBase + aRow) * K + aK;
        float4 v0 = okA ? *(const float4*)pA       : make_float4(0,0,0,0);
        float4 v1 = okA ? *(const float4*)(pA + 4) : make_float4(0,0,0,0);
        aReg[0]=v0.x; aReg[1]=v0.y; aReg[2]=v0.z; aReg[3]=v0.w;
        aReg[4]=v1.x; aReg[5]=v1.y; aReg[6]=v1.z; aReg[7]=v1.w;
        const float* pB = B + (size_t)bRow * Nc + colBase + bCol;
        float4 w0 = *(const float4*)pB;
        float4 w1 = *(const float4*)(pB + 4);
        bReg[0]=w0.x; bReg[1]=w0.y; bReg[2]=w0.z; bReg[3]=w0.w;
        bReg[4]=w1.x; bReg[5]=w1.y; bReg[6]=w1.z; bReg[7]=w1.w;
    }
#pragma unroll
    for (int j = 0; j < 8; j++) As[0][aRow][aK + j]  = f2tf32(aReg[j]);
#pragma unroll
    for (int j = 0; j < 8; j++) Bs[0][bRow][bCol + j] = f2tf32(bReg[j]);
    __syncthreads();

    for (int kt = 0; kt < NT; kt++) {
        int buf = kt & 1;
        if (kt + 1 < NT) {
            bool okA = (rowBase + aRow) < M;
            const float* pA = A + (size_t)(rowBase + aRow) * K + (kt + 1) * GBK + aK;
            float4 v0 = okA ? *(const float4*)pA       : make_float4(0,0,0,0);
            float4 v1 = okA ? *(const float4*)(pA + 4) : make_float4(0,0,0,0);
            aReg[0]=v0.x; aReg[1]=v0.y; aReg[2]=v0.z; aReg[3]=v0.w;
            aReg[4]=v1.x; aReg[5]=v1.y; aReg[6]=v1.z; aReg[7]=v1.w;
            const float* pB = B + (size_t)((kt + 1) * GBK + bRow) * Nc + colBase + bCol;
            float4 w0 = *(const float4*)pB;
            float4 w1 = *(const float4*)(pB + 4);
            bReg[0]=w0.x; bReg[1]=w0.y; bReg[2]=w0.z; bReg[3]=w0.w;
            bReg[4]=w1.x; bReg[5]=w1.y; bReg[6]=w1.z; bReg[7]=w1.w;
        }
#pragma unroll
        for (int ks = 0; ks < 2; ks++) {
            int kb = ks * 8;
            uint32_t af[4][4], bf[4][2];
#pragma unroll
            for (int mt = 0; mt < 4; mt++) {
                int r = wr * 64 + mt * 16 + lr;
                af[mt][0] = As[buf][r    ][kb + lc];
                af[mt][1] = As[buf][r + 8][kb + lc];
                af[mt][2] = As[buf][r    ][kb + lc + 4];
                af[mt][3] = As[buf][r + 8][kb + lc + 4];
            }
#pragma unroll
            for (int nt = 0; nt < 4; nt++) {
                int c = wc * 32 + nt * 8 + lr;
                bf[nt][0] = Bs[buf][kb + lc    ][c];
                bf[nt][1] = Bs[buf][kb + lc + 4][c];
            }
#pragma unroll
            for (int mt = 0; mt < 4; mt++)
#pragma unroll
                for (int nt = 0; nt < 4; nt++)
                    mma_tf32(acc[mt][nt], af[mt], bf[nt]);
        }
        if (kt + 1 < NT) {
            int nb2 = 1 - buf;
#pragma unroll
            for (int j = 0; j < 8; j++) As[nb2][aRow][aK + j]  = f2tf32(aReg[j]);
#pragma unroll
            for (int j = 0; j < 8; j++) Bs[nb2][bRow][bCol + j] = f2tf32(bReg[j]);
        }
        __syncthreads();
    }

#pragma unroll
    for (int nt = 0; nt < 4; nt++) {
        int col = colBase + wc * 32 + nt * 8 + 2 * lc;
        float2 bb = *(const float2*)&bias[col];
#pragma unroll
        for (int mt = 0; mt < 4; mt++) {
            int row = rowBase + wr * 64 + mt * 16 + lr;
#pragma unroll
            for (int half = 0; half < 2; half++) {
                int rr = row + half * 8;
                if (rr < M) {
                    float2 o;
                    o.x = acc[mt][nt][half * 2]     + bb.x;
                    o.y = acc[mt][nt][half * 2 + 1] + bb.y;
                    *(__half2*)&C[(size_t)rr * Nc + col] = __float22half2_rn(o);
                }
            }
        }
    }
}

// ---------------- output GEMM: 128x64 tile (tf32, fp32 xloc) -----------------
__global__ void __launch_bounds__(256, 2) k_mmaO(
    const float* __restrict__ A, const float* __restrict__ B,
    const float* __restrict__ bias, float* __restrict__ C)
{
    __shared__ uint32_t As[2][128][GBK + 4];
    __shared__ uint32_t Bs[2][GBK][64 + 8];

    int tid  = threadIdx.x;
    int lane = tid & 31;
    int warp = tid >> 5;
    int wr = warp >> 1, wc = warp & 1;
    int lr = lane >> 2, lc = lane & 3;
    int rowBase = blockIdx.x * 128;

    int aRow = tid >> 1;
    int aK   = (tid & 1) << 3;
    int bRow = tid >> 4;
    int bCol = (tid & 15) << 2;

    float acc[2][4][4];
#pragma unroll
    for (int m = 0; m < 2; m++)
#pragma unroll
        for (int n = 0; n < 4; n++)
#pragma unroll
            for (int r = 0; r < 4; r++) acc[m][n][r] = 0.f;

    float aReg[8], bReg[4];
    const int NT = DD / GBK;   // 16

    {
        bool okA = (rowBase + aRow) < NN;
        const float* pA = A + (size_t)(rowBase + aRow) * DD + aK;
        float4 v0 = okA ? *(const float4*)pA       : make_float4(0,0,0,0);
        float4 v1 = okA ? *(const float4*)(pA + 4) : make_float4(0,0,0,0);
        aReg[0]=v0.x; aReg[1]=v0.y; aReg[2]=v0.z; aReg[3]=v0.w;
        aReg[4]=v1.x; aReg[5]=v1.y; aReg[6]=v1.z; aReg[7]=v1.w;
        float4 w = *(const float4*)&B[(size_t)bRow * OUTD + bCol];
        bReg[0]=w.x; bReg[1]=w.y; bReg[2]=w.z; bReg[3]=w.w;
    }
#pragma unroll
    for (int j = 0; j < 8; j++) As[0][aRow][aK + j]  = f2tf32(aReg[j]);
#pragma unroll
    for (int j = 0; j < 4; j++) Bs[0][bRow][bCol + j] = f2tf32(bReg[j]);
    __syncthreads();

    for (int kt = 0; kt < NT; kt++) {
        int buf = kt & 1;
        if (kt + 1 < NT) {
            bool okA = (rowBase + aRow) < NN;
            const float* pA = A + (size_t)(rowBase + aRow) * DD + (kt + 1) * GBK + aK;
            float4 v0 = okA ? *(const float4*)pA       : make_float4(0,0,0,0);
            float4 v1 = okA ? *(const float4*)(pA + 4) : make_float4(0,0,0,0);
            aReg[0]=v0.x; aReg[1]=v0.y; aReg[2]=v0.z; aReg[3]=v0.w;
            aReg[4]=v1.x; aReg[5]=v1.y; aReg[6]=v1.z; aReg[7]=v1.w;
            float4 w = *(const float4*)&B[(size_t)((kt + 1) * GBK + bRow) * OUTD + bCol];
            bReg[0]=w.x; bReg[1]=w.y; bReg[2]=w.z; bReg[3]=w.w;
        }
#pragma unroll
        for (int ks = 0; ks < 2; ks++) {
            int kb = ks * 8;
            uint32_t af[2][4], bf[4][2];
#pragma unroll
            for (int mt = 0; mt < 2; mt++) {
                int r = wr * 32 + mt * 16 + lr;
                af[mt][0] = As[buf][r    ][kb + lc];
                af[mt][1] = As[buf][r + 8][kb + lc];
                af[mt][2] = As[buf][r    ][kb + lc + 4];
                af[mt][3] = As[buf][r + 8][kb + lc + 4];
            }
#pragma unroll
            for (int nt = 0; nt < 4; nt++) {
                int c = wc * 32 + nt * 8 + lr;
                bf[nt][0] = Bs[buf][kb + lc    ][c];
                bf[nt][1] = Bs[buf][kb + lc + 4][c];
            }
#pragma unroll
            for (int mt = 0; mt < 2; mt++)
#pragma unroll
                for (int nt = 0; nt < 4; nt++)
                    mma_tf32(acc[mt][nt], af[mt], bf[nt]);
        }
        if (kt + 1 < NT) {
            int nb2 = 1 - buf;
#pragma unroll
            for (int j = 0; j < 8; j++) As[nb2][aRow][aK + j]  = f2tf32(aReg[j]);
#pragma unroll
            for (int j = 0; j < 4; j++) Bs[nb2][bRow][bCol + j] = f2tf32(bReg[j]);
        }
        __syncthreads();
    }

#pragma unroll
    for (int nt = 0; nt < 4; nt++) {
        int col = wc * 32 + nt * 8 + 2 * lc;
        float2 bb = *(const float2*)&bias[col];
#pragma unroll
        for (int mt = 0; mt < 2; mt++) {
            int row = rowBase + wr * 32 + mt * 16 + lr;
#pragma unroll
            for (int half = 0; half < 2; half++) {
                int rr = row + half * 8;
                if (rr < NN) {
                    float2 o;
                    o.x = acc[mt][nt][half * 2]     + bb.x;
                    o.y = acc[mt][nt][half * 2 + 1] + bb.y;
                    *(float2*)&C[(size_t)rr * OUTD + col] = o;
                }
            }
        }
    }
}

// ---------------- fused 3-GEMM: fp16 m16n8k16, cp.async + ldmatrix ----------
#define GBK3 32
#define ST 3
#define TSTRH 40                    // row stride in halves (80B): conflict-free
#define TILE_H (128 * TSTRH)        // halves per stage per operand
#define SMEM3 (2 * ST * TILE_H * 2)

__global__ void __launch_bounds__(256, 2) k_mma3a(
    const __half* __restrict__ A,
    const __half* __restrict__ Wh, const float* __restrict__ bh,
    const __half* __restrict__ Wg,
    const __half* __restrict__ Wl, const float* __restrict__ bl,
    const float* __restrict__ attS, const float* __restrict__ attD,
    float* __restrict__ h, float* __restrict__ xl)
{
    extern __shared__ __half smh[];
    uint32_t sbA = (uint32_t)__cvta_generic_to_shared(smh);
    uint32_t sbB = sbA + ST * TILE_H * 2;

    int tid  = threadIdx.x;
    int lane = tid & 31;
    int warp = tid >> 5;
    int wr = warp >> 2, wc = warp & 3;
    int lr = lane >> 2, lc = lane & 3;
    int rowBase = blockIdx.y * GBM;
    int seg = blockIdx.x >> 1;
    int colBase = (blockIdx.x & 1) * GBN;
    const __half* B = (seg == 0) ? Wh : (seg == 1 ? Wg : Wl);

    // cp.async: thread t -> row t>>1, half-pair (t&1)*16 halves (2x16B)
    int row = tid >> 1;
    int kp  = (tid & 1) * 16;
    bool okA = (rowBase + row) < NN;
    const __half* gA0 = A + (size_t)(rowBase + row) * DD + kp;
    const __half* gB0 = B + (size_t)(colBase + row) * DD + kp;
    uint32_t saBase = (row * TSTRH + kp) * 2;
    // ldmatrix lane offsets (halves)
    int aOff = (wr * 64 + (lane & 15)) * TSTRH + (lane >> 4) * 8;
    int bOff = (wc * 32 + (lane & 7) + ((lane >> 4) & 1) * 8) * TSTRH
             + ((lane >> 3) & 1) * 8;

    float acc[4][4][4];
#pragma unroll
    for (int m = 0; m < 4; m++)
#pragma unroll
        for (int n = 0; n < 4; n++)
#pragma unroll
            for (int r = 0; r < 4; r++) acc[m][n][r] = 0.f;

#define ISSUE(kt, s)                                                            \
    do {                                                                        \
        const __half* gA = gA0 + (kt) * GBK3;                                   \
        uint32_t sa = sbA + (s) * TILE_H * 2 + saBase;                          \
        cpa16(sa,      gA,     okA);                                            \
        cpa16(sa + 16, gA + 8, okA);                                            \
        const __half* gB = gB0 + (kt) * GBK3;                                   \
        uint32_t sb = sbB + (s) * TILE_H * 2 + saBase;                          \
        cpa16(sb,      gB,     true);                                           \
        cpa16(sb + 16, gB + 8, true);                                           \
        CP_COMMIT();                                                            \
    } while (0)

    ISSUE(0, 0);
    ISSUE(1, 1);

    const int NT = DD / GBK3;   // 8
    for (int kt = 0; kt < NT; kt++) {
        CP_WAIT1();
        __syncthreads();
        if (kt + 2 < NT) {
            int s2 = (kt + 2) % ST;
            ISSUE(kt + 2, s2);
        } else {
            CP_COMMIT();
        }
        int s = kt % ST;
        uint32_t aS = sbA + s * TILE_H * 2 + aOff * 2;
        uint32_t bS = sbB + s * TILE_H * 2 + bOff * 2;
#pragma unroll
        for (int kc = 0; kc < 2; kc++) {      // two k16 chunks per 32-k tile
            uint32_t af[4][4], bf[4][2];
#pragma unroll
            for (int mt = 0; mt < 4; mt++)
                LDSM4(af[mt][0], af[mt][1], af[mt][2], af[mt][3],
                      aS + (mt * 16 * TSTRH + kc * 16) * 2);
            LDSM4(bf[0][0], bf[0][1], bf[1][0], bf[1][1],
                  bS + (kc * 16) * 2);
            LDSM4(bf[2][0], bf[2][1], bf[3][0], bf[3][1],
                  bS + (16 * TSTRH + kc * 16) * 2);
#pragma unroll
            for (int mt = 0; mt < 4; mt++)
#pragma unroll
                for (int nt = 0; nt < 4; nt++)
                    mma_f16(acc[mt][nt], af[mt], bf[nt]);
        }
    }
#undef ISSUE

    if (seg == 1) {
        // hg: store fp16 (gatc gather target); keep L2-resident
#pragma unroll
        for (int nt = 0; nt < 4; nt++) {
            int col = colBase + wc * 32 + nt * 8 + 2 * lc;
#pragma unroll
            for (int mt = 0; mt < 4; mt++) {
                int row2 = rowBase + wr * 64 + mt * 16 + lr;
#pragma unroll
                for (int half = 0; half < 2; half++) {
                    int rr = row2 + half * 8;
                    if (rr < NN) {
                        float2 o;
                        o.x = acc[mt][nt][half * 2];
                        o.y = acc[mt][nt][half * 2 + 1];
                        *(__half2*)&g_hgh[(size_t)rr * DD + col] =
                            __float22half2_rn(o);
                    }
                }
            }
        }
        // attention scalar partials from resident accumulators
        float2 asw[4], adw[4];
#pragma unroll
        for (int nt = 0; nt < 4; nt++) {
            int col = colBase + wc * 32 + nt * 8 + 2 * lc;
            asw[nt] = *(const float2*)&attS[col];
            adw[nt] = *(const float2*)&attD[col];
        }
        int hh = (colBase + wc * 32) >> 6;
        int slab = wc & 1;
#pragma unroll
        for (int mt = 0; mt < 4; mt++) {
#pragma unroll
            for (int half = 0; half < 2; half++) {
                float ps = 0.f, pd = 0.f;
#pragma unroll
                for (int nt = 0; nt < 4; nt++) {
                    float v0 = acc[mt][nt][half * 2];
                    float v1 = acc[mt][nt][half * 2 + 1];
                    ps = fmaf(v0, asw[nt].x, fmaf(v1, asw[nt].y, ps));
                    pd = fmaf(v0, adw[nt].x, fmaf(v1, adw[nt].y, pd));
                }
                ps += __shfl_xor_sync(0xFFFFFFFFu, ps, 1);
                ps += __shfl_xor_sync(0xFFFFFFFFu, ps, 2);
                pd += __shfl_xor_sync(0xFFFFFFFFu, pd, 1);
                pd += __shfl_xor_sync(0xFFFFFFFFu, pd, 2);
                int rr = rowBase + wr * 64 + mt * 16 + lr + half * 8;
                if (lc == 0 && rr < NN) {
                    float2 o = make_float2(ps, pd);
                    *(float2*)&g_attp[((size_t)(rr * 4 + hh) * 2 + slab) * 2] = o;
                }
            }
        }
    } else {
        bool relu = (seg == 0);
        const float* bias = (seg == 0) ? bh : bl;
        float* C = (seg == 0) ? h : xl;
#pragma unroll
        for (int nt = 0; nt < 4; nt++) {
            int col = colBase + wc * 32 + nt * 8 + 2 * lc;
            float2 bb = *(const float2*)&bias[col];
#pragma unroll
            for (int mt = 0; mt < 4; mt++) {
                int row2 = rowBase + wr * 64 + mt * 16 + lr;
#pragma unroll
                for (int half = 0; half < 2; half++) {
                    int rr = row2 + half * 8;
                    if (rr < NN) {
                        float2 o;
                        o.x = acc[mt][nt][half * 2]     + bb.x;
                        o.y = acc[mt][nt][half * 2 + 1] + bb.y;
                        if (relu) { o.x = fmaxf(o.x, 0.f); o.y = fmaxf(o.y, 0.f); }
                        __stcs((float2*)&C[(size_t)rr * DD + col], o);
                    }
                }
            }
        }
    }
}

// ---------------- attention partial reduce: a_src/a_dst [N,H] ---------------
__global__ void k_attred() {
    int i = blockIdx.x * blockDim.x + threadIdx.x;
    if (i >= NN * HH) return;
    float4 v = *(const float4*)&g_attp[(size_t)i * 4];
    g_asrc[i] = v.x + v.z;
    g_adst[i] = v.y + v.w;
}

// ---------------- GAT + combine fused: warp per node (online softmax) -------
__device__ __forceinline__ float pick4(float4 v, int h) {
    float r = v.x;
    r = (h == 1) ? v.y : r;
    r = (h == 2) ? v.z : r;
    r = (h == 3) ? v.w : r;
    return r;
}

__global__ void __launch_bounds__(256) k_gatc(
    const float* __restrict__ bg, const float* __restrict__ lng,
    const float* __restrict__ lnb, const float* __restrict__ betas, int first)
{
    int w = (blockIdx.x * blockDim.x + threadIdx.x) >> 5;
    int lane = threadIdx.x & 31;
    if (w >= NN) return;
    int n = w;
    int h = lane >> 3;
    int colb = lane * 8;

    int beg = g_rowptr[n], end = g_rowptr[n + 1];
    float4 ad4 = *(const float4*)&g_adst[n * 4];
    float adv = pick4(ad4, h);

    float m = -1e30f, s = 0.f;
    float4 acc0 = make_float4(0,0,0,0), acc1 = make_float4(0,0,0,0);

    for (int e = beg; e < end; e++) {
        int src = g_srcs[e];
        float4 as4 = *(const float4*)&g_asrc[src * 4];
        float ev = pick4(as4, h) + adv;
        ev = ev > 0.f ? ev : NEG_SLOPE * ev;
        float nm = fmaxf(m, ev);
        float sc = __expf(m - nm);
        float wg = __expf(ev - nm);
        m = nm;
        s = fmaf(s, sc, wg);
        const __half2* hp = (const __half2*)&g_hgh[(size_t)src * DD + colb];
        uint4 raw = *(const uint4*)hp;
        float2 f0 = __half22float2(*(const __half2*)&raw.x);
        float2 f1 = __half22float2(*(const __half2*)&raw.y);
        float2 f2 = __half22float2(*(const __half2*)&raw.z);
        float2 f3 = __half22float2(*(const __half2*)&raw.w);
        acc0.x = fmaf(wg, f0.x, acc0.x * sc);
        acc0.y = fmaf(wg, f0.y, acc0.y * sc);
        acc0.z = fmaf(wg, f1.x, acc0.z * sc);
        acc0.w = fmaf(wg, f1.y, acc0.w * sc);
        acc1.x = fmaf(wg, f2.x, acc1.x * sc);
        acc1.y = fmaf(wg, f2.y, acc1.y * sc);
        acc1.z = fmaf(wg, f3.x, acc1.z * sc);
        acc1.w = fmaf(wg, f3.y, acc1.w * sc);
    }
    float inv = 1.f / s;
    size_t idx = (size_t)n * DD + colb;
    float4 b0 = *(const float4*)&bg[colb];
    float4 b1 = *(const float4*)&bg[colb + 4];
    float4 x0 = __ldcs((const float4*)&g_xl[idx]);
    float4 x1 = __ldcs((const float4*)&g_xl[idx + 4]);

    float xn[8];
    xn[0] = fmaxf(fmaf(acc0.x, inv, b0.x + x0.x), 0.f);
    xn[1] = fmaxf(fmaf(acc0.y, inv, b0.y + x0.y), 0.f);
    xn[2] = fmaxf(fmaf(acc0.z, inv, b0.z + x0.z), 0.f);
    xn[3] = fmaxf(fmaf(acc0.w, inv, b0.w + x0.w), 0.f);
    xn[4] = fmaxf(fmaf(acc1.x, inv, b1.x + x1.x), 0.f);
    xn[5] = fmaxf(fmaf(acc1.y, inv, b1.y + x1.y), 0.f);
    xn[6] = fmaxf(fmaf(acc1.z, inv, b1.z + x1.z), 0.f);
    xn[7] = fmaxf(fmaf(acc1.w, inv, b1.w + x1.w), 0.f);

    // ---- fused combine: x = (1-beta)*LN(h*xn) + beta*xn ; xloc += x ----
    float4 h0 = __ldcs((const float4*)&g_h[idx]);
    float4 h1 = __ldcs((const float4*)&g_h[idx + 4]);
    float t[8] = {h0.x * xn[0], h0.y * xn[1], h0.z * xn[2], h0.w * xn[3],
                  h1.x * xn[4], h1.y * xn[5], h1.z * xn[6], h1.w * xn[7]};

    float sum = 0.f, sq = 0.f;
#pragma unroll
    for (int i = 0; i < 8; i++) { sum += t[i]; sq += t[i] * t[i]; }
#pragma unroll
    for (int o = 16; o; o >>= 1) {
        sum += __shfl_xor_sync(0xFFFFFFFFu, sum, o);
        sq  += __shfl_xor_sync(0xFFFFFFFFu, sq,  o);
    }
    float mean = sum * (1.f / DD);
    float var = sq * (1.f / DD) - mean * mean;
    float rs = rsqrtf(var + LNEPS);

    float4 lg0 = *(const float4*)&lng[colb];
    float4 lg1 = *(const float4*)&lng[colb + 4];
    float4 lb0 = *(const float4*)&lnb[colb];
    float4 lb1 = *(const float4*)&lnb[colb + 4];
    float4 be0 = *(const float4*)&betas[colb];
    float4 be1 = *(const float4*)&betas[colb + 4];
    float lg[8] = {lg0.x, lg0.y, lg0.z, lg0.w, lg1.x, lg1.y, lg1.z, lg1.w};
    float lb[8] = {lb0.x, lb0.y, lb0.z, lb0.w, lb1.x, lb1.y, lb1.z, lb1.w};
    float bev[8] = {be0.x, be0.y, be0.z, be0.w, be1.x, be1.y, be1.z, be1.w};

    float out[8];
#pragma unroll
    for (int i = 0; i < 8; i++) {
        float ln = (t[i] - mean) * rs * lg[i] + lb[i];
        float be = 1.f / (1.f + __expf(-bev[i]));
        out[i] = (1.f - be) * ln + be * xn[i];
    }

    // g_xh fp16 (next-layer GEMM input); xloc full precision
    *(__half2*)&g_xh[idx]     = __float22half2_rn(make_float2(out[0], out[1]));
    *(__half2*)&g_xh[idx + 2] = __float22half2_rn(make_float2(out[2], out[3]));
    *(__half2*)&g_xh[idx + 4] = __float22half2_rn(make_float2(out[4], out[5]));
    *(__half2*)&g_xh[idx + 6] = __float22half2_rn(make_float2(out[6], out[7]));

    float4 o0 = make_float4(out[0], out[1], out[2], out[3]);
    float4 o1 = make_float4(out[4], out[5], out[6], out[7]);
    if (first) {
        __stcs((float4*)&g_xloc[idx],     o0);
        __stcs((float4*)&g_xloc[idx + 4], o1);
    } else {
        float4 l0 = __ldcs((const float4*)&g_xloc[idx]);
        float4 l1 = __ldcs((const float4*)&g_xloc[idx + 4]);
        l0.x += o0.x; l0.y += o0.y; l0.z += o0.z; l0.w += o0.w;
        l1.x += o1.x; l1.y += o1.y; l1.z += o1.z; l1.w += o1.w;
        __stcs((float4*)&g_xloc[idx],     l0);
        __stcs((float4*)&g_xloc[idx + 4], l1);
    }
}

// ---------------- driver -----------------------------------------------------
extern "C" void kernel_launch(void* const* d_in, const int* in_sizes, int n_in,
                              void* d_out, int out_size) {
    const float* x_in   = (const float*)d_in[0];
    const int*   ei     = (const int*)  d_in[1];
    const float* Win    = (const float*)d_in[2];
    const float* b_in   = (const float*)d_in[3];
    const float* Wh     = (const float*)d_in[4];
    const float* bh     = (const float*)d_in[5];
    const float* Wg     = (const float*)d_in[6];
    const float* attS   = (const float*)d_in[7];
    const float* attD   = (const float*)d_in[8];
    const float* bg     = (const float*)d_in[9];
    const float* Wl     = (const float*)d_in[10];
    const float* bl     = (const float*)d_in[11];
    const float* lng    = (const float*)d_in[12];
    const float* lnb    = (const float*)d_in[13];
    const float* betas  = (const float*)d_in[14];
    const float* Wp     = (const float*)d_in[15];
    const float* bp     = (const float*)d_in[16];
    float* out = (float*)d_out;

    cudaFuncSetAttribute(k_mma3a, cudaFuncAttributeMaxDynamicSharedMemorySize, SMEM3);

    static cudaStream_t s2 = nullptr;
    static cudaEvent_t evFork = nullptr, evJoin = nullptr;
    if (s2 == nullptr) {
        cudaStreamCreateWithFlags(&s2, cudaStreamNonBlocking);
        cudaEventCreateWithFlags(&evFork, cudaEventDisableTiming);
        cudaEventCreateWithFlags(&evJoin, cudaEventDisableTiming);
    }

    __half* pxh;  cudaGetSymbolAddress((void**)&pxh,  g_xh);
    float*  ph;   cudaGetSymbolAddress((void**)&ph,   g_h);
    float*  pxl;  cudaGetSymbolAddress((void**)&pxl,  g_xl);
    float*  pxlo; cudaGetSymbolAddress((void**)&pxlo, g_xloc);
    __half* pwrh; cudaGetSymbolAddress((void**)&pwrh, g_wrh);

    const __half* rWh = pwrh;
    const __half* rWg = pwrh + 196608;
    const __half* rWl = pwrh + 393216;

    dim3 gA(DD / GBN, cdiv(NN, GBM));   // (2, 782)
    dim3 gF(6, cdiv(NN, GBM));          // (6, 782)

    // fork: CSR chain on s2
    cudaEventRecord(evFork, 0);
    cudaStreamWaitEvent(s2, evFork, 0);

    k_round<<<cdiv(589824, 256), 256>>>(Wh, Wg, Wl);
    k_mmaIn<<<gA, 256>>>(x_in, Win, b_in, pxh, NN, DD, DD);
    k_init_cnt<<<cdiv(NN, 256), 256, 0, s2>>>();
    k_mma3a<<<gF, 256, SMEM3>>>(pxh, rWh, bh, rWg, rWl, bl, attS, attD, ph, pxl);

    k_hist<<<cdiv(EE, 256), 256, 0, s2>>>(ei);
    int nb = cdiv(NN, 1024);
    k_scan1<<<nb, 1024, 0, s2>>>();
    k_scan2<<<1, 32, 0, s2>>>(nb);
    k_scan3<<<cdiv(NN, 256), 256, 0, s2>>>();
    k_scatter<<<cdiv(EE + NN, 256), 256, 0, s2>>>(ei);
    cudaEventRecord(evJoin, s2);
    cudaStreamWaitEvent(0, evJoin, 0);

    for (int i = 0; i < 3; i++) {
        if (i > 0) {
            k_mma3a<<<gF, 256, SMEM3>>>(pxh, rWh + i * 65536, bh + i * DD,
                                        rWg + i * 65536, rWl + i * 65536, bl + i * DD,
                                        attS + i * DD, attD + i * DD,
                                        ph, pxl);
        }
        k_attred<<<cdiv(NN * HH, 256), 256>>>();
        k_gatc<<<cdiv(NN * 32, 256), 256>>>(bg + i * DD, lng + i * DD,
                                            lnb + i * DD, betas + i * DD, i == 0);
    }

    // out = xloc @ Wp + bp
    k_mmaO<<<cdiv(NN, 128), 256>>>(pxlo, Wp, bp, out);
}

// round 16
// speedup vs baseline: 1.8440x; 1.0390x over previous
#include <cuda_runtime.h>
#include <cuda_fp16.h>
#include <cstdint>

// ----------------------------------------------------------------------------
// Polynormer forward: N=100000, E=1.6M, D=256, H=4, C=64, L=3, OUT=64
// R16: input GEMM also fp16 (x_in pre-converted, Win transposed fp16);
//      h and xl stored fp16 (only consumer is gatc streaming side) —
//      cuts k_mma3a store traffic and 100MB/launch of gatc reads.
// ----------------------------------------------------------------------------

#define NN 100000
#define EE 1600000
#define DD 256
#define HH 4
#define OUTD 64
#define NEG_SLOPE 0.2f
#define LNEPS 1e-5f

// ---------------- scratch (device globals; allocation-free) -----------------
__device__ __half g_xin [NN * DD];        // fp16 converted input features
__device__ __half g_xh  [NN * DD];        // fp16 x (layer-GEMM A operand)
__device__ __half g_h   [NN * DD];        // fp16 h
__device__ __half g_hgh [NN * DD];        // fp16 hg (gather target)
__device__ __half g_xl  [NN * DD];        // fp16 xl
__device__ float  g_xloc[NN * DD];
__device__ __half g_wrh [655360];         // fp16 transposed: Wh|Wg|Wl (9) + Win
__device__ float  g_asrc[NN * HH];
__device__ float  g_adst[NN * HH];
__device__ float  g_attp[NN * HH * 4];
__device__ int    g_cnt   [NN];
__device__ int    g_rowptr[NN + 1];
__device__ int    g_cursor[NN];
__device__ int    g_srcs  [EE + NN];
__device__ int    g_bsum[128];
__device__ int    g_boff[128];

static inline int cdiv(int a, int b) { return (a + b - 1) / b; }

__device__ __forceinline__ uint32_t f2tf32(float f) {
    uint32_t u;
    asm("cvt.rna.tf32.f32 %0, %1;" : "=r"(u) : "f"(f));
    return u;
}

// ---------------- CSR build --------------------------------------------------
__global__ void k_init_cnt() {
    int i = blockIdx.x * blockDim.x + threadIdx.x;
    if (i < NN) g_cnt[i] = 1;  // self loop
}

__global__ void k_hist(const int* __restrict__ ei) {
    int i = blockIdx.x * blockDim.x + threadIdx.x;
    if (i < EE) atomicAdd(&g_cnt[ei[EE + i]], 1);
}

__global__ void k_scan1() {
    __shared__ int sh[1024];
    int t = threadIdx.x, b = blockIdx.x;
    int idx = b * 1024 + t;
    int v = (idx < NN) ? g_cnt[idx] : 0;
    sh[t] = v;
    for (int off = 1; off < 1024; off <<= 1) {
        __syncthreads();
        int u = (t >= off) ? sh[t - off] : 0;
        __syncthreads();
        sh[t] += u;
    }
    if (idx < NN) g_rowptr[idx + 1] = sh[t];
    if (t == 1023) g_bsum[b] = sh[t];
}

__global__ void k_scan2(int nb) {
    if (threadIdx.x == 0 && blockIdx.x == 0) {
        int acc = 0;
        for (int i = 0; i < nb; i++) { g_boff[i] = acc; acc += g_bsum[i]; }
    }
}

__global__ void k_scan3() {
    int idx = blockIdx.x * blockDim.x + threadIdx.x;
    if (idx == 0) { g_rowptr[0] = 0; g_cursor[0] = 0; }
    if (idx < NN) {
        int v = g_rowptr[idx + 1] + g_boff[idx >> 10];
        g_rowptr[idx + 1] = v;
        if (idx + 1 < NN) g_cursor[idx + 1] = v;
    }
}

__global__ void k_scatter(const int* __restrict__ ei) {
    int idx = blockIdx.x * blockDim.x + threadIdx.x;
    int src, dst;
    if (idx < EE)            { src = ei[idx]; dst = ei[EE + idx]; }
    else if (idx < EE + NN)  { src = idx - EE; dst = src; }
    else return;
    int pos = atomicAdd(&g_cursor[dst], 1);
    g_srcs[pos] = src;
}

// ---------------- weight fp16 + transpose to [n][k] (9 layer mats + Win) ----
__global__ void k_round(const float* __restrict__ Wh, const float* __restrict__ Wg,
                        const float* __restrict__ Wl, const float* __restrict__ Win) {
    int t = blockIdx.x * blockDim.x + threadIdx.x;
    if (t >= 655360) return;                           // 10 matrices of 256x256
    int m = t >> 16;
    int o = t & 65535;
    int n = o >> 8, k = o & 255;
    const float* src = (m < 3) ? (Wh + m * 65536)
                     : (m < 6) ? (Wg + (m - 3) * 65536)
                     : (m < 9) ? (Wl + (m - 6) * 65536)
                               : Win;
    g_wrh[t] = __float2half_rn(src[k * 256 + n]);
}

// ---------------- x_in fp32 -> fp16 ------------------------------------------
__global__ void k_xcvt(const float* __restrict__ x_in) {
    int i = blockIdx.x * blockDim.x + threadIdx.x;    // 8 elements each
    if (i >= NN * DD / 8) return;
    const float4* p = (const float4*)(x_in + (size_t)i * 8);
    float4 a = p[0], b = p[1];
    uint4 o;
    *(__half2*)&o.x = __float22half2_rn(make_float2(a.x, a.y));
    *(__half2*)&o.y = __float22half2_rn(make_float2(a.z, a.w));
    *(__half2*)&o.z = __float22half2_rn(make_float2(b.x, b.y));
    *(__half2*)&o.w = __float22half2_rn(make_float2(b.z, b.w));
    *(uint4*)&g_xin[(size_t)i * 8] = o;
}

// ---------------- MMA primitives ---------------------------------------------
#define GBM 128
#define GBN 128
#define GBK 16

__device__ __forceinline__ void mma_tf32(float* d, const uint32_t* a, const uint32_t* b) {
    asm volatile(
        "mma.sync.aligned.m16n8k8.row.col.f32.tf32.tf32.f32 "
        "{%0,%1,%2,%3}, {%4,%5,%6,%7}, {%8,%9}, {%0,%1,%2,%3};\n"
        : "+f"(d[0]), "+f"(d[1]), "+f"(d[2]), "+f"(d[3])
        : "r"(a[0]), "r"(a[1]), "r"(a[2]), "r"(a[3]), "r"(b[0]), "r"(b[1]));
}

__device__ __forceinline__ void mma_f16(float* d, const uint32_t* a, const uint32_t* b) {
    asm volatile(
        "mma.sync.aligned.m16n8k16.row.col.f32.f16.f16.f32 "
        "{%0,%1,%2,%3}, {%4,%5,%6,%7}, {%8,%9}, {%0,%1,%2,%3};\n"
        : "+f"(d[0]), "+f"(d[1]), "+f"(d[2]), "+f"(d[3])
        : "r"(a[0]), "r"(a[1]), "r"(a[2]), "r"(a[3]), "r"(b[0]), "r"(b[1]));
}

__device__ __forceinline__ void cpa16(uint32_t sa, const void* g, bool p) {
    int sz = p ? 16 : 0;
    asm volatile("cp.async.cg.shared.global [%0], [%1], 16, %2;\n"
                 :: "r"(sa), "l"(g), "r"(sz) : "memory");
}
#define CP_COMMIT() asm volatile("cp.async.commit_group;\n" ::: "memory")
#define CP_WAIT1()  asm volatile("cp.async.wait_group 1;\n" ::: "memory")

#define LDSM4(r0, r1, r2, r3, addr)                                            \
    asm volatile("ldmatrix.sync.aligned.m8n8.x4.shared.b16 {%0,%1,%2,%3}, [%4];" \
                 : "=r"(r0), "=r"(r1), "=r"(r2), "=r"(r3) : "r"(addr))

// ---------------- output GEMM: 128x64 tile (tf32, fp32 xloc) -----------------
__global__ void __launch_bounds__(256, 2) k_mmaO(
    const float* __restrict__ A, const float* __restrict__ B,
    const float* __restrict__ bias, float* __restrict__ C)
{
    __shared__ uint32_t As[2][128][GBK + 4];
    __shared__ uint32_t Bs[2][GBK][64 + 8];

    int tid  = threadIdx.x;
    int lane = tid & 31;
    int warp = tid >> 5;
    int wr = warp >> 1, wc = warp & 1;
    int lr = lane >> 2, lc = lane & 3;
    int rowBase = blockIdx.x * 128;

    int aRow = tid >> 1;
    int aK   = (tid & 1) << 3;
    int bRow = tid >> 4;
    int bCol = (tid & 15) << 2;

    float acc[2][4][4];
#pragma unroll
    for (int m = 0; m < 2; m++)
#pragma unroll
        for (int n = 0; n < 4; n++)
#pragma unroll
            for (int r = 0; r < 4; r++) acc[m][n][r] = 0.f;

    float aReg[8], bReg[4];
    const int NT = DD / GBK;   // 16

    {
        bool okA = (rowBase + aRow) < NN;
        const float* pA = A + (size_t)(rowBase + aRow) * DD + aK;
        float4 v0 = okA ? *(const float4*)pA       : make_float4(0,0,0,0);
        float4 v1 = okA ? *(const float4*)(pA + 4) : make_float4(0,0,0,0);
        aReg[0]=v0.x; aReg[1]=v0.y; aReg[2]=v0.z; aReg[3]=v0.w;
        aReg[4]=v1.x; aReg[5]=v1.y; aReg[6]=v1.z; aReg[7]=v1.w;
        float4 w = *(const float4*)&B[(size_t)bRow * OUTD + bCol];
        bReg[0]=w.x; bReg[1]=w.y; bReg[2]=w.z; bReg[3]=w.w;
    }
#pragma unroll
    for (int j = 0; j < 8; j++) As[0][aRow][aK + j]  = f2tf32(aReg[j]);
#pragma unroll
    for (int j = 0; j < 4; j++) Bs[0][bRow][bCol + j] = f2tf32(bReg[j]);
    __syncthreads();

    for (int kt = 0; kt < NT; kt++) {
        int buf = kt & 1;
        if (kt + 1 < NT) {
            bool okA = (rowBase + aRow) < NN;
            const float* pA = A + (size_t)(rowBase + aRow) * DD + (kt + 1) * GBK + aK;
            float4 v0 = okA ? *(const float4*)pA       : make_float4(0,0,0,0);
            float4 v1 = okA ? *(const float4*)(pA + 4) : make_float4(0,0,0,0);
            aReg[0]=v0.x; aReg[1]=v0.y; aReg[2]=v0.z; aReg[3]=v0.w;
            aReg[4]=v1.x; aReg[5]=v1.y; aReg[6]=v1.z; aReg[7]=v1.w;
            float4 w = *(const float4*)&B[(size_t)((kt + 1) * GBK + bRow) * OUTD + bCol];
            bReg[0]=w.x; bReg[1]=w.y; bReg[2]=w.z; bReg[3]=w.w;
        }
#pragma unroll
        for (int ks = 0; ks < 2; ks++) {
            int kb = ks * 8;
            uint32_t af[2][4], bf[4][2];
#pragma unroll
            for (int mt = 0; mt < 2; mt++) {
                int r = wr * 32 + mt * 16 + lr;
                af[mt][0] = As[buf][r    ][kb + lc];
                af[mt][1] = As[buf][r + 8][kb + lc];
                af[mt][2] = As[buf][r    ][kb + lc + 4];
                af[mt][3] = As[buf][r + 8][kb + lc + 4];
            }
#pragma unroll
            for (int nt = 0; nt < 4; nt++) {
                int c = wc * 32 + nt * 8 + lr;
                bf[nt][0] = Bs[buf][kb + lc    ][c];
                bf[nt][1] = Bs[buf][kb + lc + 4][c];
            }
#pragma unroll
            for (int mt = 0; mt < 2; mt++)
#pragma unroll
                for (int nt = 0; nt < 4; nt++)
                    mma_tf32(acc[mt][nt], af[mt], bf[nt]);
        }
        if (kt + 1 < NT) {
            int nb2 = 1 - buf;
#pragma unroll
            for (int j = 0; j < 8; j++) As[nb2][aRow][aK + j]  = f2tf32(aReg[j]);
#pragma unroll
            for (int j = 0; j < 4; j++) Bs[nb2][bRow][bCol + j] = f2tf32(bReg[j]);
        }
        __syncthreads();
    }

#pragma unroll
    for (int nt = 0; nt < 4; nt++) {
        int col = wc * 32 + nt * 8 + 2 * lc;
        float2 bb = *(const float2*)&bias[col];
#pragma unroll
        for (int mt = 0; mt < 2; mt++) {
            int row = rowBase + wr * 32 + mt * 16 + lr;
#pragma unroll
            for (int half = 0; half < 2; half++) {
                int rr = row + half * 8;
                if (rr < NN) {
                    float2 o;
                    o.x = acc[mt][nt][half * 2]     + bb.x;
                    o.y = acc[mt][nt][half * 2 + 1] + bb.y;
                    *(float2*)&C[(size_t)rr * OUTD + col] = o;
                }
            }
        }
    }
}

// ---------------- shared fp16 GEMM mainloop constants ------------------------
#define GBK3 32
#define ST 3
#define TSTRH 40
#define TILE_H (128 * TSTRH)
#define SMEM3 (2 * ST * TILE_H * 2)

// ---------------- input GEMM: fp16, writes fp16 x ----------------------------
__global__ void __launch_bounds__(256, 2) k_mmaI16(
    const __half* __restrict__ A, const __half* __restrict__ W,
    const float* __restrict__ bias, __half* __restrict__ C)
{
    extern __shared__ __half smh[];
    uint32_t sbA = (uint32_t)__cvta_generic_to_shared(smh);
    uint32_t sbB = sbA + ST * TILE_H * 2;

    int tid  = threadIdx.x;
    int lane = tid & 31;
    int warp = tid >> 5;
    int wr = warp >> 2, wc = warp & 3;
    int lr = lane >> 2, lc = lane & 3;
    int rowBase = blockIdx.y * GBM;
    int colBase = blockIdx.x * GBN;

    int row = tid >> 1;
    int kp  = (tid & 1) * 16;
    bool okA = (rowBase + row) < NN;
    const __half* gA0 = A + (size_t)(rowBase + row) * DD + kp;
    const __half* gB0 = W + (size_t)(colBase + row) * DD + kp;
    uint32_t saBase = (row * TSTRH + kp) * 2;
    int aOff = (wr * 64 + (lane & 15)) * TSTRH + (lane >> 4) * 8;
    int bOff = (wc * 32 + (lane & 7) + ((lane >> 4) & 1) * 8) * TSTRH
             + ((lane >> 3) & 1) * 8;

    float acc[4][4][4];
#pragma unroll
    for (int m = 0; m < 4; m++)
#pragma unroll
        for (int n = 0; n < 4; n++)
#pragma unroll
            for (int r = 0; r < 4; r++) acc[m][n][r] = 0.f;

#define ISSUE(kt, s)                                                            \
    do {                                                                        \
        const __half* gA = gA0 + (kt) * GBK3;                                   \
        uint32_t sa = sbA + (s) * TILE_H * 2 + saBase;                          \
        cpa16(sa,      gA,     okA);                                            \
        cpa16(sa + 16, gA + 8, okA);                                            \
        const __half* gB = gB0 + (kt) * GBK3;                                   \
        uint32_t sb = sbB + (s) * TILE_H * 2 + saBase;                          \
        cpa16(sb,      gB,     true);                                           \
        cpa16(sb + 16, gB + 8, true);                                           \
        CP_COMMIT();                                                            \
    } while (0)

    ISSUE(0, 0);
    ISSUE(1, 1);

    const int NT = DD / GBK3;   // 8
    for (int kt = 0; kt < NT; kt++) {
        CP_WAIT1();
        __syncthreads();
        if (kt + 2 < NT) { ISSUE(kt + 2, (kt + 2) % ST); }
        else CP_COMMIT();
        int s = kt % ST;
        uint32_t aS = sbA + s * TILE_H * 2 + aOff * 2;
        uint32_t bS = sbB + s * TILE_H * 2 + bOff * 2;
#pragma unroll
        for (int kc = 0; kc < 2; kc++) {
            uint32_t af[4][4], bf[4][2];
#pragma unroll
            for (int mt = 0; mt < 4; mt++)
                LDSM4(af[mt][0], af[mt][1], af[mt][2], af[mt][3],
                      aS + (mt * 16 * TSTRH + kc * 16) * 2);
            LDSM4(bf[0][0], bf[0][1], bf[1][0], bf[1][1], bS + (kc * 16) * 2);
            LDSM4(bf[2][0], bf[2][1], bf[3][0], bf[3][1],
                  bS + (16 * TSTRH + kc * 16) * 2);
#pragma unroll
            for (int mt = 0; mt < 4; mt++)
#pragma unroll
                for (int nt = 0; nt < 4; nt++)
                    mma_f16(acc[mt][nt], af[mt], bf[nt]);
        }
    }
#undef ISSUE

#pragma unroll
    for (int nt = 0; nt < 4; nt++) {
        int col = colBase + wc * 32 + nt * 8 + 2 * lc;
        float2 bb = *(const float2*)&bias[col];
#pragma unroll
        for (int mt = 0; mt < 4; mt++) {
            int row2 = rowBase + wr * 64 + mt * 16 + lr;
#pragma unroll
            for (int half = 0; half < 2; half++) {
                int rr = row2 + half * 8;
                if (rr < NN) {
                    float2 o;
                    o.x = acc[mt][nt][half * 2]     + bb.x;
                    o.y = acc[mt][nt][half * 2 + 1] + bb.y;
                    *(__half2*)&C[(size_t)rr * DD + col] = __float22half2_rn(o);
                }
            }
        }
    }
}

// ---------------- fused 3-GEMM: fp16 m16n8k16 --------------------------------
__global__ void __launch_bounds__(256, 2) k_mma3a(
    const __half* __restrict__ A,
    const __half* __restrict__ Wh, const float* __restrict__ bh,
    const __half* __restrict__ Wg,
    const __half* __restrict__ Wl, const float* __restrict__ bl,
    const float* __restrict__ attS, const float* __restrict__ attD,
    __half* __restrict__ h, __half* __restrict__ xl)
{
    extern __shared__ __half smh[];
    uint32_t sbA = (uint32_t)__cvta_generic_to_shared(smh);
    uint32_t sbB = sbA + ST * TILE_H * 2;

    int tid  = threadIdx.x;
    int lane = tid & 31;
    int warp = tid >> 5;
    int wr = warp >> 2, wc = warp & 3;
    int lr = lane >> 2, lc = lane & 3;
    int rowBase = blockIdx.y * GBM;
    int seg = blockIdx.x >> 1;
    int colBase = (blockIdx.x & 1) * GBN;
    const __half* B = (seg == 0) ? Wh : (seg == 1 ? Wg : Wl);

    int row = tid >> 1;
    int kp  = (tid & 1) * 16;
    bool okA = (rowBase + row) < NN;
    const __half* gA0 = A + (size_t)(rowBase + row) * DD + kp;
    const __half* gB0 = B + (size_t)(colBase + row) * DD + kp;
    uint32_t saBase = (row * TSTRH + kp) * 2;
    int aOff = (wr * 64 + (lane & 15)) * TSTRH + (lane >> 4) * 8;
    int bOff = (wc * 32 + (lane & 7) + ((lane >> 4) & 1) * 8) * TSTRH
             + ((lane >> 3) & 1) * 8;

    float acc[4][4][4];
#pragma unroll
    for (int m = 0; m < 4; m++)
#pragma unroll
        for (int n = 0; n < 4; n++)
#pragma unroll
            for (int r = 0; r < 4; r++) acc[m][n][r] = 0.f;

#define ISSUE(kt, s)                                                            \
    do {                                                                        \
        const __half* gA = gA0 + (kt) * GBK3;                                   \
        uint32_t sa = sbA + (s) * TILE_H * 2 + saBase;                          \
        cpa16(sa,      gA,     okA);                                            \
        cpa16(sa + 16, gA + 8, okA);                                            \
        const __half* gB = gB0 + (kt) * GBK3;                                   \
        uint32_t sb = sbB + (s) * TILE_H * 2 + saBase;                          \
        cpa16(sb,      gB,     true);                                           \
        cpa16(sb + 16, gB + 8, true);                                           \
        CP_COMMIT();                                                            \
    } while (0)

    ISSUE(0, 0);
    ISSUE(1, 1);

    const int NT = DD / GBK3;   // 8
    for (int kt = 0; kt < NT; kt++) {
        CP_WAIT1();
        __syncthreads();
        if (kt + 2 < NT) { ISSUE(kt + 2, (kt + 2) % ST); }
        else CP_COMMIT();
        int s = kt % ST;
        uint32_t aS = sbA + s * TILE_H * 2 + aOff * 2;
        uint32_t bS = sbB + s * TILE_H * 2 + bOff * 2;
#pragma unroll
        for (int kc = 0; kc < 2; kc++) {
            uint32_t af[4][4], bf[4][2];
#pragma unroll
            for (int mt = 0; mt < 4; mt++)
                LDSM4(af[mt][0], af[mt][1], af[mt][2], af[mt][3],
                      aS + (mt * 16 * TSTRH + kc * 16) * 2);
            LDSM4(bf[0][0], bf[0][1], bf[1][0], bf[1][1], bS + (kc * 16) * 2);
            LDSM4(bf[2][0], bf[2][1], bf[3][0], bf[3][1],
                  bS + (16 * TSTRH + kc * 16) * 2);
#pragma unroll
            for (int mt = 0; mt < 4; mt++)
#pragma unroll
                for (int nt = 0; nt < 4; nt++)
                    mma_f16(acc[mt][nt], af[mt], bf[nt]);
        }
    }
#undef ISSUE

    if (seg == 1) {
        // hg fp16 (gatc gather target)
#pragma unroll
        for (int nt = 0; nt < 4; nt++) {
            int col = colBase + wc * 32 + nt * 8 + 2 * lc;
#pragma unroll
            for (int mt = 0; mt < 4; mt++) {
                int row2 = rowBase + wr * 64 + mt * 16 + lr;
#pragma unroll
                for (int half = 0; half < 2; half++) {
                    int rr = row2 + half * 8;
                    if (rr < NN) {
                        float2 o;
                        o.x = acc[mt][nt][half * 2];
                        o.y = acc[mt][nt][half * 2 + 1];
                        *(__half2*)&g_hgh[(size_t)rr * DD + col] =
                            __float22half2_rn(o);
                    }
                }
            }
        }
        // attention scalar partials
        float2 asw[4], adw[4];
#pragma unroll
        for (int nt = 0; nt < 4; nt++) {
            int col = colBase + wc * 32 + nt * 8 + 2 * lc;
            asw[nt] = *(const float2*)&attS[col];
            adw[nt] = *(const float2*)&attD[col];
        }
        int hh = (colBase + wc * 32) >> 6;
        int slab = wc & 1;
#pragma unroll
        for (int mt = 0; mt < 4; mt++) {
#pragma unroll
            for (int half = 0; half < 2; half++) {
                float ps = 0.f, pd = 0.f;
#pragma unroll
                for (int nt = 0; nt < 4; nt++) {
                    float v0 = acc[mt][nt][half * 2];
                    float v1 = acc[mt][nt][half * 2 + 1];
                    ps = fmaf(v0, asw[nt].x, fmaf(v1, asw[nt].y, ps));
                    pd = fmaf(v0, adw[nt].x, fmaf(v1, adw[nt].y, pd));
                }
                ps += __shfl_xor_sync(0xFFFFFFFFu, ps, 1);
                ps += __shfl_xor_sync(0xFFFFFFFFu, ps, 2);
                pd += __shfl_xor_sync(0xFFFFFFFFu, pd, 1);
                pd += __shfl_xor_sync(0xFFFFFFFFu, pd, 2);
                int rr = rowBase + wr * 64 + mt * 16 + lr + half * 8;
                if (lc == 0 && rr < NN) {
                    float2 o = make_float2(ps, pd);
                    *(float2*)&g_attp[((size_t)(rr * 4 + hh) * 2 + slab) * 2] = o;
                }
            }
        }
    } else {
        bool relu = (seg == 0);
        const float* bias = (seg == 0) ? bh : bl;
        __half* C = (seg == 0) ? h : xl;
#pragma unroll
        for (int nt = 0; nt < 4; nt++) {
            int col = colBase + wc * 32 + nt * 8 + 2 * lc;
            float2 bb = *(const float2*)&bias[col];
#pragma unroll
            for (int mt = 0; mt < 4; mt++) {
                int row2 = rowBase + wr * 64 + mt * 16 + lr;
#pragma unroll
                for (int half = 0; half < 2; half++) {
                    int rr = row2 + half * 8;
                    if (rr < NN) {
                        float2 o;
                        o.x = acc[mt][nt][half * 2]     + bb.x;
                        o.y = acc[mt][nt][half * 2 + 1] + bb.y;
                        if (relu) { o.x = fmaxf(o.x, 0.f); o.y = fmaxf(o.y, 0.f); }
                        __stcs((__half2*)&C[(size_t)rr * DD + col],
                               __float22half2_rn(o));
                    }
                }
            }
        }
    }
}

// ---------------- attention partial reduce ------------------------------------
__global__ void k_attred() {
    int i = blockIdx.x * blockDim.x + threadIdx.x;
    if (i >= NN * HH) return;
    float4 v = *(const float4*)&g_attp[(size_t)i * 4];
    g_asrc[i] = v.x + v.z;
    g_adst[i] = v.y + v.w;
}

// ---------------- GAT + combine fused: warp per node -------------------------
__device__ __forceinline__ float pick4(float4 v, int h) {
    float r = v.x;
    r = (h == 1) ? v.y : r;
    r = (h == 2) ? v.z : r;
    r = (h == 3) ? v.w : r;
    return r;
}

__device__ __forceinline__ void h8(uint4 raw, float* f) {
    float2 a = __half22float2(*(const __half2*)&raw.x);
    float2 b = __half22float2(*(const __half2*)&raw.y);
    float2 c = __half22float2(*(const __half2*)&raw.z);
    float2 d = __half22float2(*(const __half2*)&raw.w);
    f[0]=a.x; f[1]=a.y; f[2]=b.x; f[3]=b.y; f[4]=c.x; f[5]=c.y; f[6]=d.x; f[7]=d.y;
}

__global__ void __launch_bounds__(256) k_gatc(
    const float* __restrict__ bg, const float* __restrict__ lng,
    const float* __restrict__ lnb, const float* __restrict__ betas, int first)
{
    int w = (blockIdx.x * blockDim.x + threadIdx.x) >> 5;
    int lane = threadIdx.x & 31;
    if (w >= NN) return;
    int n = w;
    int h = lane >> 3;
    int colb = lane * 8;

    int beg = g_rowptr[n], end = g_rowptr[n + 1];
    float4 ad4 = *(const float4*)&g_adst[n * 4];
    float adv = pick4(ad4, h);

    float m = -1e30f, s = 0.f;
    float4 acc0 = make_float4(0,0,0,0), acc1 = make_float4(0,0,0,0);

    for (int e = beg; e < end; e++) {
        int src = g_srcs[e];
        float4 as4 = *(const float4*)&g_asrc[src * 4];
        float ev = pick4(as4, h) + adv;
        ev = ev > 0.f ? ev : NEG_SLOPE * ev;
        float nm = fmaxf(m, ev);
        float sc = __expf(m - nm);
        float wg = __expf(ev - nm);
        m = nm;
        s = fmaf(s, sc, wg);
        uint4 raw = *(const uint4*)&g_hgh[(size_t)src * DD + colb];
        float f[8];
        h8(raw, f);
        acc0.x = fmaf(wg, f[0], acc0.x * sc);
        acc0.y = fmaf(wg, f[1], acc0.y * sc);
        acc0.z = fmaf(wg, f[2], acc0.z * sc);
        acc0.w = fmaf(wg, f[3], acc0.w * sc);
        acc1.x = fmaf(wg, f[4], acc1.x * sc);
        acc1.y = fmaf(wg, f[5], acc1.y * sc);
        acc1.z = fmaf(wg, f[6], acc1.z * sc);
        acc1.w = fmaf(wg, f[7], acc1.w * sc);
    }
    float inv = 1.f / s;
    size_t idx = (size_t)n * DD + colb;
    float4 b0 = *(const float4*)&bg[colb];
    float4 b1 = *(const float4*)&bg[colb + 4];
    float xlv[8], hv[8];
    h8(__ldcs((const uint4*)&g_xl[idx]), xlv);
    h8(__ldcs((const uint4*)&g_h[idx]),  hv);

    float xn[8];
    xn[0] = fmaxf(fmaf(acc0.x, inv, b0.x + xlv[0]), 0.f);
    xn[1] = fmaxf(fmaf(acc0.y, inv, b0.y + xlv[1]), 0.f);
    xn[2] = fmaxf(fmaf(acc0.z, inv, b0.z + xlv[2]), 0.f);
    xn[3] = fmaxf(fmaf(acc0.w, inv, b0.w + xlv[3]), 0.f);
    xn[4] = fmaxf(fmaf(acc1.x, inv, b1.x + xlv[4]), 0.f);
    xn[5] = fmaxf(fmaf(acc1.y, inv, b1.y + xlv[5]), 0.f);
    xn[6] = fmaxf(fmaf(acc1.z, inv, b1.z + xlv[6]), 0.f);
    xn[7] = fmaxf(fmaf(acc1.w, inv, b1.w + xlv[7]), 0.f);

    float t[8];
#pragma unroll
    for (int i = 0; i < 8; i++) t[i] = hv[i] * xn[i];

    float sum = 0.f, sq = 0.f;
#pragma unroll
    for (int i = 0; i < 8; i++) { sum += t[i]; sq += t[i] * t[i]; }
#pragma unroll
    for (int o = 16; o; o >>= 1) {
        sum += __shfl_xor_sync(0xFFFFFFFFu, sum, o);
        sq  += __shfl_xor_sync(0xFFFFFFFFu, sq,  o);
    }
    float mean = sum * (1.f / DD);
    float var = sq * (1.f / DD) - mean * mean;
    float rs = rsqrtf(var + LNEPS);

    float4 lg0 = *(const float4*)&lng[colb];
    float4 lg1 = *(const float4*)&lng[colb + 4];
    float4 lb0 = *(const float4*)&lnb[colb];
    float4 lb1 = *(const float4*)&lnb[colb + 4];
    float4 be0 = *(const float4*)&betas[colb];
    float4 be1 = *(const float4*)&betas[colb + 4];
    float lg[8] = {lg0.x, lg0.y, lg0.z, lg0.w, lg1.x, lg1.y, lg1.z, lg1.w};
    float lb[8] = {lb0.x, lb0.y, lb0.z, lb0.w, lb1.x, lb1.y, lb1.z, lb1.w};
    float bev[8] = {be0.x, be0.y, be0.z, be0.w, be1.x, be1.y, be1.z, be1.w};

    float out[8];
#pragma unroll
    for (int i = 0; i < 8; i++) {
        float ln = (t[i] - mean) * rs * lg[i] + lb[i];
        float be = 1.f / (1.f + __expf(-bev[i]));
        out[i] = (1.f - be) * ln + be * xn[i];
    }

    // g_xh fp16 (next-layer GEMM input); xloc full precision
    *(__half2*)&g_xh[idx]     = __float22half2_rn(make_float2(out[0], out[1]));
    *(__half2*)&g_xh[idx + 2] = __float22half2_rn(make_float2(out[2], out[3]));
    *(__half2*)&g_xh[idx + 4] = __float22half2_rn(make_float2(out[4], out[5]));
    *(__half2*)&g_xh[idx + 6] = __float22half2_rn(make_float2(out[6], out[7]));

    float4 o0 = make_float4(out[0], out[1], out[2], out[3]);
    float4 o1 = make_float4(out[4], out[5], out[6], out[7]);
    if (first) {
        __stcs((float4*)&g_xloc[idx],     o0);
        __stcs((float4*)&g_xloc[idx + 4], o1);
    } else {
        float4 l0 = __ldcs((const float4*)&g_xloc[idx]);
        float4 l1 = __ldcs((const float4*)&g_xloc[idx + 4]);
        l0.x += o0.x; l0.y += o0.y; l0.z += o0.z; l0.w += o0.w;
        l1.x += o1.x; l1.y += o1.y; l1.z += o1.z; l1.w += o1.w;
        __stcs((float4*)&g_xloc[idx],     l0);
        __stcs((float4*)&g_xloc[idx + 4], l1);
    }
}

// ---------------- driver -----------------------------------------------------
extern "C" void kernel_launch(void* const* d_in, const int* in_sizes, int n_in,
                              void* d_out, int out_size) {
    const float* x_in   = (const float*)d_in[0];
    const int*   ei     = (const int*)  d_in[1];
    const float* Win    = (const float*)d_in[2];
    const float* b_in   = (const float*)d_in[3];
    const float* Wh     = (const float*)d_in[4];
    const float* bh     = (const float*)d_in[5];
    const float* Wg     = (const float*)d_in[6];
    const float* attS   = (const float*)d_in[7];
    const float* attD   = (const float*)d_in[8];
    const float* bg     = (const float*)d_in[9];
    const float* Wl     = (const float*)d_in[10];
    const float* bl     = (const float*)d_in[11];
    const float* lng    = (const float*)d_in[12];
    const float* lnb    = (const float*)d_in[13];
    const float* betas  = (const float*)d_in[14];
    const float* Wp     = (const float*)d_in[15];
    const float* bp     = (const float*)d_in[16];
    float* out = (float*)d_out;

    cudaFuncSetAttribute(k_mma3a,  cudaFuncAttributeMaxDynamicSharedMemorySize, SMEM3);
    cudaFuncSetAttribute(k_mmaI16, cudaFuncAttributeMaxDynamicSharedMemorySize, SMEM3);

    static cudaStream_t s2 = nullptr;
    static cudaEvent_t evFork = nullptr, evJoin = nullptr;
    if (s2 == nullptr) {
        cudaStreamCreateWithFlags(&s2, cudaStreamNonBlocking);
        cudaEventCreateWithFlags(&evFork, cudaEventDisableTiming);
        cudaEventCreateWithFlags(&evJoin, cudaEventDisableTiming);
    }

    __half* pxin; cudaGetSymbolAddress((void**)&pxin, g_xin);
    __half* pxh;  cudaGetSymbolAddress((void**)&pxh,  g_xh);
    __half* ph;   cudaGetSymbolAddress((void**)&ph,   g_h);
    __half* pxl;  cudaGetSymbolAddress((void**)&pxl,  g_xl);
    float*  pxlo; cudaGetSymbolAddress((void**)&pxlo, g_xloc);
    __half* pwrh; cudaGetSymbolAddress((void**)&pwrh, g_wrh);

    const __half* rWh  = pwrh;
    const __half* rWg  = pwrh + 196608;
    const __half* rWl  = pwrh + 393216;
    const __half* rWin = pwrh + 589824;

    dim3 gI(2, cdiv(NN, GBM));          // (2, 782)
    dim3 gF(6, cdiv(NN, GBM));          // (6, 782)

    // fork: CSR chain on s2
    cudaEventRecord(evFork, 0);
    cudaStreamWaitEvent(s2, evFork, 0);

    k_round<<<cdiv(655360, 256), 256>>>(Wh, Wg, Wl, Win);
    k_xcvt<<<cdiv(NN * DD / 8, 256), 256>>>(x_in);
    k_mmaI16<<<gI, 256, SMEM3>>>(pxin, rWin, b_in, pxh);
    k_init_cnt<<<cdiv(NN, 256), 256, 0, s2>>>();
    k_mma3a<<<gF, 256, SMEM3>>>(pxh, rWh, bh, rWg, rWl, bl, attS, attD, ph, pxl);

    k_hist<<<cdiv(EE, 256), 256, 0, s2>>>(ei);
    int nb = cdiv(NN, 1024);
    k_scan1<<<nb, 1024, 0, s2>>>();
    k_scan2<<<1, 32, 0, s2>>>(nb);
    k_scan3<<<cdiv(NN, 256), 256, 0, s2>>>();
    k_scatter<<<cdiv(EE + NN, 256), 256, 0, s2>>>(ei);
    cudaEventRecord(evJoin, s2);
    cudaStreamWaitEvent(0, evJoin, 0);

    for (int i = 0; i < 3; i++) {
        if (i > 0) {
            k_mma3a<<<gF, 256, SMEM3>>>(pxh, rWh + i * 65536, bh + i * DD,
                                        rWg + i * 65536, rWl + i * 65536, bl + i * DD,
                                        attS + i * DD, attD + i * DD,
                                        ph, pxl);
        }
        k_attred<<<cdiv(NN * HH, 256), 256>>>();
        k_gatc<<<cdiv(NN * 32, 256), 256>>>(bg + i * DD, lng + i * DD,
                                            lnb + i * DD, betas + i * DD, i == 0);
    }

    // out = xloc @ Wp + bp
    k_mmaO<<<cdiv(NN, 128), 256>>>(pxlo, Wp, bp, out);
}